// round 11
// baseline (speedup 1.0000x reference)
#include <cuda_runtime.h>
#include <cuda_fp16.h>
#include <cstdint>

#define Bq 8
#define Tq 512
#define Cq 768
#define Hq 12
#define Dq 64
#define Lq 12
#define Vq 32000
#define FFq 3072
#define Mq (Bq*Tq)          // 4096
#define BHq (Bq*Hq)         // 96
#define TT  (Tq*Tq)         // 262144
#define C3  (3*Cq)          // 2304

// ---------------- scratch (device globals) ----------------------------------
__device__ float g_x  [Mq*Cq];
__device__ float g_t2 [2*Mq*Cq];        // split-K partial outputs
__device__ float g_ps [4*BHq*Tq];

__device__ __half g_xb   [Mq*Cq];
__device__ __half g_qkvb [(size_t)Mq*C3];
__device__ __half g_pb   [(size_t)BHq*TT];
__device__ __half g_vs   [Mq*Cq];
__device__ __half g_t1b  [Mq*Cq];
__device__ __half g_ffnb [(size_t)Mq*FFq];
__device__ __half g_wqkv [(size_t)Lq*C3*Cq];
__device__ __half g_wob  [(size_t)Lq*Cq*Cq];
__device__ __half g_w1b  [(size_t)Lq*FFq*Cq];
__device__ __half g_w2b  [(size_t)Lq*Cq*FFq];
__device__ __half g_wdb  [(size_t)Vq*Cq];

// ---------------- small helpers ---------------------------------------------
__device__ __forceinline__ uint32_t s2u(const void* p) {
    return (uint32_t)__cvta_generic_to_shared(p);
}
__device__ __forceinline__ void cpa16p(void* smem, const void* gmem) {
    asm volatile("cp.async.cg.shared.global [%0], [%1], 16;\n"
        :: "r"(s2u(smem)), "l"(gmem));
}
__device__ __forceinline__ void ldm_x4(uint32_t* r, uint32_t addr) {
    asm volatile("ldmatrix.sync.aligned.m8n8.x4.shared.b16 {%0,%1,%2,%3}, [%4];"
        : "=r"(r[0]), "=r"(r[1]), "=r"(r[2]), "=r"(r[3]) : "r"(addr));
}
__device__ __forceinline__ void ldm_x4_t(uint32_t* r, uint32_t addr) {
    asm volatile("ldmatrix.sync.aligned.m8n8.x4.trans.shared.b16 {%0,%1,%2,%3}, [%4];"
        : "=r"(r[0]), "=r"(r[1]), "=r"(r[2]), "=r"(r[3]) : "r"(addr));
}
__device__ __forceinline__ void mma16816(float* c, const uint32_t* a, uint32_t b0, uint32_t b1) {
    asm volatile(
        "mma.sync.aligned.m16n8k16.row.col.f32.f16.f16.f32 "
        "{%0,%1,%2,%3}, {%4,%5,%6,%7}, {%8,%9}, {%0,%1,%2,%3};"
        : "+f"(c[0]), "+f"(c[1]), "+f"(c[2]), "+f"(c[3])
        : "r"(a[0]), "r"(a[1]), "r"(a[2]), "r"(a[3]), "r"(b0), "r"(b1));
}

// ============ dense GEMM: C[M,N] = A[M,K-slice] @ Bt[N,K-slice]^T ============
// CTA 64x128, 128 threads (4 warps, 2m x 2n), warp tile 32x64, BK=64,
// 2-stage cp.async smem pipeline + REGISTER fragment double-buffering
// (ldmatrix of kk+16 issued before mma batch of kk). 3 CTAs/SM.
#define D_ASZ  (64*72)
#define D_BSZ  (128*72)
#define D_SMEM (2*(D_ASZ + D_BSZ)*2)     // 55296 bytes

__global__ void __launch_bounds__(128, 3)
gemm_d(const __half* __restrict__ A, const __half* __restrict__ Bt,
       const float* __restrict__ bias, void* __restrict__ Cout,
       int K, int lda, int ldb, int ldc,
       long sK, long sC, int relu, int outhalf)
{
    extern __shared__ __half sm[];
    __half* As = sm;                 // [2][64][72]
    __half* Bs = sm + 2 * D_ASZ;     // [2][128][72]

    A  += (long)blockIdx.z * sK;
    Bt += (long)blockIdx.z * sK;
    float*  Cf = (float*)Cout  + (long)blockIdx.z * sC;
    __half* Ch = (__half*)Cout + (long)blockIdx.z * sC;

    const int tid  = threadIdx.x;
    const int lane = tid & 31;
    const int warp = tid >> 5;
    const int wm   = warp >> 1;          // 0..1
    const int wn   = warp & 1;           // 0..1
    const int bm = blockIdx.y * 64;
    const int bn = blockIdx.x * 128;

    const __half* Ag = A  + (long)bm * lda;
    const __half* Bg = Bt + (long)bn * ldb;

    float acc[2][8][4];
#pragma unroll
    for (int i = 0; i < 2; i++)
#pragma unroll
        for (int j = 0; j < 8; j++)
#pragma unroll
            for (int q = 0; q < 4; q++) acc[i][j][q] = 0.f;

    auto stage = [&](int s, int k0) {
        __half* Ab = As + s * D_ASZ;
        __half* Bb = Bs + s * D_BSZ;
#pragma unroll
        for (int i = 0; i < 4; i++) {                 // A: 512 16B-chunks
            int ci = tid + (i << 7);
            int r = ci >> 3, c = (ci & 7) << 3;
            cpa16p(&Ab[r * 72 + c], Ag + (long)r * lda + k0 + c);
        }
#pragma unroll
        for (int i = 0; i < 8; i++) {                 // B: 1024 chunks
            int ci = tid + (i << 7);
            int r = ci >> 3, c = (ci & 7) << 3;
            cpa16p(&Bb[r * 72 + c], Bg + (long)r * ldb + k0 + c);
        }
        asm volatile("cp.async.commit_group;" ::: "memory");
    };

    const int laddrA = (wm * 32 + (lane & 15)) * 72 + ((lane >> 4) << 3);
    const int laddrB = (wn * 64 + (lane & 15)) * 72 + ((lane >> 4) << 3);

    auto compute = [&](int s) {
        uint32_t aBase = s2u(As + s * D_ASZ);
        uint32_t bBase = s2u(Bs + s * D_BSZ);
        uint32_t ar[2][2][4], br[2][4][4];
        // prefetch kk=0 fragments into buffer 0
#pragma unroll
        for (int mt = 0; mt < 2; mt++)
            ldm_x4(ar[0][mt], aBase + 2u * (laddrA + mt * 16 * 72));
#pragma unroll
        for (int nt = 0; nt < 4; nt++)
            ldm_x4(br[0][nt], bBase + 2u * (laddrB + nt * 16 * 72));
#pragma unroll
        for (int ks = 0; ks < 4; ks++) {
            const int cur = ks & 1;
            if (ks < 3) {                 // prefetch next kk fragments first
                const int kk = (ks + 1) << 4;
#pragma unroll
                for (int mt = 0; mt < 2; mt++)
                    ldm_x4(ar[cur ^ 1][mt], aBase + 2u * (laddrA + mt * 16 * 72 + kk));
#pragma unroll
                for (int nt = 0; nt < 4; nt++)
                    ldm_x4(br[cur ^ 1][nt], bBase + 2u * (laddrB + nt * 16 * 72 + kk));
            }
#pragma unroll
            for (int mt = 0; mt < 2; mt++)
#pragma unroll
                for (int n8 = 0; n8 < 8; n8++) {
                    int nt = n8 >> 1, h = n8 & 1;
                    mma16816(acc[mt][n8], ar[cur][mt], br[cur][nt][h], br[cur][nt][2 + h]);
                }
        }
    };

    const int nk = K >> 6;
    stage(0, 0);
    stage(1, 64);
    for (int kt = 0; kt < nk; kt++) {
        if (kt + 1 < nk) asm volatile("cp.async.wait_group 1;" ::: "memory");
        else             asm volatile("cp.async.wait_group 0;" ::: "memory");
        __syncthreads();
        compute(kt & 1);
        __syncthreads();
        if (kt + 2 < nk) stage(kt & 1, (kt + 2) << 6);
    }

    // epilogue
    const int r0 = bm + wm * 32 + (lane >> 2);
    const int c0 = bn + wn * 64 + ((lane & 3) << 1);
#pragma unroll
    for (int n8 = 0; n8 < 8; n8++) {
        int c = c0 + n8 * 8;
        float bb0 = 0.f, bb1 = 0.f;
        if (bias) { bb0 = __ldg(&bias[c]); bb1 = __ldg(&bias[c + 1]); }
#pragma unroll
        for (int mt = 0; mt < 2; mt++) {
#pragma unroll
            for (int hh = 0; hh < 2; hh++) {
                int r = r0 + mt * 16 + hh * 8;
                float v0 = acc[mt][n8][hh * 2 + 0] + bb0;
                float v1 = acc[mt][n8][hh * 2 + 1] + bb1;
                if (relu) { v0 = fmaxf(v0, 0.f); v1 = fmaxf(v1, 0.f); }
                if (outhalf) {
                    *reinterpret_cast<__half2*>(Ch + (long)r * ldc + c) =
                        __floats2half2_rn(v0, v1);
                } else {
                    *reinterpret_cast<float2*>(Cf + (long)r * ldc + c) = make_float2(v0, v1);
                }
            }
        }
    }
}

// ========== mma.sync GEMM for scores (EXPSUM) and AV =========================
template<int BN, bool BT, bool EXPSUM>
__global__ void __launch_bounds__(256, 2)
gemm_tc(const __half* __restrict__ A, const __half* __restrict__ B,
        void* __restrict__ Cout, float* __restrict__ psum,
        int K, int lda, int ldb, int ldc,
        long sAo, long sAi, long sBo, long sBi, long sCo, long sCi, int zdiv,
        float alpha)
{
    extern __shared__ __half smem_dyn[];
    constexpr int ASIZE = 128 * 40;
    constexpr int BROWS = BT ? BN : 32;
    constexpr int BCOLS = BT ? 40 : (BN + 8);
    constexpr int BSIZE = BROWS * BCOLS;
    __half* Asm = smem_dyn;
    __half* Bsm = smem_dyn + 3 * ASIZE;

    const int zo = blockIdx.z / zdiv, zi = blockIdx.z - zo * zdiv;
    A += zo * sAo + zi * sAi;
    B += zo * sBo + zi * sBi;
    __half* Ch = (__half*)Cout + zo * sCo + zi * sCi;

    const int bm = blockIdx.y * 128;
    const int bn = blockIdx.x * BN;
    const int tid  = threadIdx.x;
    const int lane = tid & 31;
    const int warp = tid >> 5;
    const int wm   = warp & 3;
    const int wn   = warp >> 2;
    const int m_w  = wm * 32;
    const int n_w  = wn * (BN / 2);
    constexpr int NT8  = (BN / 2) / 8;
    constexpr int NT16 = (BN / 2) / 16;

    const __half* Ag = A + (long)bm * lda;
    const __half* Bg = BT ? (B + (long)bn * ldb) : (B + bn);

    float acc[2][NT8][4];
#pragma unroll
    for (int i = 0; i < 2; i++)
#pragma unroll
        for (int j = 0; j < NT8; j++)
#pragma unroll
            for (int q = 0; q < 4; q++) acc[i][j][q] = 0.f;

    auto stage = [&](int s, int k0) {
        __half* As = Asm + s * ASIZE;
        __half* Bs = Bsm + s * BSIZE;
#pragma unroll
        for (int i = 0; i < 2; i++) {
            int ci = tid + i * 256;
            int r = ci >> 2, kc = (ci & 3) << 3;
            cpa16p(&As[r * 40 + kc], Ag + (long)r * lda + k0 + kc);
        }
        if (BT) {
            constexpr int IT = (BN * 4) / 256;
#pragma unroll
            for (int i = 0; i < IT; i++) {
                int ci = tid + i * 256;
                int r = ci >> 2, kc = (ci & 3) << 3;
                cpa16p(&Bs[r * 40 + kc], Bg + (long)r * ldb + k0 + kc);
            }
        } else {
            constexpr int CH = BN / 8;
            constexpr int IT = (32 * CH) / 256;
#pragma unroll
            for (int i = 0; i < IT; i++) {
                int ci = tid + i * 256;
                int r = ci / CH, nc = (ci % CH) << 3;
                cpa16p(&Bs[r * BCOLS + nc], Bg + (long)(k0 + r) * ldb + nc);
            }
        }
    };

    auto compute = [&](int s) {
        uint32_t aBase = s2u(Asm + s * ASIZE);
        uint32_t bBase = s2u(Bsm + s * BSIZE);
#pragma unroll
        for (int kk = 0; kk < 32; kk += 16) {
            uint32_t ar[2][4];
#pragma unroll
            for (int mt = 0; mt < 2; mt++) {
                uint32_t addr = aBase +
                    2u * ((m_w + mt * 16 + (lane & 15)) * 40 + kk + ((lane >> 4) << 3));
                ldm_x4(ar[mt], addr);
            }
            uint32_t br[NT16][4];
#pragma unroll
            for (int nt = 0; nt < NT16; nt++) {
                if (BT) {
                    uint32_t addr = bBase +
                        2u * ((n_w + nt * 16 + (lane & 15)) * 40 + kk + ((lane >> 4) << 3));
                    ldm_x4(br[nt], addr);
                } else {
                    uint32_t addr = bBase +
                        2u * ((kk + (lane & 15)) * BCOLS + n_w + nt * 16 + ((lane >> 4) << 3));
                    ldm_x4_t(br[nt], addr);
                }
            }
#pragma unroll
            for (int mt = 0; mt < 2; mt++)
#pragma unroll
                for (int n8 = 0; n8 < NT8; n8++) {
                    int nt = n8 >> 1, h = n8 & 1;
                    uint32_t b0, b1;
                    if (BT) { b0 = br[nt][h];     b1 = br[nt][2 + h];     }
                    else    { b0 = br[nt][h * 2]; b1 = br[nt][h * 2 + 1]; }
                    mma16816(acc[mt][n8], ar[mt], b0, b1);
                }
        }
    };

    const int ntile = K >> 5;
    stage(0, 0);
    asm volatile("cp.async.commit_group;");
    stage(1, 32);
    asm volatile("cp.async.commit_group;");
    for (int kt = 0; kt < ntile; kt++) {
        asm volatile("cp.async.wait_group 1;");
        __syncthreads();
        if (kt + 2 < ntile) stage((kt + 2) % 3, (kt + 2) << 5);
        asm volatile("cp.async.commit_group;");
        compute(kt % 3);
    }

    const int r0 = bm + m_w + (lane >> 2);
    const int c0 = bn + n_w + ((lane & 3) << 1);

    if (EXPSUM) {
        float cs[NT8][2];
#pragma unroll
        for (int n8 = 0; n8 < NT8; n8++) { cs[n8][0] = 0.f; cs[n8][1] = 0.f; }
#pragma unroll
        for (int n8 = 0; n8 < NT8; n8++) {
            int c = c0 + n8 * 8;
#pragma unroll
            for (int mt = 0; mt < 2; mt++) {
#pragma unroll
                for (int hh = 0; hh < 2; hh++) {
                    int r = r0 + mt * 16 + hh * 8;
                    float v0 = __expf(fmaf(acc[mt][n8][hh * 2 + 0], alpha, -4.f));
                    float v1 = __expf(fmaf(acc[mt][n8][hh * 2 + 1], alpha, -4.f));
                    *reinterpret_cast<__half2*>(Ch + (long)r * ldc + c) =
                        __floats2half2_rn(v0, v1);
                    cs[n8][0] += v0; cs[n8][1] += v1;
                }
            }
        }
#pragma unroll
        for (int n8 = 0; n8 < NT8; n8++)
#pragma unroll
            for (int p = 0; p < 2; p++) {
                float v = cs[n8][p];
                v += __shfl_xor_sync(0xffffffffu, v, 4);
                v += __shfl_xor_sync(0xffffffffu, v, 8);
                v += __shfl_xor_sync(0xffffffffu, v, 16);
                cs[n8][p] = v;
            }
        __syncthreads();
        float* sred = (float*)smem_dyn;
        if (lane < 4) {
#pragma unroll
            for (int n8 = 0; n8 < NT8; n8++) {
                sred[warp * 64 + n8 * 8 + lane * 2 + 0] = cs[n8][0];
                sred[warp * 64 + n8 * 8 + lane * 2 + 1] = cs[n8][1];
            }
        }
        __syncthreads();
        if (tid < 128) {
            int wn2 = tid >> 6, cin = tid & 63;
            float t = 0.f;
#pragma unroll
            for (int w2 = 0; w2 < 4; w2++) t += sred[(wn2 * 4 + w2) * 64 + cin];
            psum[((long)blockIdx.y * gridDim.z + blockIdx.z) * ldc + bn + tid] = t;
        }
        return;
    }

#pragma unroll
    for (int n8 = 0; n8 < NT8; n8++) {
        int c = c0 + n8 * 8;
#pragma unroll
        for (int mt = 0; mt < 2; mt++) {
#pragma unroll
            for (int hh = 0; hh < 2; hh++) {
                int r = r0 + mt * 16 + hh * 8;
                float v0 = acc[mt][n8][hh * 2 + 0] * alpha;
                float v1 = acc[mt][n8][hh * 2 + 1] * alpha;
                *reinterpret_cast<__half2*>(Ch + (long)r * ldc + c) =
                    __floats2half2_rn(v0, v1);
            }
        }
    }
}

#define SMEM_128T (3*(128*40 + 128*40)*2)   // 61440
#define SMEM_64F  (3*(128*40 + 32*72)*2)    // 44544

// ---------------- weight transpose+convert kernels ---------------------------
__global__ void tr_f2h(const float* __restrict__ src, __half* __restrict__ dst,
                       int K, int N, long sSrc, long sDst)
{
    src += (long)blockIdx.z * sSrc;
    dst += (long)blockIdx.z * sDst;
    __shared__ float t[64][65];
    const int n0 = blockIdx.x * 64, k0 = blockIdx.y * 64;
    const int tid = threadIdx.x;
#pragma unroll
    for (int i = 0; i < 16; i++) {
        int idx = tid + i * 256;
        int r = idx >> 6, c = idx & 63;
        t[r][c] = src[(long)(k0 + r) * N + n0 + c];
    }
    __syncthreads();
#pragma unroll
    for (int i = 0; i < 16; i++) {
        int idx = tid + i * 256;
        int r = idx >> 6, c = idx & 63;
        dst[(long)(n0 + r) * K + k0 + c] = __float2half(t[c][r]);
    }
}

__global__ void tr_qkv_all(const float* __restrict__ Wq, const float* __restrict__ Wk,
                           const float* __restrict__ Wv, __half* __restrict__ dst)
{
    const int z = blockIdx.z;
    const int w = z / (Lq * Hq);
    const int lh = z - w * (Lq * Hq);
    const int l = lh / Hq, h = lh - l * Hq;
    const float* W = (w == 0) ? Wq : ((w == 1) ? Wk : Wv);
    const float* src = W + (long)lh * Cq * Dq;
    __half* d = dst + (long)l * C3 * Cq + (long)(w * 768 + h * Dq) * Cq;
    __shared__ float t[64][65];
    const int k0 = blockIdx.y * 64;
    const int tid = threadIdx.x;
#pragma unroll
    for (int i = 0; i < 16; i++) {
        int idx = tid + i * 256;
        int r = idx >> 6, c = idx & 63;
        t[r][c] = src[(long)(k0 + r) * Dq + c];
    }
    __syncthreads();
#pragma unroll
    for (int i = 0; i < 16; i++) {
        int idx = tid + i * 256;
        int r = idx >> 6, c = idx & 63;
        d[(long)r * Cq + k0 + c] = __float2half(t[c][r]);
    }
}

// ---------------- embed -------------------------------------------------------
__global__ void embed_kernel(const int* __restrict__ ids, const float* __restrict__ emb,
                             const float* __restrict__ pos,
                             float* __restrict__ x, __half* __restrict__ xb)
{
    int idx = blockIdx.x * blockDim.x + threadIdx.x;
    if (idx >= Mq * Cq) return;
    int m = idx / Cq, c = idx - m * Cq;
    int t = m & (Tq - 1);
    int tok = ids[m];
    float v = emb[(size_t)tok * Cq + c] + pos[(size_t)t * Cq + c];
    x[idx]  = v;
    xb[idx] = __float2half(v);
}

// vs[m][c] = V[m][c] / colsum
__global__ void vscale_kernel(const __half* __restrict__ qkv,
                              const float* __restrict__ ps, __half* __restrict__ vs)
{
    int idx = blockIdx.x * blockDim.x + threadIdx.x;
    if (idx >= Mq * Cq / 2) return;
    int c2 = idx % (Cq / 2);
    int m  = idx / (Cq / 2);
    int c  = c2 * 2;
    int b  = m >> 9, t = m & 511, h = c >> 6;
    long si = (((long)b * Hq + h) << 9) + t;
    float s = ps[si] + ps[(long)BHq * Tq + si]
            + ps[2L * BHq * Tq + si] + ps[3L * BHq * Tq + si];
    float r = 1.f / s;
    __half2 v = *reinterpret_cast<const __half2*>(&qkv[(long)m * C3 + 1536 + c]);
    float2 f = __half22float2(v);
    *reinterpret_cast<__half2*>(&vs[(long)m * Cq + c]) = __floats2half2_rn(f.x * r, f.y * r);
}

// ---------------- residual add (split-K sum) + bias + layernorm ---------------
__device__ __forceinline__ float block_sum768(float val, float* sh)
{
#pragma unroll
    for (int o = 16; o > 0; o >>= 1) val += __shfl_xor_sync(0xffffffffu, val, o);
    __syncthreads();
    if ((threadIdx.x & 31) == 0) sh[threadIdx.x >> 5] = val;
    __syncthreads();
    float tot = 0.f;
#pragma unroll
    for (int i = 0; i < 8; i++) tot += sh[i];
    return tot;
}

__global__ void __launch_bounds__(256)
add_ln_kernel(float* __restrict__ x, const float* __restrict__ y0,
              const float* __restrict__ y1, const float* __restrict__ bias,
              const float* __restrict__ g, const float* __restrict__ bta,
              __half* __restrict__ xb)
{
    __shared__ float sh[8];
    long row = blockIdx.x;
    int tid = threadIdx.x;
    float v[3];
    float s = 0.f;
#pragma unroll
    for (int j = 0; j < 3; j++) {
        int c = tid + j * 256;
        v[j] = x[row * Cq + c] + y0[row * Cq + c] + y1[row * Cq + c] + bias[c];
        s += v[j];
    }
    float mu = block_sum768(s, sh) * (1.f / Cq);
    float s2 = 0.f;
#pragma unroll
    for (int j = 0; j < 3; j++) { float d = v[j] - mu; s2 += d * d; }
    float var = block_sum768(s2, sh) * (1.f / Cq);
    float rstd = rsqrtf(var + 1e-5f);
#pragma unroll
    for (int j = 0; j < 3; j++) {
        int c = tid + j * 256;
        float o = (v[j] - mu) * rstd * g[c] + bta[c];
        x[row * Cq + c]  = o;
        xb[row * Cq + c] = __float2half(o);
    }
}

// ---------------- launch -------------------------------------------------------
extern "C" void kernel_launch(void* const* d_in, const int* in_sizes, int n_in,
                              void* d_out, int out_size)
{
    const int*   ids  = (const int*)  d_in[0];
    const float* emb  = (const float*)d_in[1];
    const float* pos  = (const float*)d_in[2];
    const float* Wq   = (const float*)d_in[3];
    const float* Wk   = (const float*)d_in[4];
    const float* Wv   = (const float*)d_in[5];
    const float* Wo   = (const float*)d_in[6];
    const float* bo   = (const float*)d_in[7];
    const float* ln1g = (const float*)d_in[8];
    const float* ln1b = (const float*)d_in[9];
    const float* W1   = (const float*)d_in[10];
    const float* b1   = (const float*)d_in[11];
    const float* W2   = (const float*)d_in[12];
    const float* b2   = (const float*)d_in[13];
    const float* ln2g = (const float*)d_in[14];
    const float* ln2b = (const float*)d_in[15];
    const float* decW = (const float*)d_in[16];
    const float* decb = (const float*)d_in[17];
    float* out = (float*)d_out;

    cudaFuncSetAttribute(gemm_d,
        cudaFuncAttributeMaxDynamicSharedMemorySize, D_SMEM);
    cudaFuncSetAttribute(gemm_tc<128, true, true>,
        cudaFuncAttributeMaxDynamicSharedMemorySize, SMEM_128T);
    cudaFuncSetAttribute(gemm_tc<64, false, false>,
        cudaFuncAttributeMaxDynamicSharedMemorySize, SMEM_64F);

    float *x, *t2, *ps;
    __half *xb, *qkvb, *pb, *vs, *t1b, *ffnb;
    __half *wqkv, *wob, *w1b, *w2b, *wdb;
    cudaGetSymbolAddress((void**)&x,    g_x);
    cudaGetSymbolAddress((void**)&t2,   g_t2);
    cudaGetSymbolAddress((void**)&ps,   g_ps);
    cudaGetSymbolAddress((void**)&xb,   g_xb);
    cudaGetSymbolAddress((void**)&qkvb, g_qkvb);
    cudaGetSymbolAddress((void**)&pb,   g_pb);
    cudaGetSymbolAddress((void**)&vs,   g_vs);
    cudaGetSymbolAddress((void**)&t1b,  g_t1b);
    cudaGetSymbolAddress((void**)&ffnb, g_ffnb);
    cudaGetSymbolAddress((void**)&wqkv, g_wqkv);
    cudaGetSymbolAddress((void**)&wob,  g_wob);
    cudaGetSymbolAddress((void**)&w1b,  g_w1b);
    cudaGetSymbolAddress((void**)&w2b,  g_w2b);
    cudaGetSymbolAddress((void**)&wdb,  g_wdb);

    // launch 1: embed; 2: qkv weights; 3: Wo; 4: QKV GEMM layer 0 (ncu target)
    embed_kernel<<<(Mq * Cq + 255) / 256, 256>>>(ids, emb, pos, x, xb);
    tr_qkv_all<<<dim3(1, 12, 3 * Lq * Hq), 256>>>(Wq, Wk, Wv, wqkv);
    tr_f2h<<<dim3(12, 12, Lq), 256>>>(Wo, wob, Cq, Cq, (long)Cq * Cq, (long)Cq * Cq);
    gemm_d<<<dim3(C3 / 128, Mq / 64, 1), 128, D_SMEM>>>(
        xb, wqkv, nullptr, qkvb, Cq, Cq, Cq, C3, 0, 0, 0, 1);
    tr_f2h<<<dim3(48, 12, Lq), 256>>>(W1, w1b, Cq, FFq, (long)Cq * FFq, (long)Cq * FFq);
    tr_f2h<<<dim3(12, 48, Lq), 256>>>(W2, w2b, FFq, Cq, (long)FFq * Cq, (long)FFq * Cq);
    tr_f2h<<<dim3(500, 12, 1), 256>>>(decW, wdb, Cq, Vq, 0, 0);

    for (int l = 0; l < Lq; l++) {
        const __half* wol = wob + (size_t)l * Cq * Cq;
        const __half* w1l = w1b + (size_t)l * Cq * FFq;
        const __half* w2l = w2b + (size_t)l * FFq * Cq;
        const float* bol = bo + (size_t)l * Cq;
        const float* b1l = b1 + (size_t)l * FFq;
        const float* b2l = b2 + (size_t)l * Cq;

        // scores + exp + column partial sums: pb = exp(0.125*QK^T - 4)
        gemm_tc<128, true, true><<<dim3(Tq / 128, Tq / 128, BHq), 256, SMEM_128T>>>(
            qkvb, qkvb + 768, pb, ps,
            Dq, C3, C3, Tq,
            (long)Tq * C3, Dq, (long)Tq * C3, Dq, (long)Hq * TT, TT, Hq,
            0.125f);

        vscale_kernel<<<(Mq * Cq / 2 + 255) / 256, 256>>>(qkvb, ps, vs);

        // AV (out fp16, concat-head layout)
        gemm_tc<64, false, false><<<dim3(1, Tq / 128, BHq), 256, SMEM_64F>>>(
            pb, vs, t1b, nullptr,
            Tq, Tq, Cq, Cq,
            (long)Hq * TT, TT, (long)Tq * Cq, Dq, (long)Tq * Cq, Dq, Hq,
            1.f);

        // output projection: split-K x2 -> t2[0], t2[1]; bias in add_ln
        gemm_d<<<dim3(Cq / 128, Mq / 64, 2), 128, D_SMEM>>>(
            t1b, wol, nullptr, t2, Cq / 2, Cq, Cq, Cq,
            (long)(Cq / 2), (long)Mq * Cq, 0, 0);
        add_ln_kernel<<<Mq, 256>>>(x, t2, t2 + (long)Mq * Cq, bol,
            ln1g + (size_t)l * Cq, ln1b + (size_t)l * Cq, xb);

        // FFN1 (full-K, throughput-bound)
        gemm_d<<<dim3(FFq / 128, Mq / 64, 1), 128, D_SMEM>>>(
            xb, w1l, b1l, ffnb, Cq, Cq, Cq, FFq, 0, 0, 1, 1);
        // FFN2: split-K x2
        gemm_d<<<dim3(Cq / 128, Mq / 64, 2), 128, D_SMEM>>>(
            ffnb, w2l, nullptr, t2, FFq / 2, FFq, FFq, Cq,
            (long)(FFq / 2), (long)Mq * Cq, 0, 0);
        add_ln_kernel<<<Mq, 256>>>(x, t2, t2 + (long)Mq * Cq, b2l,
            ln2g + (size_t)l * Cq, ln2b + (size_t)l * Cq, xb);

        // QKV for next layer
        if (l + 1 < Lq) {
            const __half* wq1 = wqkv + (size_t)(l + 1) * C3 * Cq;
            gemm_d<<<dim3(C3 / 128, Mq / 64, 1), 128, D_SMEM>>>(
                xb, wq1, nullptr, qkvb, Cq, Cq, Cq, C3, 0, 0, 0, 1);
        }
    }

    // decoder: [4096,768] @ [768,32000] + bias (out fp32)
    gemm_d<<<dim3(Vq / 128, Mq / 64, 1), 128, D_SMEM>>>(
        xb, wdb, decb, out, Cq, Cq, Cq, Vq, 0, 0, 0, 0);
}

// round 12
// speedup vs baseline: 1.0497x; 1.0497x over previous
#include <cuda_runtime.h>
#include <cuda_fp16.h>
#include <cstdint>

#define Bq 8
#define Tq 512
#define Cq 768
#define Hq 12
#define Dq 64
#define Lq 12
#define Vq 32000
#define FFq 3072
#define Mq (Bq*Tq)          // 4096
#define BHq (Bq*Hq)         // 96
#define TT  (Tq*Tq)         // 262144
#define C3  (3*Cq)          // 2304
#define LOG2E 1.4426950408889634f

// ---------------- scratch (device globals) ----------------------------------
__device__ float g_x  [Mq*Cq];
__device__ float g_t2 [2*Mq*Cq];        // split-K partial outputs
__device__ float g_ps [4*BHq*Tq];

__device__ __half g_xb   [Mq*Cq];
__device__ __half g_qkvb [(size_t)Mq*C3];
__device__ __half g_pb   [(size_t)BHq*TT];
__device__ __half g_vs   [Mq*Cq];
__device__ __half g_t1b  [Mq*Cq];
__device__ __half g_ffnb [(size_t)Mq*FFq];
__device__ __half g_wqkv [(size_t)Lq*C3*Cq];
__device__ __half g_wob  [(size_t)Lq*Cq*Cq];
__device__ __half g_w1b  [(size_t)Lq*FFq*Cq];
__device__ __half g_w2b  [(size_t)Lq*Cq*FFq];
__device__ __half g_wdb  [(size_t)Vq*Cq];

// ---------------- small helpers ---------------------------------------------
__device__ __forceinline__ uint32_t s2u(const void* p) {
    return (uint32_t)__cvta_generic_to_shared(p);
}
__device__ __forceinline__ void cpa16p(void* smem, const void* gmem) {
    asm volatile("cp.async.cg.shared.global [%0], [%1], 16;\n"
        :: "r"(s2u(smem)), "l"(gmem));
}
__device__ __forceinline__ void ldm_x4(uint32_t* r, uint32_t addr) {
    asm volatile("ldmatrix.sync.aligned.m8n8.x4.shared.b16 {%0,%1,%2,%3}, [%4];"
        : "=r"(r[0]), "=r"(r[1]), "=r"(r[2]), "=r"(r[3]) : "r"(addr));
}
__device__ __forceinline__ void ldm_x4_t(uint32_t* r, uint32_t addr) {
    asm volatile("ldmatrix.sync.aligned.m8n8.x4.trans.shared.b16 {%0,%1,%2,%3}, [%4];"
        : "=r"(r[0]), "=r"(r[1]), "=r"(r[2]), "=r"(r[3]) : "r"(addr));
}
__device__ __forceinline__ void mma16816(float* c, const uint32_t* a, uint32_t b0, uint32_t b1) {
    asm volatile(
        "mma.sync.aligned.m16n8k16.row.col.f32.f16.f16.f32 "
        "{%0,%1,%2,%3}, {%4,%5,%6,%7}, {%8,%9}, {%0,%1,%2,%3};"
        : "+f"(c[0]), "+f"(c[1]), "+f"(c[2]), "+f"(c[3])
        : "r"(a[0]), "r"(a[1]), "r"(a[2]), "r"(a[3]), "r"(b0), "r"(b1));
}

// ============ dense GEMM: C[M,N] = A[M,K-slice] @ Bt[N,K-slice]^T ============
// CTA 64x128, 128 threads (4 warps, 2m x 2n), warp tile 32x64, BK=64,
// 2-stage cp.async, 4 CTAs/SM. Split-K via blockIdx.z (offset z*sK, out +z*sC).
#define D_ASZ  (64*72)
#define D_BSZ  (128*72)
#define D_SMEM (2*(D_ASZ + D_BSZ)*2)     // 55296 bytes

__global__ void __launch_bounds__(128, 4)
gemm_d(const __half* __restrict__ A, const __half* __restrict__ Bt,
       const float* __restrict__ bias, void* __restrict__ Cout,
       int K, int lda, int ldb, int ldc,
       long sK, long sC, int relu, int outhalf)
{
    extern __shared__ __half sm[];
    __half* As = sm;                 // [2][64][72]
    __half* Bs = sm + 2 * D_ASZ;     // [2][128][72]

    A  += (long)blockIdx.z * sK;
    Bt += (long)blockIdx.z * sK;
    float*  Cf = (float*)Cout  + (long)blockIdx.z * sC;
    __half* Ch = (__half*)Cout + (long)blockIdx.z * sC;

    const int tid  = threadIdx.x;
    const int lane = tid & 31;
    const int warp = tid >> 5;
    const int wm   = warp >> 1;          // 0..1
    const int wn   = warp & 1;           // 0..1
    const int bm = blockIdx.y * 64;
    const int bn = blockIdx.x * 128;

    const __half* Ag = A  + (long)bm * lda;
    const __half* Bg = Bt + (long)bn * ldb;

    float acc[2][8][4];
#pragma unroll
    for (int i = 0; i < 2; i++)
#pragma unroll
        for (int j = 0; j < 8; j++)
#pragma unroll
            for (int q = 0; q < 4; q++) acc[i][j][q] = 0.f;

    auto stage = [&](int s, int k0) {
        __half* Ab = As + s * D_ASZ;
        __half* Bb = Bs + s * D_BSZ;
#pragma unroll
        for (int i = 0; i < 4; i++) {                 // A: 512 16B-chunks
            int ci = tid + (i << 7);
            int r = ci >> 3, c = (ci & 7) << 3;
            cpa16p(&Ab[r * 72 + c], Ag + (long)r * lda + k0 + c);
        }
#pragma unroll
        for (int i = 0; i < 8; i++) {                 // B: 1024 chunks
            int ci = tid + (i << 7);
            int r = ci >> 3, c = (ci & 7) << 3;
            cpa16p(&Bb[r * 72 + c], Bg + (long)r * ldb + k0 + c);
        }
        asm volatile("cp.async.commit_group;" ::: "memory");
    };

    auto compute = [&](int s) {
        uint32_t aBase = s2u(As + s * D_ASZ);
        uint32_t bBase = s2u(Bs + s * D_BSZ);
#pragma unroll
        for (int kk = 0; kk < 64; kk += 16) {
            uint32_t ar[2][4], br[4][4];
#pragma unroll
            for (int mt = 0; mt < 2; mt++) {
                uint32_t addr = aBase +
                    2u * ((wm * 32 + mt * 16 + (lane & 15)) * 72 + kk + ((lane >> 4) << 3));
                ldm_x4(ar[mt], addr);
            }
#pragma unroll
            for (int nt = 0; nt < 4; nt++) {
                uint32_t addr = bBase +
                    2u * ((wn * 64 + nt * 16 + (lane & 15)) * 72 + kk + ((lane >> 4) << 3));
                ldm_x4(br[nt], addr);
            }
#pragma unroll
            for (int mt = 0; mt < 2; mt++)
#pragma unroll
                for (int n8 = 0; n8 < 8; n8++) {
                    int nt = n8 >> 1, h = n8 & 1;
                    mma16816(acc[mt][n8], ar[mt], br[nt][h], br[nt][2 + h]);
                }
        }
    };

    const int nk = K >> 6;
    stage(0, 0);
    stage(1, 64);
    for (int kt = 0; kt < nk; kt++) {
        if (kt + 1 < nk) asm volatile("cp.async.wait_group 1;" ::: "memory");
        else             asm volatile("cp.async.wait_group 0;" ::: "memory");
        __syncthreads();
        compute(kt & 1);
        __syncthreads();
        if (kt + 2 < nk) stage(kt & 1, (kt + 2) << 6);
    }

    // epilogue
    const int r0 = bm + wm * 32 + (lane >> 2);
    const int c0 = bn + wn * 64 + ((lane & 3) << 1);
#pragma unroll
    for (int n8 = 0; n8 < 8; n8++) {
        int c = c0 + n8 * 8;
        float bb0 = 0.f, bb1 = 0.f;
        if (bias) { bb0 = __ldg(&bias[c]); bb1 = __ldg(&bias[c + 1]); }
#pragma unroll
        for (int mt = 0; mt < 2; mt++) {
#pragma unroll
            for (int hh = 0; hh < 2; hh++) {
                int r = r0 + mt * 16 + hh * 8;
                float v0 = acc[mt][n8][hh * 2 + 0] + bb0;
                float v1 = acc[mt][n8][hh * 2 + 1] + bb1;
                if (relu) { v0 = fmaxf(v0, 0.f); v1 = fmaxf(v1, 0.f); }
                if (outhalf) {
                    *reinterpret_cast<__half2*>(Ch + (long)r * ldc + c) =
                        __floats2half2_rn(v0, v1);
                } else {
                    *reinterpret_cast<float2*>(Cf + (long)r * ldc + c) = make_float2(v0, v1);
                }
            }
        }
    }
}

// ========== mma.sync GEMM for scores (EXPSUM) and AV =========================
template<int BN, bool BT, bool EXPSUM>
__global__ void __launch_bounds__(256, 2)
gemm_tc(const __half* __restrict__ A, const __half* __restrict__ B,
        void* __restrict__ Cout, float* __restrict__ psum,
        int K, int lda, int ldb, int ldc,
        long sAo, long sAi, long sBo, long sBi, long sCo, long sCi, int zdiv,
        float alpha2, float off2)
{
    extern __shared__ __half smem_dyn[];
    constexpr int ASIZE = 128 * 40;
    constexpr int BROWS = BT ? BN : 32;
    constexpr int BCOLS = BT ? 40 : (BN + 8);
    constexpr int BSIZE = BROWS * BCOLS;
    __half* Asm = smem_dyn;
    __half* Bsm = smem_dyn + 3 * ASIZE;

    const int zo = blockIdx.z / zdiv, zi = blockIdx.z - zo * zdiv;
    A += zo * sAo + zi * sAi;
    B += zo * sBo + zi * sBi;
    __half* Ch = (__half*)Cout + zo * sCo + zi * sCi;

    const int bm = blockIdx.y * 128;
    const int bn = blockIdx.x * BN;
    const int tid  = threadIdx.x;
    const int lane = tid & 31;
    const int warp = tid >> 5;
    const int wm   = warp & 3;
    const int wn   = warp >> 2;
    const int m_w  = wm * 32;
    const int n_w  = wn * (BN / 2);
    constexpr int NT8  = (BN / 2) / 8;
    constexpr int NT16 = (BN / 2) / 16;

    const __half* Ag = A + (long)bm * lda;
    const __half* Bg = BT ? (B + (long)bn * ldb) : (B + bn);

    float acc[2][NT8][4];
#pragma unroll
    for (int i = 0; i < 2; i++)
#pragma unroll
        for (int j = 0; j < NT8; j++)
#pragma unroll
            for (int q = 0; q < 4; q++) acc[i][j][q] = 0.f;

    auto stage = [&](int s, int k0) {
        __half* As = Asm + s * ASIZE;
        __half* Bs = Bsm + s * BSIZE;
#pragma unroll
        for (int i = 0; i < 2; i++) {
            int ci = tid + i * 256;
            int r = ci >> 2, kc = (ci & 3) << 3;
            cpa16p(&As[r * 40 + kc], Ag + (long)r * lda + k0 + kc);
        }
        if (BT) {
            constexpr int IT = (BN * 4) / 256;
#pragma unroll
            for (int i = 0; i < IT; i++) {
                int ci = tid + i * 256;
                int r = ci >> 2, kc = (ci & 3) << 3;
                cpa16p(&Bs[r * 40 + kc], Bg + (long)r * ldb + k0 + kc);
            }
        } else {
            constexpr int CH = BN / 8;
            constexpr int IT = (32 * CH) / 256;
#pragma unroll
            for (int i = 0; i < IT; i++) {
                int ci = tid + i * 256;
                int r = ci / CH, nc = (ci % CH) << 3;
                cpa16p(&Bs[r * BCOLS + nc], Bg + (long)(k0 + r) * ldb + nc);
            }
        }
    };

    auto compute = [&](int s) {
        uint32_t aBase = s2u(Asm + s * ASIZE);
        uint32_t bBase = s2u(Bsm + s * BSIZE);
#pragma unroll
        for (int kk = 0; kk < 32; kk += 16) {
            uint32_t ar[2][4];
#pragma unroll
            for (int mt = 0; mt < 2; mt++) {
                uint32_t addr = aBase +
                    2u * ((m_w + mt * 16 + (lane & 15)) * 40 + kk + ((lane >> 4) << 3));
                ldm_x4(ar[mt], addr);
            }
            uint32_t br[NT16][4];
#pragma unroll
            for (int nt = 0; nt < NT16; nt++) {
                if (BT) {
                    uint32_t addr = bBase +
                        2u * ((n_w + nt * 16 + (lane & 15)) * 40 + kk + ((lane >> 4) << 3));
                    ldm_x4(br[nt], addr);
                } else {
                    uint32_t addr = bBase +
                        2u * ((kk + (lane & 15)) * BCOLS + n_w + nt * 16 + ((lane >> 4) << 3));
                    ldm_x4_t(br[nt], addr);
                }
            }
#pragma unroll
            for (int mt = 0; mt < 2; mt++)
#pragma unroll
                for (int n8 = 0; n8 < NT8; n8++) {
                    int nt = n8 >> 1, h = n8 & 1;
                    uint32_t b0, b1;
                    if (BT) { b0 = br[nt][h];     b1 = br[nt][2 + h];     }
                    else    { b0 = br[nt][h * 2]; b1 = br[nt][h * 2 + 1]; }
                    mma16816(acc[mt][n8], ar[mt], b0, b1);
                }
        }
    };

    const int ntile = K >> 5;
    stage(0, 0);
    asm volatile("cp.async.commit_group;");
    stage(1, 32);
    asm volatile("cp.async.commit_group;");
    for (int kt = 0; kt < ntile; kt++) {
        asm volatile("cp.async.wait_group 1;");
        __syncthreads();
        if (kt + 2 < ntile) stage((kt + 2) % 3, (kt + 2) << 5);
        asm volatile("cp.async.commit_group;");
        compute(kt % 3);
    }

    const int r0 = bm + m_w + (lane >> 2);
    const int c0 = bn + n_w + ((lane & 3) << 1);

    if (EXPSUM) {
        float cs[NT8][2];
#pragma unroll
        for (int n8 = 0; n8 < NT8; n8++) { cs[n8][0] = 0.f; cs[n8][1] = 0.f; }
#pragma unroll
        for (int n8 = 0; n8 < NT8; n8++) {
            int c = c0 + n8 * 8;
#pragma unroll
            for (int mt = 0; mt < 2; mt++) {
#pragma unroll
                for (int hh = 0; hh < 2; hh++) {
                    int r = r0 + mt * 16 + hh * 8;
                    float v0 = exp2f(fmaf(acc[mt][n8][hh * 2 + 0], alpha2, off2));
                    float v1 = exp2f(fmaf(acc[mt][n8][hh * 2 + 1], alpha2, off2));
                    *reinterpret_cast<__half2*>(Ch + (long)r * ldc + c) =
                        __floats2half2_rn(v0, v1);
                    cs[n8][0] += v0; cs[n8][1] += v1;
                }
            }
        }
#pragma unroll
        for (int n8 = 0; n8 < NT8; n8++)
#pragma unroll
            for (int p = 0; p < 2; p++) {
                float v = cs[n8][p];
                v += __shfl_xor_sync(0xffffffffu, v, 4);
                v += __shfl_xor_sync(0xffffffffu, v, 8);
                v += __shfl_xor_sync(0xffffffffu, v, 16);
                cs[n8][p] = v;
            }
        __syncthreads();
        float* sred = (float*)smem_dyn;
        if (lane < 4) {
#pragma unroll
            for (int n8 = 0; n8 < NT8; n8++) {
                sred[warp * 64 + n8 * 8 + lane * 2 + 0] = cs[n8][0];
                sred[warp * 64 + n8 * 8 + lane * 2 + 1] = cs[n8][1];
            }
        }
        __syncthreads();
        if (tid < 128) {
            int wn2 = tid >> 6, cin = tid & 63;
            float t = 0.f;
#pragma unroll
            for (int w2 = 0; w2 < 4; w2++) t += sred[(wn2 * 4 + w2) * 64 + cin];
            psum[((long)blockIdx.y * gridDim.z + blockIdx.z) * ldc + bn + tid] = t;
        }
        return;
    }

#pragma unroll
    for (int n8 = 0; n8 < NT8; n8++) {
        int c = c0 + n8 * 8;
#pragma unroll
        for (int mt = 0; mt < 2; mt++) {
#pragma unroll
            for (int hh = 0; hh < 2; hh++) {
                int r = r0 + mt * 16 + hh * 8;
                float v0 = acc[mt][n8][hh * 2 + 0];
                float v1 = acc[mt][n8][hh * 2 + 1];
                *reinterpret_cast<__half2*>(Ch + (long)r * ldc + c) =
                    __floats2half2_rn(v0, v1);
            }
        }
    }
}

#define SMEM_128T (3*(128*40 + 128*40)*2)   // 61440
#define SMEM_64F  (3*(128*40 + 32*72)*2)    // 44544

// ---------------- weight transpose+convert kernels ---------------------------
__global__ void tr_f2h(const float* __restrict__ src, __half* __restrict__ dst,
                       int K, int N, long sSrc, long sDst)
{
    src += (long)blockIdx.z * sSrc;
    dst += (long)blockIdx.z * sDst;
    __shared__ float t[64][65];
    const int n0 = blockIdx.x * 64, k0 = blockIdx.y * 64;
    const int tid = threadIdx.x;
#pragma unroll
    for (int i = 0; i < 16; i++) {
        int idx = tid + i * 256;
        int r = idx >> 6, c = idx & 63;
        t[r][c] = src[(long)(k0 + r) * N + n0 + c];
    }
    __syncthreads();
#pragma unroll
    for (int i = 0; i < 16; i++) {
        int idx = tid + i * 256;
        int r = idx >> 6, c = idx & 63;
        dst[(long)(n0 + r) * K + k0 + c] = __float2half(t[c][r]);
    }
}

__global__ void tr_qkv_all(const float* __restrict__ Wq, const float* __restrict__ Wk,
                           const float* __restrict__ Wv, __half* __restrict__ dst)
{
    const int z = blockIdx.z;
    const int w = z / (Lq * Hq);
    const int lh = z - w * (Lq * Hq);
    const int l = lh / Hq, h = lh - l * Hq;
    const float* W = (w == 0) ? Wq : ((w == 1) ? Wk : Wv);
    const float* src = W + (long)lh * Cq * Dq;
    __half* d = dst + (long)l * C3 * Cq + (long)(w * 768 + h * Dq) * Cq;
    __shared__ float t[64][65];
    const int k0 = blockIdx.y * 64;
    const int tid = threadIdx.x;
#pragma unroll
    for (int i = 0; i < 16; i++) {
        int idx = tid + i * 256;
        int r = idx >> 6, c = idx & 63;
        t[r][c] = src[(long)(k0 + r) * Dq + c];
    }
    __syncthreads();
#pragma unroll
    for (int i = 0; i < 16; i++) {
        int idx = tid + i * 256;
        int r = idx >> 6, c = idx & 63;
        d[(long)r * Cq + k0 + c] = __float2half(t[c][r]);
    }
}

// ---------------- embed -------------------------------------------------------
__global__ void embed_kernel(const int* __restrict__ ids, const float* __restrict__ emb,
                             const float* __restrict__ pos,
                             float* __restrict__ x, __half* __restrict__ xb)
{
    int idx = blockIdx.x * blockDim.x + threadIdx.x;
    if (idx >= Mq * Cq) return;
    int m = idx / Cq, c = idx - m * Cq;
    int t = m & (Tq - 1);
    int tok = ids[m];
    float v = emb[(size_t)tok * Cq + c] + pos[(size_t)t * Cq + c];
    x[idx]  = v;
    xb[idx] = __float2half(v);
}

// vs[m][c] = V[m][c] / colsum
__global__ void vscale_kernel(const __half* __restrict__ qkv,
                              const float* __restrict__ ps, __half* __restrict__ vs)
{
    int idx = blockIdx.x * blockDim.x + threadIdx.x;
    if (idx >= Mq * Cq / 2) return;
    int c2 = idx % (Cq / 2);
    int m  = idx / (Cq / 2);
    int c  = c2 * 2;
    int b  = m >> 9, t = m & 511, h = c >> 6;
    long si = (((long)b * Hq + h) << 9) + t;
    float s = ps[si] + ps[(long)BHq * Tq + si]
            + ps[2L * BHq * Tq + si] + ps[3L * BHq * Tq + si];
    float r = 1.f / s;
    __half2 v = *reinterpret_cast<const __half2*>(&qkv[(long)m * C3 + 1536 + c]);
    float2 f = __half22float2(v);
    *reinterpret_cast<__half2*>(&vs[(long)m * Cq + c]) = __floats2half2_rn(f.x * r, f.y * r);
}

// ---------------- residual add (split-K sum) + bias + layernorm ---------------
// 192 threads, one float4 per thread (768 = 192*4)
__global__ void __launch_bounds__(192)
add_ln_kernel(float* __restrict__ x, const float* __restrict__ y0,
              const float* __restrict__ y1, const float* __restrict__ bias,
              const float* __restrict__ g, const float* __restrict__ bta,
              __half* __restrict__ xb)
{
    __shared__ float sh[6];
    long row = blockIdx.x;
    int tid = threadIdx.x;
    int c = tid << 2;
    float4 xv = *reinterpret_cast<const float4*>(&x [row * Cq + c]);
    float4 a0 = *reinterpret_cast<const float4*>(&y0[row * Cq + c]);
    float4 a1 = *reinterpret_cast<const float4*>(&y1[row * Cq + c]);
    float4 bv = *reinterpret_cast<const float4*>(&bias[c]);
    float v0 = xv.x + a0.x + a1.x + bv.x;
    float v1 = xv.y + a0.y + a1.y + bv.y;
    float v2 = xv.z + a0.z + a1.z + bv.z;
    float v3 = xv.w + a0.w + a1.w + bv.w;

    float s = v0 + v1 + v2 + v3;
#pragma unroll
    for (int o = 16; o > 0; o >>= 1) s += __shfl_xor_sync(0xffffffffu, s, o);
    if ((tid & 31) == 0) sh[tid >> 5] = s;
    __syncthreads();
    float mu = (sh[0] + sh[1] + sh[2] + sh[3] + sh[4] + sh[5]) * (1.f / Cq);
    __syncthreads();

    float d0 = v0 - mu, d1 = v1 - mu, d2 = v2 - mu, d3 = v3 - mu;
    float s2 = d0 * d0 + d1 * d1 + d2 * d2 + d3 * d3;
#pragma unroll
    for (int o = 16; o > 0; o >>= 1) s2 += __shfl_xor_sync(0xffffffffu, s2, o);
    if ((tid & 31) == 0) sh[tid >> 5] = s2;
    __syncthreads();
    float var = (sh[0] + sh[1] + sh[2] + sh[3] + sh[4] + sh[5]) * (1.f / Cq);
    float rstd = rsqrtf(var + 1e-5f);

    float4 gv = *reinterpret_cast<const float4*>(&g[c]);
    float4 tv = *reinterpret_cast<const float4*>(&bta[c]);
    float o0 = d0 * rstd * gv.x + tv.x;
    float o1 = d1 * rstd * gv.y + tv.y;
    float o2 = d2 * rstd * gv.z + tv.z;
    float o3 = d3 * rstd * gv.w + tv.w;
    *reinterpret_cast<float4*>(&x[row * Cq + c]) = make_float4(o0, o1, o2, o3);
    __half2 h0 = __floats2half2_rn(o0, o1);
    __half2 h1 = __floats2half2_rn(o2, o3);
    *reinterpret_cast<__half2*>(&xb[row * Cq + c])     = h0;
    *reinterpret_cast<__half2*>(&xb[row * Cq + c + 2]) = h1;
}

// ---------------- launch -------------------------------------------------------
extern "C" void kernel_launch(void* const* d_in, const int* in_sizes, int n_in,
                              void* d_out, int out_size)
{
    const int*   ids  = (const int*)  d_in[0];
    const float* emb  = (const float*)d_in[1];
    const float* pos  = (const float*)d_in[2];
    const float* Wq   = (const float*)d_in[3];
    const float* Wk   = (const float*)d_in[4];
    const float* Wv   = (const float*)d_in[5];
    const float* Wo   = (const float*)d_in[6];
    const float* bo   = (const float*)d_in[7];
    const float* ln1g = (const float*)d_in[8];
    const float* ln1b = (const float*)d_in[9];
    const float* W1   = (const float*)d_in[10];
    const float* b1   = (const float*)d_in[11];
    const float* W2   = (const float*)d_in[12];
    const float* b2   = (const float*)d_in[13];
    const float* ln2g = (const float*)d_in[14];
    const float* ln2b = (const float*)d_in[15];
    const float* decW = (const float*)d_in[16];
    const float* decb = (const float*)d_in[17];
    float* out = (float*)d_out;

    cudaFuncSetAttribute(gemm_d,
        cudaFuncAttributeMaxDynamicSharedMemorySize, D_SMEM);
    cudaFuncSetAttribute(gemm_tc<128, true, true>,
        cudaFuncAttributeMaxDynamicSharedMemorySize, SMEM_128T);
    cudaFuncSetAttribute(gemm_tc<64, false, false>,
        cudaFuncAttributeMaxDynamicSharedMemorySize, SMEM_64F);

    float *x, *t2, *ps;
    __half *xb, *qkvb, *pb, *vs, *t1b, *ffnb;
    __half *wqkv, *wob, *w1b, *w2b, *wdb;
    cudaGetSymbolAddress((void**)&x,    g_x);
    cudaGetSymbolAddress((void**)&t2,   g_t2);
    cudaGetSymbolAddress((void**)&ps,   g_ps);
    cudaGetSymbolAddress((void**)&xb,   g_xb);
    cudaGetSymbolAddress((void**)&qkvb, g_qkvb);
    cudaGetSymbolAddress((void**)&pb,   g_pb);
    cudaGetSymbolAddress((void**)&vs,   g_vs);
    cudaGetSymbolAddress((void**)&t1b,  g_t1b);
    cudaGetSymbolAddress((void**)&ffnb, g_ffnb);
    cudaGetSymbolAddress((void**)&wqkv, g_wqkv);
    cudaGetSymbolAddress((void**)&wob,  g_wob);
    cudaGetSymbolAddress((void**)&w1b,  g_w1b);
    cudaGetSymbolAddress((void**)&w2b,  g_w2b);
    cudaGetSymbolAddress((void**)&wdb,  g_wdb);

    // launch 1: embed; 2: qkv weights; 3: Wo; 4: QKV GEMM layer 0 (ncu target)
    embed_kernel<<<(Mq * Cq + 255) / 256, 256>>>(ids, emb, pos, x, xb);
    tr_qkv_all<<<dim3(1, 12, 3 * Lq * Hq), 256>>>(Wq, Wk, Wv, wqkv);
    tr_f2h<<<dim3(12, 12, Lq), 256>>>(Wo, wob, Cq, Cq, (long)Cq * Cq, (long)Cq * Cq);
    gemm_d<<<dim3(C3 / 128, Mq / 64, 1), 128, D_SMEM>>>(
        xb, wqkv, nullptr, qkvb, Cq, Cq, Cq, C3, 0, 0, 0, 1);
    tr_f2h<<<dim3(48, 12, Lq), 256>>>(W1, w1b, Cq, FFq, (long)Cq * FFq, (long)Cq * FFq);
    tr_f2h<<<dim3(12, 48, Lq), 256>>>(W2, w2b, FFq, Cq, (long)FFq * Cq, (long)FFq * Cq);
    tr_f2h<<<dim3(500, 12, 1), 256>>>(decW, wdb, Cq, Vq, 0, 0);

    for (int l = 0; l < Lq; l++) {
        const __half* wol = wob + (size_t)l * Cq * Cq;
        const __half* w1l = w1b + (size_t)l * Cq * FFq;
        const __half* w2l = w2b + (size_t)l * FFq * Cq;
        const float* bol = bo + (size_t)l * Cq;
        const float* b1l = b1 + (size_t)l * FFq;
        const float* b2l = b2 + (size_t)l * Cq;

        // scores + exp2 + column partial sums: pb = exp2(0.125*log2e*S - 4*log2e)
        gemm_tc<128, true, true><<<dim3(Tq / 128, Tq / 128, BHq), 256, SMEM_128T>>>(
            qkvb, qkvb + 768, pb, ps,
            Dq, C3, C3, Tq,
            (long)Tq * C3, Dq, (long)Tq * C3, Dq, (long)Hq * TT, TT, Hq,
            0.125f * LOG2E, -4.f * LOG2E);

        vscale_kernel<<<(Mq * Cq / 2 + 255) / 256, 256>>>(qkvb, ps, vs);

        // AV (out fp16, concat-head layout)
        gemm_tc<64, false, false><<<dim3(1, Tq / 128, BHq), 256, SMEM_64F>>>(
            pb, vs, t1b, nullptr,
            Tq, Tq, Cq, Cq,
            (long)Hq * TT, TT, (long)Tq * Cq, Dq, (long)Tq * Cq, Dq, Hq,
            0.f, 0.f);

        // output projection: split-K x2 -> t2[0], t2[1]; bias in add_ln
        gemm_d<<<dim3(Cq / 128, Mq / 64, 2), 128, D_SMEM>>>(
            t1b, wol, nullptr, t2, Cq / 2, Cq, Cq, Cq,
            (long)(Cq / 2), (long)Mq * Cq, 0, 0);
        add_ln_kernel<<<Mq, 192>>>(x, t2, t2 + (long)Mq * Cq, bol,
            ln1g + (size_t)l * Cq, ln1b + (size_t)l * Cq, xb);

        // FFN1 (full-K, throughput-bound)
        gemm_d<<<dim3(FFq / 128, Mq / 64, 1), 128, D_SMEM>>>(
            xb, w1l, b1l, ffnb, Cq, Cq, Cq, FFq, 0, 0, 1, 1);
        // FFN2: split-K x2
        gemm_d<<<dim3(Cq / 128, Mq / 64, 2), 128, D_SMEM>>>(
            ffnb, w2l, nullptr, t2, FFq / 2, FFq, FFq, Cq,
            (long)(FFq / 2), (long)Mq * Cq, 0, 0);
        add_ln_kernel<<<Mq, 192>>>(x, t2, t2 + (long)Mq * Cq, b2l,
            ln2g + (size_t)l * Cq, ln2b + (size_t)l * Cq, xb);

        // QKV for next layer
        if (l + 1 < Lq) {
            const __half* wq1 = wqkv + (size_t)(l + 1) * C3 * Cq;
            gemm_d<<<dim3(C3 / 128, Mq / 64, 1), 128, D_SMEM>>>(
                xb, wq1, nullptr, qkvb, Cq, Cq, Cq, C3, 0, 0, 0, 1);
        }
    }

    // decoder: [4096,768] @ [768,32000] + bias (out fp32)
    gemm_d<<<dim3(Vq / 128, Mq / 64, 1), 128, D_SMEM>>>(
        xb, wdb, decb, out, Cq, Cq, Cq, Vq, 0, 0, 0, 0);
}

// round 13
// speedup vs baseline: 1.0501x; 1.0004x over previous
#include <cuda_runtime.h>
#include <cuda_fp16.h>
#include <cstdint>

#define Bq 8
#define Tq 512
#define Cq 768
#define Hq 12
#define Dq 64
#define Lq 12
#define Vq 32000
#define FFq 3072
#define Mq (Bq*Tq)          // 4096
#define BHq (Bq*Hq)         // 96
#define TT  (Tq*Tq)         // 262144
#define C3  (3*Cq)          // 2304
#define LOG2E 1.4426950408889634f

// ---------------- scratch (device globals) ----------------------------------
__device__ float g_x  [Mq*Cq];
__device__ float g_ps [4*BHq*Tq];

__device__ __half g_t2h  [2*(size_t)Mq*Cq];   // split-K partial outputs (fp16)
__device__ __half g_xb   [Mq*Cq];
__device__ __half g_qkvb [(size_t)Mq*C3];
__device__ __half g_pb   [(size_t)BHq*TT];
__device__ __half g_vs   [Mq*Cq];
__device__ __half g_t1b  [Mq*Cq];
__device__ __half g_ffnb [(size_t)Mq*FFq];
__device__ __half g_wqkv [(size_t)Lq*C3*Cq];
__device__ __half g_wob  [(size_t)Lq*Cq*Cq];
__device__ __half g_w1b  [(size_t)Lq*FFq*Cq];
__device__ __half g_w2b  [(size_t)Lq*Cq*FFq];
__device__ __half g_wdb  [(size_t)Vq*Cq];

// ---------------- small helpers ---------------------------------------------
__device__ __forceinline__ uint32_t s2u(const void* p) {
    return (uint32_t)__cvta_generic_to_shared(p);
}
__device__ __forceinline__ void cpa16p(void* smem, const void* gmem) {
    asm volatile("cp.async.cg.shared.global [%0], [%1], 16;\n"
        :: "r"(s2u(smem)), "l"(gmem));
}
__device__ __forceinline__ void ldm_x4(uint32_t* r, uint32_t addr) {
    asm volatile("ldmatrix.sync.aligned.m8n8.x4.shared.b16 {%0,%1,%2,%3}, [%4];"
        : "=r"(r[0]), "=r"(r[1]), "=r"(r[2]), "=r"(r[3]) : "r"(addr));
}
__device__ __forceinline__ void ldm_x4_t(uint32_t* r, uint32_t addr) {
    asm volatile("ldmatrix.sync.aligned.m8n8.x4.trans.shared.b16 {%0,%1,%2,%3}, [%4];"
        : "=r"(r[0]), "=r"(r[1]), "=r"(r[2]), "=r"(r[3]) : "r"(addr));
}
__device__ __forceinline__ void mma16816(float* c, const uint32_t* a, uint32_t b0, uint32_t b1) {
    asm volatile(
        "mma.sync.aligned.m16n8k16.row.col.f32.f16.f16.f32 "
        "{%0,%1,%2,%3}, {%4,%5,%6,%7}, {%8,%9}, {%0,%1,%2,%3};"
        : "+f"(c[0]), "+f"(c[1]), "+f"(c[2]), "+f"(c[3])
        : "r"(a[0]), "r"(a[1]), "r"(a[2]), "r"(a[3]), "r"(b0), "r"(b1));
}

// ============ dense GEMM: C[M,N] = A[M,K-slice] @ Bt[N,K-slice]^T ============
// CTA 64x128, 128 threads (4 warps, 2m x 2n), warp tile 32x64, BK=64,
// 2-stage cp.async, 4 CTAs/SM. Split-K via blockIdx.z (offset z*sK, out +z*sC).
#define D_ASZ  (64*72)
#define D_BSZ  (128*72)
#define D_SMEM (2*(D_ASZ + D_BSZ)*2)     // 55296 bytes

__global__ void __launch_bounds__(128, 4)
gemm_d(const __half* __restrict__ A, const __half* __restrict__ Bt,
       const float* __restrict__ bias, void* __restrict__ Cout,
       int K, int lda, int ldb, int ldc,
       long sK, long sC, int relu, int outhalf)
{
    extern __shared__ __half sm[];
    __half* As = sm;                 // [2][64][72]
    __half* Bs = sm + 2 * D_ASZ;     // [2][128][72]

    A  += (long)blockIdx.z * sK;
    Bt += (long)blockIdx.z * sK;
    float*  Cf = (float*)Cout  + (long)blockIdx.z * sC;
    __half* Ch = (__half*)Cout + (long)blockIdx.z * sC;

    const int tid  = threadIdx.x;
    const int lane = tid & 31;
    const int warp = tid >> 5;
    const int wm   = warp >> 1;          // 0..1
    const int wn   = warp & 1;           // 0..1
    const int bm = blockIdx.y * 64;
    const int bn = blockIdx.x * 128;

    const __half* Ag = A  + (long)bm * lda;
    const __half* Bg = Bt + (long)bn * ldb;

    float acc[2][8][4];
#pragma unroll
    for (int i = 0; i < 2; i++)
#pragma unroll
        for (int j = 0; j < 8; j++)
#pragma unroll
            for (int q = 0; q < 4; q++) acc[i][j][q] = 0.f;

    auto stage = [&](int s, int k0) {
        __half* Ab = As + s * D_ASZ;
        __half* Bb = Bs + s * D_BSZ;
#pragma unroll
        for (int i = 0; i < 4; i++) {                 // A: 512 16B-chunks
            int ci = tid + (i << 7);
            int r = ci >> 3, c = (ci & 7) << 3;
            cpa16p(&Ab[r * 72 + c], Ag + (long)r * lda + k0 + c);
        }
#pragma unroll
        for (int i = 0; i < 8; i++) {                 // B: 1024 chunks
            int ci = tid + (i << 7);
            int r = ci >> 3, c = (ci & 7) << 3;
            cpa16p(&Bb[r * 72 + c], Bg + (long)r * ldb + k0 + c);
        }
        asm volatile("cp.async.commit_group;" ::: "memory");
    };

    auto compute = [&](int s) {
        uint32_t aBase = s2u(As + s * D_ASZ);
        uint32_t bBase = s2u(Bs + s * D_BSZ);
#pragma unroll
        for (int kk = 0; kk < 64; kk += 16) {
            uint32_t ar[2][4], br[4][4];
#pragma unroll
            for (int mt = 0; mt < 2; mt++) {
                uint32_t addr = aBase +
                    2u * ((wm * 32 + mt * 16 + (lane & 15)) * 72 + kk + ((lane >> 4) << 3));
                ldm_x4(ar[mt], addr);
            }
#pragma unroll
            for (int nt = 0; nt < 4; nt++) {
                uint32_t addr = bBase +
                    2u * ((wn * 64 + nt * 16 + (lane & 15)) * 72 + kk + ((lane >> 4) << 3));
                ldm_x4(br[nt], addr);
            }
#pragma unroll
            for (int mt = 0; mt < 2; mt++)
#pragma unroll
                for (int n8 = 0; n8 < 8; n8++) {
                    int nt = n8 >> 1, h = n8 & 1;
                    mma16816(acc[mt][n8], ar[mt], br[nt][h], br[nt][2 + h]);
                }
        }
    };

    const int nk = K >> 6;
    stage(0, 0);
    stage(1, 64);
    for (int kt = 0; kt < nk; kt++) {
        if (kt + 1 < nk) asm volatile("cp.async.wait_group 1;" ::: "memory");
        else             asm volatile("cp.async.wait_group 0;" ::: "memory");
        __syncthreads();
        compute(kt & 1);
        __syncthreads();
        if (kt + 2 < nk) stage(kt & 1, (kt + 2) << 6);
    }

    // epilogue
    const int r0 = bm + wm * 32 + (lane >> 2);
    const int c0 = bn + wn * 64 + ((lane & 3) << 1);
#pragma unroll
    for (int n8 = 0; n8 < 8; n8++) {
        int c = c0 + n8 * 8;
        float bb0 = 0.f, bb1 = 0.f;
        if (bias) { bb0 = __ldg(&bias[c]); bb1 = __ldg(&bias[c + 1]); }
#pragma unroll
        for (int mt = 0; mt < 2; mt++) {
#pragma unroll
            for (int hh = 0; hh < 2; hh++) {
                int r = r0 + mt * 16 + hh * 8;
                float v0 = acc[mt][n8][hh * 2 + 0] + bb0;
                float v1 = acc[mt][n8][hh * 2 + 1] + bb1;
                if (relu) { v0 = fmaxf(v0, 0.f); v1 = fmaxf(v1, 0.f); }
                if (outhalf) {
                    *reinterpret_cast<__half2*>(Ch + (long)r * ldc + c) =
                        __floats2half2_rn(v0, v1);
                } else {
                    *reinterpret_cast<float2*>(Cf + (long)r * ldc + c) = make_float2(v0, v1);
                }
            }
        }
    }
}

// ========== mma.sync GEMM for scores (EXPSUM) and AV =========================
template<int BN, bool BT, bool EXPSUM>
__global__ void __launch_bounds__(256, 2)
gemm_tc(const __half* __restrict__ A, const __half* __restrict__ B,
        void* __restrict__ Cout, float* __restrict__ psum,
        int K, int lda, int ldb, int ldc,
        long sAo, long sAi, long sBo, long sBi, long sCo, long sCi, int zdiv,
        float alpha2, float off2)
{
    extern __shared__ __half smem_dyn[];
    constexpr int ASIZE = 128 * 40;
    constexpr int BROWS = BT ? BN : 32;
    constexpr int BCOLS = BT ? 40 : (BN + 8);
    constexpr int BSIZE = BROWS * BCOLS;
    __half* Asm = smem_dyn;
    __half* Bsm = smem_dyn + 3 * ASIZE;

    const int zo = blockIdx.z / zdiv, zi = blockIdx.z - zo * zdiv;
    A += zo * sAo + zi * sAi;
    B += zo * sBo + zi * sBi;
    __half* Ch = (__half*)Cout + zo * sCo + zi * sCi;

    const int bm = blockIdx.y * 128;
    const int bn = blockIdx.x * BN;
    const int tid  = threadIdx.x;
    const int lane = tid & 31;
    const int warp = tid >> 5;
    const int wm   = warp & 3;
    const int wn   = warp >> 2;
    const int m_w  = wm * 32;
    const int n_w  = wn * (BN / 2);
    constexpr int NT8  = (BN / 2) / 8;
    constexpr int NT16 = (BN / 2) / 16;

    const __half* Ag = A + (long)bm * lda;
    const __half* Bg = BT ? (B + (long)bn * ldb) : (B + bn);

    float acc[2][NT8][4];
#pragma unroll
    for (int i = 0; i < 2; i++)
#pragma unroll
        for (int j = 0; j < NT8; j++)
#pragma unroll
            for (int q = 0; q < 4; q++) acc[i][j][q] = 0.f;

    auto stage = [&](int s, int k0) {
        __half* As = Asm + s * ASIZE;
        __half* Bs = Bsm + s * BSIZE;
#pragma unroll
        for (int i = 0; i < 2; i++) {
            int ci = tid + i * 256;
            int r = ci >> 2, kc = (ci & 3) << 3;
            cpa16p(&As[r * 40 + kc], Ag + (long)r * lda + k0 + kc);
        }
        if (BT) {
            constexpr int IT = (BN * 4) / 256;
#pragma unroll
            for (int i = 0; i < IT; i++) {
                int ci = tid + i * 256;
                int r = ci >> 2, kc = (ci & 3) << 3;
                cpa16p(&Bs[r * 40 + kc], Bg + (long)r * ldb + k0 + kc);
            }
        } else {
            constexpr int CH = BN / 8;
            constexpr int IT = (32 * CH) / 256;
#pragma unroll
            for (int i = 0; i < IT; i++) {
                int ci = tid + i * 256;
                int r = ci / CH, nc = (ci % CH) << 3;
                cpa16p(&Bs[r * BCOLS + nc], Bg + (long)(k0 + r) * ldb + nc);
            }
        }
    };

    auto compute = [&](int s) {
        uint32_t aBase = s2u(Asm + s * ASIZE);
        uint32_t bBase = s2u(Bsm + s * BSIZE);
#pragma unroll
        for (int kk = 0; kk < 32; kk += 16) {
            uint32_t ar[2][4];
#pragma unroll
            for (int mt = 0; mt < 2; mt++) {
                uint32_t addr = aBase +
                    2u * ((m_w + mt * 16 + (lane & 15)) * 40 + kk + ((lane >> 4) << 3));
                ldm_x4(ar[mt], addr);
            }
            uint32_t br[NT16][4];
#pragma unroll
            for (int nt = 0; nt < NT16; nt++) {
                if (BT) {
                    uint32_t addr = bBase +
                        2u * ((n_w + nt * 16 + (lane & 15)) * 40 + kk + ((lane >> 4) << 3));
                    ldm_x4(br[nt], addr);
                } else {
                    uint32_t addr = bBase +
                        2u * ((kk + (lane & 15)) * BCOLS + n_w + nt * 16 + ((lane >> 4) << 3));
                    ldm_x4_t(br[nt], addr);
                }
            }
#pragma unroll
            for (int mt = 0; mt < 2; mt++)
#pragma unroll
                for (int n8 = 0; n8 < NT8; n8++) {
                    int nt = n8 >> 1, h = n8 & 1;
                    uint32_t b0, b1;
                    if (BT) { b0 = br[nt][h];     b1 = br[nt][2 + h];     }
                    else    { b0 = br[nt][h * 2]; b1 = br[nt][h * 2 + 1]; }
                    mma16816(acc[mt][n8], ar[mt], b0, b1);
                }
        }
    };

    const int ntile = K >> 5;
    stage(0, 0);
    asm volatile("cp.async.commit_group;");
    stage(1, 32);
    asm volatile("cp.async.commit_group;");
    for (int kt = 0; kt < ntile; kt++) {
        asm volatile("cp.async.wait_group 1;");
        __syncthreads();
        if (kt + 2 < ntile) stage((kt + 2) % 3, (kt + 2) << 5);
        asm volatile("cp.async.commit_group;");
        compute(kt % 3);
    }

    const int r0 = bm + m_w + (lane >> 2);
    const int c0 = bn + n_w + ((lane & 3) << 1);

    if (EXPSUM) {
        float cs[NT8][2];
#pragma unroll
        for (int n8 = 0; n8 < NT8; n8++) { cs[n8][0] = 0.f; cs[n8][1] = 0.f; }
#pragma unroll
        for (int n8 = 0; n8 < NT8; n8++) {
            int c = c0 + n8 * 8;
#pragma unroll
            for (int mt = 0; mt < 2; mt++) {
#pragma unroll
                for (int hh = 0; hh < 2; hh++) {
                    int r = r0 + mt * 16 + hh * 8;
                    float v0 = exp2f(fmaf(acc[mt][n8][hh * 2 + 0], alpha2, off2));
                    float v1 = exp2f(fmaf(acc[mt][n8][hh * 2 + 1], alpha2, off2));
                    *reinterpret_cast<__half2*>(Ch + (long)r * ldc + c) =
                        __floats2half2_rn(v0, v1);
                    cs[n8][0] += v0; cs[n8][1] += v1;
                }
            }
        }
#pragma unroll
        for (int n8 = 0; n8 < NT8; n8++)
#pragma unroll
            for (int p = 0; p < 2; p++) {
                float v = cs[n8][p];
                v += __shfl_xor_sync(0xffffffffu, v, 4);
                v += __shfl_xor_sync(0xffffffffu, v, 8);
                v += __shfl_xor_sync(0xffffffffu, v, 16);
                cs[n8][p] = v;
            }
        __syncthreads();
        float* sred = (float*)smem_dyn;
        if (lane < 4) {
#pragma unroll
            for (int n8 = 0; n8 < NT8; n8++) {
                sred[warp * 64 + n8 * 8 + lane * 2 + 0] = cs[n8][0];
                sred[warp * 64 + n8 * 8 + lane * 2 + 1] = cs[n8][1];
            }
        }
        __syncthreads();
        if (tid < 128) {
            int wn2 = tid >> 6, cin = tid & 63;
            float t = 0.f;
#pragma unroll
            for (int w2 = 0; w2 < 4; w2++) t += sred[(wn2 * 4 + w2) * 64 + cin];
            psum[((long)blockIdx.y * gridDim.z + blockIdx.z) * ldc + bn + tid] = t;
        }
        return;
    }

#pragma unroll
    for (int n8 = 0; n8 < NT8; n8++) {
        int c = c0 + n8 * 8;
#pragma unroll
        for (int mt = 0; mt < 2; mt++) {
#pragma unroll
            for (int hh = 0; hh < 2; hh++) {
                int r = r0 + mt * 16 + hh * 8;
                float v0 = acc[mt][n8][hh * 2 + 0];
                float v1 = acc[mt][n8][hh * 2 + 1];
                *reinterpret_cast<__half2*>(Ch + (long)r * ldc + c) =
                    __floats2half2_rn(v0, v1);
            }
        }
    }
}

#define SMEM_128T (3*(128*40 + 128*40)*2)   // 61440
#define SMEM_64F  (3*(128*40 + 32*72)*2)    // 44544

// ---------------- weight transpose+convert kernels ---------------------------
__global__ void tr_f2h(const float* __restrict__ src, __half* __restrict__ dst,
                       int K, int N, long sSrc, long sDst)
{
    src += (long)blockIdx.z * sSrc;
    dst += (long)blockIdx.z * sDst;
    __shared__ float t[64][65];
    const int n0 = blockIdx.x * 64, k0 = blockIdx.y * 64;
    const int tid = threadIdx.x;
#pragma unroll
    for (int i = 0; i < 16; i++) {
        int idx = tid + i * 256;
        int r = idx >> 6, c = idx & 63;
        t[r][c] = src[(long)(k0 + r) * N + n0 + c];
    }
    __syncthreads();
#pragma unroll
    for (int i = 0; i < 16; i++) {
        int idx = tid + i * 256;
        int r = idx >> 6, c = idx & 63;
        dst[(long)(n0 + r) * K + k0 + c] = __float2half(t[c][r]);
    }
}

__global__ void tr_qkv_all(const float* __restrict__ Wq, const float* __restrict__ Wk,
                           const float* __restrict__ Wv, __half* __restrict__ dst)
{
    const int z = blockIdx.z;
    const int w = z / (Lq * Hq);
    const int lh = z - w * (Lq * Hq);
    const int l = lh / Hq, h = lh - l * Hq;
    const float* W = (w == 0) ? Wq : ((w == 1) ? Wk : Wv);
    const float* src = W + (long)lh * Cq * Dq;
    __half* d = dst + (long)l * C3 * Cq + (long)(w * 768 + h * Dq) * Cq;
    __shared__ float t[64][65];
    const int k0 = blockIdx.y * 64;
    const int tid = threadIdx.x;
#pragma unroll
    for (int i = 0; i < 16; i++) {
        int idx = tid + i * 256;
        int r = idx >> 6, c = idx & 63;
        t[r][c] = src[(long)(k0 + r) * Dq + c];
    }
    __syncthreads();
#pragma unroll
    for (int i = 0; i < 16; i++) {
        int idx = tid + i * 256;
        int r = idx >> 6, c = idx & 63;
        d[(long)r * Cq + k0 + c] = __float2half(t[c][r]);
    }
}

// ---------------- embed -------------------------------------------------------
__global__ void embed_kernel(const int* __restrict__ ids, const float* __restrict__ emb,
                             const float* __restrict__ pos,
                             float* __restrict__ x, __half* __restrict__ xb)
{
    int idx = blockIdx.x * blockDim.x + threadIdx.x;
    if (idx >= Mq * Cq) return;
    int m = idx / Cq, c = idx - m * Cq;
    int t = m & (Tq - 1);
    int tok = ids[m];
    float v = emb[(size_t)tok * Cq + c] + pos[(size_t)t * Cq + c];
    x[idx]  = v;
    xb[idx] = __float2half(v);
}

// vs[m][c] = V[m][c] / colsum
__global__ void vscale_kernel(const __half* __restrict__ qkv,
                              const float* __restrict__ ps, __half* __restrict__ vs)
{
    int idx = blockIdx.x * blockDim.x + threadIdx.x;
    if (idx >= Mq * Cq / 2) return;
    int c2 = idx % (Cq / 2);
    int m  = idx / (Cq / 2);
    int c  = c2 * 2;
    int b  = m >> 9, t = m & 511, h = c >> 6;
    long si = (((long)b * Hq + h) << 9) + t;
    float s = ps[si] + ps[(long)BHq * Tq + si]
            + ps[2L * BHq * Tq + si] + ps[3L * BHq * Tq + si];
    float r = 1.f / s;
    __half2 v = *reinterpret_cast<const __half2*>(&qkv[(long)m * C3 + 1536 + c]);
    float2 f = __half22float2(v);
    *reinterpret_cast<__half2*>(&vs[(long)m * Cq + c]) = __floats2half2_rn(f.x * r, f.y * r);
}

// ---------------- residual add (fp16 split-K partials) + bias + layernorm -----
// 192 threads, one float4 per thread (768 = 192*4)
__global__ void __launch_bounds__(192)
add_ln_kernel(float* __restrict__ x, const __half* __restrict__ y0,
              const __half* __restrict__ y1, const float* __restrict__ bias,
              const float* __restrict__ g, const float* __restrict__ bta,
              __half* __restrict__ xb)
{
    __shared__ float sh[6];
    long row = blockIdx.x;
    int tid = threadIdx.x;
    int c = tid << 2;
    float4 xv = *reinterpret_cast<const float4*>(&x [row * Cq + c]);
    uint2 u0 = *reinterpret_cast<const uint2*>(&y0[row * Cq + c]);
    uint2 u1 = *reinterpret_cast<const uint2*>(&y1[row * Cq + c]);
    float2 a0lo = __half22float2(*reinterpret_cast<__half2*>(&u0.x));
    float2 a0hi = __half22float2(*reinterpret_cast<__half2*>(&u0.y));
    float2 a1lo = __half22float2(*reinterpret_cast<__half2*>(&u1.x));
    float2 a1hi = __half22float2(*reinterpret_cast<__half2*>(&u1.y));
    float4 bv = *reinterpret_cast<const float4*>(&bias[c]);
    float v0 = xv.x + a0lo.x + a1lo.x + bv.x;
    float v1 = xv.y + a0lo.y + a1lo.y + bv.y;
    float v2 = xv.z + a0hi.x + a1hi.x + bv.z;
    float v3 = xv.w + a0hi.y + a1hi.y + bv.w;

    float s = v0 + v1 + v2 + v3;
#pragma unroll
    for (int o = 16; o > 0; o >>= 1) s += __shfl_xor_sync(0xffffffffu, s, o);
    if ((tid & 31) == 0) sh[tid >> 5] = s;
    __syncthreads();
    float mu = (sh[0] + sh[1] + sh[2] + sh[3] + sh[4] + sh[5]) * (1.f / Cq);
    __syncthreads();

    float d0 = v0 - mu, d1 = v1 - mu, d2 = v2 - mu, d3 = v3 - mu;
    float s2 = d0 * d0 + d1 * d1 + d2 * d2 + d3 * d3;
#pragma unroll
    for (int o = 16; o > 0; o >>= 1) s2 += __shfl_xor_sync(0xffffffffu, s2, o);
    if ((tid & 31) == 0) sh[tid >> 5] = s2;
    __syncthreads();
    float var = (sh[0] + sh[1] + sh[2] + sh[3] + sh[4] + sh[5]) * (1.f / Cq);
    float rstd = rsqrtf(var + 1e-5f);

    float4 gv = *reinterpret_cast<const float4*>(&g[c]);
    float4 tv = *reinterpret_cast<const float4*>(&bta[c]);
    float o0 = d0 * rstd * gv.x + tv.x;
    float o1 = d1 * rstd * gv.y + tv.y;
    float o2 = d2 * rstd * gv.z + tv.z;
    float o3 = d3 * rstd * gv.w + tv.w;
    *reinterpret_cast<float4*>(&x[row * Cq + c]) = make_float4(o0, o1, o2, o3);
    __half2 h0 = __floats2half2_rn(o0, o1);
    __half2 h1 = __floats2half2_rn(o2, o3);
    *reinterpret_cast<__half2*>(&xb[row * Cq + c])     = h0;
    *reinterpret_cast<__half2*>(&xb[row * Cq + c + 2]) = h1;
}

// ---------------- launch -------------------------------------------------------
extern "C" void kernel_launch(void* const* d_in, const int* in_sizes, int n_in,
                              void* d_out, int out_size)
{
    const int*   ids  = (const int*)  d_in[0];
    const float* emb  = (const float*)d_in[1];
    const float* pos  = (const float*)d_in[2];
    const float* Wq   = (const float*)d_in[3];
    const float* Wk   = (const float*)d_in[4];
    const float* Wv   = (const float*)d_in[5];
    const float* Wo   = (const float*)d_in[6];
    const float* bo   = (const float*)d_in[7];
    const float* ln1g = (const float*)d_in[8];
    const float* ln1b = (const float*)d_in[9];
    const float* W1   = (const float*)d_in[10];
    const float* b1   = (const float*)d_in[11];
    const float* W2   = (const float*)d_in[12];
    const float* b2   = (const float*)d_in[13];
    const float* ln2g = (const float*)d_in[14];
    const float* ln2b = (const float*)d_in[15];
    const float* decW = (const float*)d_in[16];
    const float* decb = (const float*)d_in[17];
    float* out = (float*)d_out;

    cudaFuncSetAttribute(gemm_d,
        cudaFuncAttributeMaxDynamicSharedMemorySize, D_SMEM);
    cudaFuncSetAttribute(gemm_tc<128, true, true>,
        cudaFuncAttributeMaxDynamicSharedMemorySize, SMEM_128T);
    cudaFuncSetAttribute(gemm_tc<64, false, false>,
        cudaFuncAttributeMaxDynamicSharedMemorySize, SMEM_64F);

    float *x, *ps;
    __half *t2h, *xb, *qkvb, *pb, *vs, *t1b, *ffnb;
    __half *wqkv, *wob, *w1b, *w2b, *wdb;
    cudaGetSymbolAddress((void**)&x,    g_x);
    cudaGetSymbolAddress((void**)&t2h,  g_t2h);
    cudaGetSymbolAddress((void**)&ps,   g_ps);
    cudaGetSymbolAddress((void**)&xb,   g_xb);
    cudaGetSymbolAddress((void**)&qkvb, g_qkvb);
    cudaGetSymbolAddress((void**)&pb,   g_pb);
    cudaGetSymbolAddress((void**)&vs,   g_vs);
    cudaGetSymbolAddress((void**)&t1b,  g_t1b);
    cudaGetSymbolAddress((void**)&ffnb, g_ffnb);
    cudaGetSymbolAddress((void**)&wqkv, g_wqkv);
    cudaGetSymbolAddress((void**)&wob,  g_wob);
    cudaGetSymbolAddress((void**)&w1b,  g_w1b);
    cudaGetSymbolAddress((void**)&w2b,  g_w2b);
    cudaGetSymbolAddress((void**)&wdb,  g_wdb);

    // launch 1: embed; 2: qkv weights; 3: Wo; 4: QKV GEMM layer 0 (ncu target)
    embed_kernel<<<(Mq * Cq + 255) / 256, 256>>>(ids, emb, pos, x, xb);
    tr_qkv_all<<<dim3(1, 12, 3 * Lq * Hq), 256>>>(Wq, Wk, Wv, wqkv);
    tr_f2h<<<dim3(12, 12, Lq), 256>>>(Wo, wob, Cq, Cq, (long)Cq * Cq, (long)Cq * Cq);
    gemm_d<<<dim3(C3 / 128, Mq / 64, 1), 128, D_SMEM>>>(
        xb, wqkv, nullptr, qkvb, Cq, Cq, Cq, C3, 0, 0, 0, 1);
    tr_f2h<<<dim3(48, 12, Lq), 256>>>(W1, w1b, Cq, FFq, (long)Cq * FFq, (long)Cq * FFq);
    tr_f2h<<<dim3(12, 48, Lq), 256>>>(W2, w2b, FFq, Cq, (long)FFq * Cq, (long)FFq * Cq);
    tr_f2h<<<dim3(500, 12, 1), 256>>>(decW, wdb, Cq, Vq, 0, 0);

    for (int l = 0; l < Lq; l++) {
        const __half* wol = wob + (size_t)l * Cq * Cq;
        const __half* w1l = w1b + (size_t)l * Cq * FFq;
        const __half* w2l = w2b + (size_t)l * FFq * Cq;
        const float* bol = bo + (size_t)l * Cq;
        const float* b1l = b1 + (size_t)l * FFq;
        const float* b2l = b2 + (size_t)l * Cq;

        // scores + exp2 + column partial sums: pb = exp2(0.125*log2e*S - 4*log2e)
        gemm_tc<128, true, true><<<dim3(Tq / 128, Tq / 128, BHq), 256, SMEM_128T>>>(
            qkvb, qkvb + 768, pb, ps,
            Dq, C3, C3, Tq,
            (long)Tq * C3, Dq, (long)Tq * C3, Dq, (long)Hq * TT, TT, Hq,
            0.125f * LOG2E, -4.f * LOG2E);

        vscale_kernel<<<(Mq * Cq / 2 + 255) / 256, 256>>>(qkvb, ps, vs);

        // AV (out fp16, concat-head layout)
        gemm_tc<64, false, false><<<dim3(1, Tq / 128, BHq), 256, SMEM_64F>>>(
            pb, vs, t1b, nullptr,
            Tq, Tq, Cq, Cq,
            (long)Hq * TT, TT, (long)Tq * Cq, Dq, (long)Tq * Cq, Dq, Hq,
            0.f, 0.f);

        // output projection: split-K x2 -> fp16 partials t2h[0], t2h[1]
        gemm_d<<<dim3(Cq / 128, Mq / 64, 2), 128, D_SMEM>>>(
            t1b, wol, nullptr, t2h, Cq / 2, Cq, Cq, Cq,
            (long)(Cq / 2), (long)Mq * Cq, 0, 1);
        add_ln_kernel<<<Mq, 192>>>(x, t2h, t2h + (long)Mq * Cq, bol,
            ln1g + (size_t)l * Cq, ln1b + (size_t)l * Cq, xb);

        // FFN1 (full-K, throughput-bound)
        gemm_d<<<dim3(FFq / 128, Mq / 64, 1), 128, D_SMEM>>>(
            xb, w1l, b1l, ffnb, Cq, Cq, Cq, FFq, 0, 0, 1, 1);
        // FFN2: split-K x2 -> fp16 partials
        gemm_d<<<dim3(Cq / 128, Mq / 64, 2), 128, D_SMEM>>>(
            ffnb, w2l, nullptr, t2h, FFq / 2, FFq, FFq, Cq,
            (long)(FFq / 2), (long)Mq * Cq, 0, 1);
        add_ln_kernel<<<Mq, 192>>>(x, t2h, t2h + (long)Mq * Cq, b2l,
            ln2g + (size_t)l * Cq, ln2b + (size_t)l * Cq, xb);

        // QKV for next layer
        if (l + 1 < Lq) {
            const __half* wq1 = wqkv + (size_t)(l + 1) * C3 * Cq;
            gemm_d<<<dim3(C3 / 128, Mq / 64, 1), 128, D_SMEM>>>(
                xb, wq1, nullptr, qkvb, Cq, Cq, Cq, C3, 0, 0, 0, 1);
        }
    }

    // decoder: [4096,768] @ [768,32000] + bias (out fp32)
    gemm_d<<<dim3(Vq / 128, Mq / 64, 1), 128, D_SMEM>>>(
        xb, wdb, decb, out, Cq, Cq, Cq, Vq, 0, 0, 0, 0);
}

// round 14
// speedup vs baseline: 1.0539x; 1.0037x over previous
#include <cuda_runtime.h>
#include <cuda_fp16.h>
#include <cstdint>

#define Bq 8
#define Tq 512
#define Cq 768
#define Hq 12
#define Dq 64
#define Lq 12
#define Vq 32000
#define FFq 3072
#define Mq (Bq*Tq)          // 4096
#define BHq (Bq*Hq)         // 96
#define TT  (Tq*Tq)         // 262144
#define C3  (3*Cq)          // 2304
#define LOG2E 1.4426950408889634f

// ---------------- scratch (device globals) ----------------------------------
__device__ float g_x  [Mq*Cq];
__device__ float g_ps [4*BHq*Tq];

__device__ __half g_t2h  [2*(size_t)Mq*Cq];   // split-K partial outputs (fp16)
__device__ __half g_xb   [Mq*Cq];
__device__ __half g_qkvb [(size_t)Mq*C3];
__device__ __half g_pb   [(size_t)BHq*TT];
__device__ __half g_vs   [Mq*Cq];
__device__ __half g_t1b  [Mq*Cq];
__device__ __half g_ffnb [(size_t)Mq*FFq];
__device__ __half g_wqkv [(size_t)Lq*C3*Cq];
__device__ __half g_wob  [(size_t)Lq*Cq*Cq];
__device__ __half g_w1b  [(size_t)Lq*FFq*Cq];
__device__ __half g_w2b  [(size_t)Lq*Cq*FFq];
__device__ __half g_wdb  [(size_t)Vq*Cq];

// ---------------- small helpers ---------------------------------------------
__device__ __forceinline__ uint32_t s2u(const void* p) {
    return (uint32_t)__cvta_generic_to_shared(p);
}
__device__ __forceinline__ void cpa16p(void* smem, const void* gmem) {
    asm volatile("cp.async.cg.shared.global [%0], [%1], 16;\n"
        :: "r"(s2u(smem)), "l"(gmem));
}
__device__ __forceinline__ void ldm_x4(uint32_t* r, uint32_t addr) {
    asm volatile("ldmatrix.sync.aligned.m8n8.x4.shared.b16 {%0,%1,%2,%3}, [%4];"
        : "=r"(r[0]), "=r"(r[1]), "=r"(r[2]), "=r"(r[3]) : "r"(addr));
}
__device__ __forceinline__ void ldm_x4_t(uint32_t* r, uint32_t addr) {
    asm volatile("ldmatrix.sync.aligned.m8n8.x4.trans.shared.b16 {%0,%1,%2,%3}, [%4];"
        : "=r"(r[0]), "=r"(r[1]), "=r"(r[2]), "=r"(r[3]) : "r"(addr));
}
__device__ __forceinline__ void mma16816(float* c, const uint32_t* a, uint32_t b0, uint32_t b1) {
    asm volatile(
        "mma.sync.aligned.m16n8k16.row.col.f32.f16.f16.f32 "
        "{%0,%1,%2,%3}, {%4,%5,%6,%7}, {%8,%9}, {%0,%1,%2,%3};"
        : "+f"(c[0]), "+f"(c[1]), "+f"(c[2]), "+f"(c[3])
        : "r"(a[0]), "r"(a[1]), "r"(a[2]), "r"(a[3]), "r"(b0), "r"(b1));
}

// ============ dense GEMM: C[M,N] = A[M,K-slice] @ Bt[N,K-slice]^T ============
// CTA 64x128, 128 threads (4 warps, 2m x 2n), warp tile 32x64, BK=64,
// 2-stage cp.async, 4 CTAs/SM. Split-K via blockIdx.z (offset z*sK, out +z*sC).
#define D_ASZ  (64*72)
#define D_BSZ  (128*72)
#define D_SMEM (2*(D_ASZ + D_BSZ)*2)     // 55296 bytes

__global__ void __launch_bounds__(128, 4)
gemm_d(const __half* __restrict__ A, const __half* __restrict__ Bt,
       const float* __restrict__ bias, void* __restrict__ Cout,
       int K, int lda, int ldb, int ldc,
       long sK, long sC, int relu, int outhalf)
{
    extern __shared__ __half sm[];
    __half* As = sm;                 // [2][64][72]
    __half* Bs = sm + 2 * D_ASZ;     // [2][128][72]

    A  += (long)blockIdx.z * sK;
    Bt += (long)blockIdx.z * sK;
    float*  Cf = (float*)Cout  + (long)blockIdx.z * sC;
    __half* Ch = (__half*)Cout + (long)blockIdx.z * sC;

    const int tid  = threadIdx.x;
    const int lane = tid & 31;
    const int warp = tid >> 5;
    const int wm   = warp >> 1;          // 0..1
    const int wn   = warp & 1;           // 0..1
    const int bm = blockIdx.y * 64;
    const int bn = blockIdx.x * 128;

    const __half* Ag = A  + (long)bm * lda;
    const __half* Bg = Bt + (long)bn * ldb;

    float acc[2][8][4];
#pragma unroll
    for (int i = 0; i < 2; i++)
#pragma unroll
        for (int j = 0; j < 8; j++)
#pragma unroll
            for (int q = 0; q < 4; q++) acc[i][j][q] = 0.f;

    auto stage = [&](int s, int k0) {
        __half* Ab = As + s * D_ASZ;
        __half* Bb = Bs + s * D_BSZ;
#pragma unroll
        for (int i = 0; i < 4; i++) {                 // A: 512 16B-chunks
            int ci = tid + (i << 7);
            int r = ci >> 3, c = (ci & 7) << 3;
            cpa16p(&Ab[r * 72 + c], Ag + (long)r * lda + k0 + c);
        }
#pragma unroll
        for (int i = 0; i < 8; i++) {                 // B: 1024 chunks
            int ci = tid + (i << 7);
            int r = ci >> 3, c = (ci & 7) << 3;
            cpa16p(&Bb[r * 72 + c], Bg + (long)r * ldb + k0 + c);
        }
        asm volatile("cp.async.commit_group;" ::: "memory");
    };

    auto compute = [&](int s) {
        uint32_t aBase = s2u(As + s * D_ASZ);
        uint32_t bBase = s2u(Bs + s * D_BSZ);
#pragma unroll
        for (int kk = 0; kk < 64; kk += 16) {
            uint32_t ar[2][4], br[4][4];
#pragma unroll
            for (int mt = 0; mt < 2; mt++) {
                uint32_t addr = aBase +
                    2u * ((wm * 32 + mt * 16 + (lane & 15)) * 72 + kk + ((lane >> 4) << 3));
                ldm_x4(ar[mt], addr);
            }
#pragma unroll
            for (int nt = 0; nt < 4; nt++) {
                uint32_t addr = bBase +
                    2u * ((wn * 64 + nt * 16 + (lane & 15)) * 72 + kk + ((lane >> 4) << 3));
                ldm_x4(br[nt], addr);
            }
#pragma unroll
            for (int mt = 0; mt < 2; mt++)
#pragma unroll
                for (int n8 = 0; n8 < 8; n8++) {
                    int nt = n8 >> 1, h = n8 & 1;
                    mma16816(acc[mt][n8], ar[mt], br[nt][h], br[nt][2 + h]);
                }
        }
    };

    const int nk = K >> 6;
    stage(0, 0);
    stage(1, 64);
    for (int kt = 0; kt < nk; kt++) {
        if (kt + 1 < nk) asm volatile("cp.async.wait_group 1;" ::: "memory");
        else             asm volatile("cp.async.wait_group 0;" ::: "memory");
        __syncthreads();
        compute(kt & 1);
        __syncthreads();
        if (kt + 2 < nk) stage(kt & 1, (kt + 2) << 6);
    }

    // epilogue
    const int r0 = bm + wm * 32 + (lane >> 2);
    const int c0 = bn + wn * 64 + ((lane & 3) << 1);
#pragma unroll
    for (int n8 = 0; n8 < 8; n8++) {
        int c = c0 + n8 * 8;
        float bb0 = 0.f, bb1 = 0.f;
        if (bias) { bb0 = __ldg(&bias[c]); bb1 = __ldg(&bias[c + 1]); }
#pragma unroll
        for (int mt = 0; mt < 2; mt++) {
#pragma unroll
            for (int hh = 0; hh < 2; hh++) {
                int r = r0 + mt * 16 + hh * 8;
                float v0 = acc[mt][n8][hh * 2 + 0] + bb0;
                float v1 = acc[mt][n8][hh * 2 + 1] + bb1;
                if (relu) { v0 = fmaxf(v0, 0.f); v1 = fmaxf(v1, 0.f); }
                if (outhalf) {
                    *reinterpret_cast<__half2*>(Ch + (long)r * ldc + c) =
                        __floats2half2_rn(v0, v1);
                } else {
                    *reinterpret_cast<float2*>(Cf + (long)r * ldc + c) = make_float2(v0, v1);
                }
            }
        }
    }
}

// ========== mma.sync GEMM for scores (EXPSUM) and AV =========================
template<int BN, bool BT, bool EXPSUM>
__global__ void __launch_bounds__(256, 2)
gemm_tc(const __half* __restrict__ A, const __half* __restrict__ B,
        void* __restrict__ Cout, float* __restrict__ psum,
        int K, int lda, int ldb, int ldc,
        long sAo, long sAi, long sBo, long sBi, long sCo, long sCi, int zdiv,
        float alpha2, float off2)
{
    extern __shared__ __half smem_dyn[];
    constexpr int ASIZE = 128 * 40;
    constexpr int BROWS = BT ? BN : 32;
    constexpr int BCOLS = BT ? 40 : (BN + 8);
    constexpr int BSIZE = BROWS * BCOLS;
    __half* Asm = smem_dyn;
    __half* Bsm = smem_dyn + 3 * ASIZE;

    const int zo = blockIdx.z / zdiv, zi = blockIdx.z - zo * zdiv;
    A += zo * sAo + zi * sAi;
    B += zo * sBo + zi * sBi;
    __half* Ch = (__half*)Cout + zo * sCo + zi * sCi;

    const int bm = blockIdx.y * 128;
    const int bn = blockIdx.x * BN;
    const int tid  = threadIdx.x;
    const int lane = tid & 31;
    const int warp = tid >> 5;
    const int wm   = warp & 3;
    const int wn   = warp >> 2;
    const int m_w  = wm * 32;
    const int n_w  = wn * (BN / 2);
    constexpr int NT8  = (BN / 2) / 8;
    constexpr int NT16 = (BN / 2) / 16;

    const __half* Ag = A + (long)bm * lda;
    const __half* Bg = BT ? (B + (long)bn * ldb) : (B + bn);

    float acc[2][NT8][4];
#pragma unroll
    for (int i = 0; i < 2; i++)
#pragma unroll
        for (int j = 0; j < NT8; j++)
#pragma unroll
            for (int q = 0; q < 4; q++) acc[i][j][q] = 0.f;

    auto stage = [&](int s, int k0) {
        __half* As = Asm + s * ASIZE;
        __half* Bs = Bsm + s * BSIZE;
#pragma unroll
        for (int i = 0; i < 2; i++) {
            int ci = tid + i * 256;
            int r = ci >> 2, kc = (ci & 3) << 3;
            cpa16p(&As[r * 40 + kc], Ag + (long)r * lda + k0 + kc);
        }
        if (BT) {
            constexpr int IT = (BN * 4) / 256;
#pragma unroll
            for (int i = 0; i < IT; i++) {
                int ci = tid + i * 256;
                int r = ci >> 2, kc = (ci & 3) << 3;
                cpa16p(&Bs[r * 40 + kc], Bg + (long)r * ldb + k0 + kc);
            }
        } else {
            constexpr int CH = BN / 8;
            constexpr int IT = (32 * CH) / 256;
#pragma unroll
            for (int i = 0; i < IT; i++) {
                int ci = tid + i * 256;
                int r = ci / CH, nc = (ci % CH) << 3;
                cpa16p(&Bs[r * BCOLS + nc], Bg + (long)(k0 + r) * ldb + nc);
            }
        }
    };

    auto compute = [&](int s) {
        uint32_t aBase = s2u(Asm + s * ASIZE);
        uint32_t bBase = s2u(Bsm + s * BSIZE);
#pragma unroll
        for (int kk = 0; kk < 32; kk += 16) {
            uint32_t ar[2][4];
#pragma unroll
            for (int mt = 0; mt < 2; mt++) {
                uint32_t addr = aBase +
                    2u * ((m_w + mt * 16 + (lane & 15)) * 40 + kk + ((lane >> 4) << 3));
                ldm_x4(ar[mt], addr);
            }
            uint32_t br[NT16][4];
#pragma unroll
            for (int nt = 0; nt < NT16; nt++) {
                if (BT) {
                    uint32_t addr = bBase +
                        2u * ((n_w + nt * 16 + (lane & 15)) * 40 + kk + ((lane >> 4) << 3));
                    ldm_x4(br[nt], addr);
                } else {
                    uint32_t addr = bBase +
                        2u * ((kk + (lane & 15)) * BCOLS + n_w + nt * 16 + ((lane >> 4) << 3));
                    ldm_x4_t(br[nt], addr);
                }
            }
#pragma unroll
            for (int mt = 0; mt < 2; mt++)
#pragma unroll
                for (int n8 = 0; n8 < NT8; n8++) {
                    int nt = n8 >> 1, h = n8 & 1;
                    uint32_t b0, b1;
                    if (BT) { b0 = br[nt][h];     b1 = br[nt][2 + h];     }
                    else    { b0 = br[nt][h * 2]; b1 = br[nt][h * 2 + 1]; }
                    mma16816(acc[mt][n8], ar[mt], b0, b1);
                }
        }
    };

    const int ntile = K >> 5;
    stage(0, 0);
    asm volatile("cp.async.commit_group;");
    stage(1, 32);
    asm volatile("cp.async.commit_group;");
    for (int kt = 0; kt < ntile; kt++) {
        asm volatile("cp.async.wait_group 1;");
        __syncthreads();
        if (kt + 2 < ntile) stage((kt + 2) % 3, (kt + 2) << 5);
        asm volatile("cp.async.commit_group;");
        compute(kt % 3);
    }

    const int r0 = bm + m_w + (lane >> 2);
    const int c0 = bn + n_w + ((lane & 3) << 1);

    if (EXPSUM) {
        float cs[NT8][2];
#pragma unroll
        for (int n8 = 0; n8 < NT8; n8++) { cs[n8][0] = 0.f; cs[n8][1] = 0.f; }
#pragma unroll
        for (int n8 = 0; n8 < NT8; n8++) {
            int c = c0 + n8 * 8;
#pragma unroll
            for (int mt = 0; mt < 2; mt++) {
#pragma unroll
                for (int hh = 0; hh < 2; hh++) {
                    int r = r0 + mt * 16 + hh * 8;
                    float v0 = exp2f(fmaf(acc[mt][n8][hh * 2 + 0], alpha2, off2));
                    float v1 = exp2f(fmaf(acc[mt][n8][hh * 2 + 1], alpha2, off2));
                    *reinterpret_cast<__half2*>(Ch + (long)r * ldc + c) =
                        __floats2half2_rn(v0, v1);
                    cs[n8][0] += v0; cs[n8][1] += v1;
                }
            }
        }
#pragma unroll
        for (int n8 = 0; n8 < NT8; n8++)
#pragma unroll
            for (int p = 0; p < 2; p++) {
                float v = cs[n8][p];
                v += __shfl_xor_sync(0xffffffffu, v, 4);
                v += __shfl_xor_sync(0xffffffffu, v, 8);
                v += __shfl_xor_sync(0xffffffffu, v, 16);
                cs[n8][p] = v;
            }
        __syncthreads();
        float* sred = (float*)smem_dyn;
        if (lane < 4) {
#pragma unroll
            for (int n8 = 0; n8 < NT8; n8++) {
                sred[warp * 64 + n8 * 8 + lane * 2 + 0] = cs[n8][0];
                sred[warp * 64 + n8 * 8 + lane * 2 + 1] = cs[n8][1];
            }
        }
        __syncthreads();
        if (tid < 128) {
            int wn2 = tid >> 6, cin = tid & 63;
            float t = 0.f;
#pragma unroll
            for (int w2 = 0; w2 < 4; w2++) t += sred[(wn2 * 4 + w2) * 64 + cin];
            psum[((long)blockIdx.y * gridDim.z + blockIdx.z) * ldc + bn + tid] = t;
        }
        return;
    }

#pragma unroll
    for (int n8 = 0; n8 < NT8; n8++) {
        int c = c0 + n8 * 8;
#pragma unroll
        for (int mt = 0; mt < 2; mt++) {
#pragma unroll
            for (int hh = 0; hh < 2; hh++) {
                int r = r0 + mt * 16 + hh * 8;
                float v0 = acc[mt][n8][hh * 2 + 0];
                float v1 = acc[mt][n8][hh * 2 + 1];
                *reinterpret_cast<__half2*>(Ch + (long)r * ldc + c) =
                    __floats2half2_rn(v0, v1);
            }
        }
    }
}

#define SMEM_128T (3*(128*40 + 128*40)*2)   // 61440
#define SMEM_64F  (3*(128*40 + 32*72)*2)    // 44544

// ---------------- weight transpose+convert kernels ---------------------------
__global__ void tr_f2h(const float* __restrict__ src, __half* __restrict__ dst,
                       int K, int N, long sSrc, long sDst)
{
    src += (long)blockIdx.z * sSrc;
    dst += (long)blockIdx.z * sDst;
    __shared__ float t[64][65];
    const int n0 = blockIdx.x * 64, k0 = blockIdx.y * 64;
    const int tid = threadIdx.x;
#pragma unroll
    for (int i = 0; i < 16; i++) {
        int idx = tid + i * 256;
        int r = idx >> 6, c = idx & 63;
        t[r][c] = src[(long)(k0 + r) * N + n0 + c];
    }
    __syncthreads();
#pragma unroll
    for (int i = 0; i < 16; i++) {
        int idx = tid + i * 256;
        int r = idx >> 6, c = idx & 63;
        dst[(long)(n0 + r) * K + k0 + c] = __float2half(t[c][r]);
    }
}

__global__ void tr_qkv_all(const float* __restrict__ Wq, const float* __restrict__ Wk,
                           const float* __restrict__ Wv, __half* __restrict__ dst)
{
    const int z = blockIdx.z;
    const int w = z / (Lq * Hq);
    const int lh = z - w * (Lq * Hq);
    const int l = lh / Hq, h = lh - l * Hq;
    const float* W = (w == 0) ? Wq : ((w == 1) ? Wk : Wv);
    const float* src = W + (long)lh * Cq * Dq;
    __half* d = dst + (long)l * C3 * Cq + (long)(w * 768 + h * Dq) * Cq;
    __shared__ float t[64][65];
    const int k0 = blockIdx.y * 64;
    const int tid = threadIdx.x;
#pragma unroll
    for (int i = 0; i < 16; i++) {
        int idx = tid + i * 256;
        int r = idx >> 6, c = idx & 63;
        t[r][c] = src[(long)(k0 + r) * Dq + c];
    }
    __syncthreads();
#pragma unroll
    for (int i = 0; i < 16; i++) {
        int idx = tid + i * 256;
        int r = idx >> 6, c = idx & 63;
        d[(long)r * Cq + k0 + c] = __float2half(t[c][r]);
    }
}

// ---------------- embed -------------------------------------------------------
__global__ void embed_kernel(const int* __restrict__ ids, const float* __restrict__ emb,
                             const float* __restrict__ pos,
                             float* __restrict__ x, __half* __restrict__ xb)
{
    int idx = blockIdx.x * blockDim.x + threadIdx.x;
    if (idx >= Mq * Cq) return;
    int m = idx / Cq, c = idx - m * Cq;
    int t = m & (Tq - 1);
    int tok = ids[m];
    float v = emb[(size_t)tok * Cq + c] + pos[(size_t)t * Cq + c];
    x[idx]  = v;
    xb[idx] = __float2half(v);
}

// vs[m][c] = V[m][c] / colsum
__global__ void vscale_kernel(const __half* __restrict__ qkv,
                              const float* __restrict__ ps, __half* __restrict__ vs)
{
    int idx = blockIdx.x * blockDim.x + threadIdx.x;
    if (idx >= Mq * Cq / 2) return;
    int c2 = idx % (Cq / 2);
    int m  = idx / (Cq / 2);
    int c  = c2 * 2;
    int b  = m >> 9, t = m & 511, h = c >> 6;
    long si = (((long)b * Hq + h) << 9) + t;
    float s = ps[si] + ps[(long)BHq * Tq + si]
            + ps[2L * BHq * Tq + si] + ps[3L * BHq * Tq + si];
    float r = 1.f / s;
    __half2 v = *reinterpret_cast<const __half2*>(&qkv[(long)m * C3 + 1536 + c]);
    float2 f = __half22float2(v);
    *reinterpret_cast<__half2*>(&vs[(long)m * Cq + c]) = __floats2half2_rn(f.x * r, f.y * r);
}

// ---------------- residual add (fp16 split-K partials) + bias + layernorm -----
// 192 threads, one float4 per thread (768 = 192*4)
__global__ void __launch_bounds__(192)
add_ln_kernel(float* __restrict__ x, const __half* __restrict__ y0,
              const __half* __restrict__ y1, const float* __restrict__ bias,
              const float* __restrict__ g, const float* __restrict__ bta,
              __half* __restrict__ xb)
{
    __shared__ float sh[6];
    long row = blockIdx.x;
    int tid = threadIdx.x;
    int c = tid << 2;
    float4 xv = *reinterpret_cast<const float4*>(&x [row * Cq + c]);
    uint2 u0 = *reinterpret_cast<const uint2*>(&y0[row * Cq + c]);
    uint2 u1 = *reinterpret_cast<const uint2*>(&y1[row * Cq + c]);
    float2 a0lo = __half22float2(*reinterpret_cast<__half2*>(&u0.x));
    float2 a0hi = __half22float2(*reinterpret_cast<__half2*>(&u0.y));
    float2 a1lo = __half22float2(*reinterpret_cast<__half2*>(&u1.x));
    float2 a1hi = __half22float2(*reinterpret_cast<__half2*>(&u1.y));
    float4 bv = *reinterpret_cast<const float4*>(&bias[c]);
    float v0 = xv.x + a0lo.x + a1lo.x + bv.x;
    float v1 = xv.y + a0lo.y + a1lo.y + bv.y;
    float v2 = xv.z + a0hi.x + a1hi.x + bv.z;
    float v3 = xv.w + a0hi.y + a1hi.y + bv.w;

    float s = v0 + v1 + v2 + v3;
#pragma unroll
    for (int o = 16; o > 0; o >>= 1) s += __shfl_xor_sync(0xffffffffu, s, o);
    if ((tid & 31) == 0) sh[tid >> 5] = s;
    __syncthreads();
    float mu = (sh[0] + sh[1] + sh[2] + sh[3] + sh[4] + sh[5]) * (1.f / Cq);
    __syncthreads();

    float d0 = v0 - mu, d1 = v1 - mu, d2 = v2 - mu, d3 = v3 - mu;
    float s2 = d0 * d0 + d1 * d1 + d2 * d2 + d3 * d3;
#pragma unroll
    for (int o = 16; o > 0; o >>= 1) s2 += __shfl_xor_sync(0xffffffffu, s2, o);
    if ((tid & 31) == 0) sh[tid >> 5] = s2;
    __syncthreads();
    float var = (sh[0] + sh[1] + sh[2] + sh[3] + sh[4] + sh[5]) * (1.f / Cq);
    float rstd = rsqrtf(var + 1e-5f);

    float4 gv = *reinterpret_cast<const float4*>(&g[c]);
    float4 tv = *reinterpret_cast<const float4*>(&bta[c]);
    float o0 = d0 * rstd * gv.x + tv.x;
    float o1 = d1 * rstd * gv.y + tv.y;
    float o2 = d2 * rstd * gv.z + tv.z;
    float o3 = d3 * rstd * gv.w + tv.w;
    *reinterpret_cast<float4*>(&x[row * Cq + c]) = make_float4(o0, o1, o2, o3);
    __half2 h0 = __floats2half2_rn(o0, o1);
    __half2 h1 = __floats2half2_rn(o2, o3);
    *reinterpret_cast<__half2*>(&xb[row * Cq + c])     = h0;
    *reinterpret_cast<__half2*>(&xb[row * Cq + c + 2]) = h1;
}

// ---------------- launch -------------------------------------------------------
static cudaStream_t g_side = nullptr;
static cudaEvent_t  g_evFork = nullptr, g_evJoin = nullptr;

extern "C" void kernel_launch(void* const* d_in, const int* in_sizes, int n_in,
                              void* d_out, int out_size)
{
    const int*   ids  = (const int*)  d_in[0];
    const float* emb  = (const float*)d_in[1];
    const float* pos  = (const float*)d_in[2];
    const float* Wq   = (const float*)d_in[3];
    const float* Wk   = (const float*)d_in[4];
    const float* Wv   = (const float*)d_in[5];
    const float* Wo   = (const float*)d_in[6];
    const float* bo   = (const float*)d_in[7];
    const float* ln1g = (const float*)d_in[8];
    const float* ln1b = (const float*)d_in[9];
    const float* W1   = (const float*)d_in[10];
    const float* b1   = (const float*)d_in[11];
    const float* W2   = (const float*)d_in[12];
    const float* b2   = (const float*)d_in[13];
    const float* ln2g = (const float*)d_in[14];
    const float* ln2b = (const float*)d_in[15];
    const float* decW = (const float*)d_in[16];
    const float* decb = (const float*)d_in[17];
    float* out = (float*)d_out;

    if (!g_side) {
        cudaStreamCreateWithFlags(&g_side, cudaStreamNonBlocking);
        cudaEventCreateWithFlags(&g_evFork, cudaEventDisableTiming);
        cudaEventCreateWithFlags(&g_evJoin, cudaEventDisableTiming);
    }

    cudaFuncSetAttribute(gemm_d,
        cudaFuncAttributeMaxDynamicSharedMemorySize, D_SMEM);
    cudaFuncSetAttribute(gemm_tc<128, true, true>,
        cudaFuncAttributeMaxDynamicSharedMemorySize, SMEM_128T);
    cudaFuncSetAttribute(gemm_tc<64, false, false>,
        cudaFuncAttributeMaxDynamicSharedMemorySize, SMEM_64F);

    float *x, *ps;
    __half *t2h, *xb, *qkvb, *pb, *vs, *t1b, *ffnb;
    __half *wqkv, *wob, *w1b, *w2b, *wdb;
    cudaGetSymbolAddress((void**)&x,    g_x);
    cudaGetSymbolAddress((void**)&t2h,  g_t2h);
    cudaGetSymbolAddress((void**)&ps,   g_ps);
    cudaGetSymbolAddress((void**)&xb,   g_xb);
    cudaGetSymbolAddress((void**)&qkvb, g_qkvb);
    cudaGetSymbolAddress((void**)&pb,   g_pb);
    cudaGetSymbolAddress((void**)&vs,   g_vs);
    cudaGetSymbolAddress((void**)&t1b,  g_t1b);
    cudaGetSymbolAddress((void**)&ffnb, g_ffnb);
    cudaGetSymbolAddress((void**)&wqkv, g_wqkv);
    cudaGetSymbolAddress((void**)&wob,  g_wob);
    cudaGetSymbolAddress((void**)&w1b,  g_w1b);
    cudaGetSymbolAddress((void**)&w2b,  g_w2b);
    cudaGetSymbolAddress((void**)&wdb,  g_wdb);

    // fork: heavy FFN/decoder weight transposes on side stream, overlapping
    // with embed + QKV weights + layer-0 attention on the main stream.
    cudaEventRecord(g_evFork, 0);
    cudaStreamWaitEvent(g_side, g_evFork, 0);
    tr_f2h<<<dim3(48, 12, Lq), 256, 0, g_side>>>(W1, w1b, Cq, FFq,
        (long)Cq * FFq, (long)Cq * FFq);
    tr_f2h<<<dim3(12, 48, Lq), 256, 0, g_side>>>(W2, w2b, FFq, Cq,
        (long)FFq * Cq, (long)FFq * Cq);
    tr_f2h<<<dim3(500, 12, 1), 256, 0, g_side>>>(decW, wdb, Cq, Vq, 0, 0);
    cudaEventRecord(g_evJoin, g_side);

    // main stream: launch 1: embed; 2: qkv weights; 3: Wo; 4: QKV (ncu target)
    embed_kernel<<<(Mq * Cq + 255) / 256, 256>>>(ids, emb, pos, x, xb);
    tr_qkv_all<<<dim3(1, 12, 3 * Lq * Hq), 256>>>(Wq, Wk, Wv, wqkv);
    tr_f2h<<<dim3(12, 12, Lq), 256>>>(Wo, wob, Cq, Cq, (long)Cq * Cq, (long)Cq * Cq);
    gemm_d<<<dim3(C3 / 128, Mq / 64, 1), 128, D_SMEM>>>(
        xb, wqkv, nullptr, qkvb, Cq, Cq, Cq, C3, 0, 0, 0, 1);

    bool joined = false;
    for (int l = 0; l < Lq; l++) {
        const __half* wol = wob + (size_t)l * Cq * Cq;
        const __half* w1l = w1b + (size_t)l * Cq * FFq;
        const __half* w2l = w2b + (size_t)l * FFq * Cq;
        const float* bol = bo + (size_t)l * Cq;
        const float* b1l = b1 + (size_t)l * FFq;
        const float* b2l = b2 + (size_t)l * Cq;

        // scores + exp2 + column partial sums
        gemm_tc<128, true, true><<<dim3(Tq / 128, Tq / 128, BHq), 256, SMEM_128T>>>(
            qkvb, qkvb + 768, pb, ps,
            Dq, C3, C3, Tq,
            (long)Tq * C3, Dq, (long)Tq * C3, Dq, (long)Hq * TT, TT, Hq,
            0.125f * LOG2E, -4.f * LOG2E);

        vscale_kernel<<<(Mq * Cq / 2 + 255) / 256, 256>>>(qkvb, ps, vs);

        // AV (out fp16, concat-head layout)
        gemm_tc<64, false, false><<<dim3(1, Tq / 128, BHq), 256, SMEM_64F>>>(
            pb, vs, t1b, nullptr,
            Tq, Tq, Cq, Cq,
            (long)Hq * TT, TT, (long)Tq * Cq, Dq, (long)Tq * Cq, Dq, Hq,
            0.f, 0.f);

        // output projection: split-K x2 -> fp16 partials
        gemm_d<<<dim3(Cq / 128, Mq / 64, 2), 128, D_SMEM>>>(
            t1b, wol, nullptr, t2h, Cq / 2, Cq, Cq, Cq,
            (long)(Cq / 2), (long)Mq * Cq, 0, 1);
        add_ln_kernel<<<Mq, 192>>>(x, t2h, t2h + (long)Mq * Cq, bol,
            ln1g + (size_t)l * Cq, ln1b + (size_t)l * Cq, xb);

        // join side stream before first use of w1b/w2b
        if (!joined) {
            cudaStreamWaitEvent(0, g_evJoin, 0);
            joined = true;
        }

        // FFN1
        gemm_d<<<dim3(FFq / 128, Mq / 64, 1), 128, D_SMEM>>>(
            xb, w1l, b1l, ffnb, Cq, Cq, Cq, FFq, 0, 0, 1, 1);
        // FFN2: split-K x2 -> fp16 partials
        gemm_d<<<dim3(Cq / 128, Mq / 64, 2), 128, D_SMEM>>>(
            ffnb, w2l, nullptr, t2h, FFq / 2, FFq, FFq, Cq,
            (long)(FFq / 2), (long)Mq * Cq, 0, 1);
        add_ln_kernel<<<Mq, 192>>>(x, t2h, t2h + (long)Mq * Cq, b2l,
            ln2g + (size_t)l * Cq, ln2b + (size_t)l * Cq, xb);

        // QKV for next layer
        if (l + 1 < Lq) {
            const __half* wq1 = wqkv + (size_t)(l + 1) * C3 * Cq;
            gemm_d<<<dim3(C3 / 128, Mq / 64, 1), 128, D_SMEM>>>(
                xb, wq1, nullptr, qkvb, Cq, Cq, Cq, C3, 0, 0, 0, 1);
        }
    }

    // decoder: [4096,768] @ [768,32000] + bias (out fp32)
    gemm_d<<<dim3(Vq / 128, Mq / 64, 1), 128, D_SMEM>>>(
        xb, wdb, decb, out, Cq, Cq, Cq, Vq, 0, 0, 0, 0);
}

// round 15
// speedup vs baseline: 1.0788x; 1.0236x over previous
#include <cuda_runtime.h>
#include <cuda_fp16.h>
#include <cstdint>

#define Bq 8
#define Tq 512
#define Cq 768
#define Hq 12
#define Dq 64
#define Lq 12
#define Vq 32000
#define FFq 3072
#define Mq (Bq*Tq)          // 4096
#define BHq (Bq*Hq)         // 96
#define TT  (Tq*Tq)         // 262144
#define C3  (3*Cq)          // 2304
#define LOG2E 1.4426950408889634f
#define NPS 8               // score q-tile partials

// ---------------- scratch (device globals) ----------------------------------
__device__ float g_x  [Mq*Cq];
__device__ float g_ps [NPS*BHq*Tq];

__device__ __half g_t2h  [2*(size_t)Mq*Cq];   // split-K partial outputs (fp16)
__device__ __half g_xb   [Mq*Cq];
__device__ __half g_qkvb [(size_t)Mq*C3];
__device__ __half g_pb   [(size_t)BHq*TT];
__device__ __half g_vs   [Mq*Cq];
__device__ __half g_t1b  [Mq*Cq];
__device__ __half g_ffnb [(size_t)Mq*FFq];
__device__ __half g_wqkv [(size_t)Lq*C3*Cq];
__device__ __half g_wob  [(size_t)Lq*Cq*Cq];
__device__ __half g_w1b  [(size_t)Lq*FFq*Cq];
__device__ __half g_w2b  [(size_t)Lq*Cq*FFq];
__device__ __half g_wdb  [(size_t)Vq*Cq];

// ---------------- small helpers ---------------------------------------------
__device__ __forceinline__ uint32_t s2u(const void* p) {
    return (uint32_t)__cvta_generic_to_shared(p);
}
__device__ __forceinline__ void cpa16p(void* smem, const void* gmem) {
    asm volatile("cp.async.cg.shared.global [%0], [%1], 16;\n"
        :: "r"(s2u(smem)), "l"(gmem));
}
__device__ __forceinline__ void ldm_x4(uint32_t* r, uint32_t addr) {
    asm volatile("ldmatrix.sync.aligned.m8n8.x4.shared.b16 {%0,%1,%2,%3}, [%4];"
        : "=r"(r[0]), "=r"(r[1]), "=r"(r[2]), "=r"(r[3]) : "r"(addr));
}
__device__ __forceinline__ void ldm_x4_t(uint32_t* r, uint32_t addr) {
    asm volatile("ldmatrix.sync.aligned.m8n8.x4.trans.shared.b16 {%0,%1,%2,%3}, [%4];"
        : "=r"(r[0]), "=r"(r[1]), "=r"(r[2]), "=r"(r[3]) : "r"(addr));
}
__device__ __forceinline__ void mma16816(float* c, const uint32_t* a, uint32_t b0, uint32_t b1) {
    asm volatile(
        "mma.sync.aligned.m16n8k16.row.col.f32.f16.f16.f32 "
        "{%0,%1,%2,%3}, {%4,%5,%6,%7}, {%8,%9}, {%0,%1,%2,%3};"
        : "+f"(c[0]), "+f"(c[1]), "+f"(c[2]), "+f"(c[3])
        : "r"(a[0]), "r"(a[1]), "r"(a[2]), "r"(a[3]), "r"(b0), "r"(b1));
}

// ============ dense GEMM: C[M,N] = A[M,K-slice] @ Bt[N,K-slice]^T ============
// CTA 64x128, 128 threads (4 warps, 2m x 2n), warp tile 32x64, BK=64,
// 2-stage cp.async, 4 CTAs/SM. Split-K via blockIdx.z (offset z*sK, out +z*sC).
#define D_ASZ  (64*72)
#define D_BSZ  (128*72)
#define D_SMEM (2*(D_ASZ + D_BSZ)*2)     // 55296 bytes
#define S_SMEM ((D_ASZ + D_BSZ)*2)       // 27648 bytes (single stage)

__global__ void __launch_bounds__(128, 4)
gemm_d(const __half* __restrict__ A, const __half* __restrict__ Bt,
       const float* __restrict__ bias, void* __restrict__ Cout,
       int K, int lda, int ldb, int ldc,
       long sK, long sC, int relu, int outhalf)
{
    extern __shared__ __half sm[];
    __half* As = sm;                 // [2][64][72]
    __half* Bs = sm + 2 * D_ASZ;     // [2][128][72]

    A  += (long)blockIdx.z * sK;
    Bt += (long)blockIdx.z * sK;
    float*  Cf = (float*)Cout  + (long)blockIdx.z * sC;
    __half* Ch = (__half*)Cout + (long)blockIdx.z * sC;

    const int tid  = threadIdx.x;
    const int lane = tid & 31;
    const int warp = tid >> 5;
    const int wm   = warp >> 1;          // 0..1
    const int wn   = warp & 1;           // 0..1
    const int bm = blockIdx.y * 64;
    const int bn = blockIdx.x * 128;

    const __half* Ag = A  + (long)bm * lda;
    const __half* Bg = Bt + (long)bn * ldb;

    float acc[2][8][4];
#pragma unroll
    for (int i = 0; i < 2; i++)
#pragma unroll
        for (int j = 0; j < 8; j++)
#pragma unroll
            for (int q = 0; q < 4; q++) acc[i][j][q] = 0.f;

    auto stage = [&](int s, int k0) {
        __half* Ab = As + s * D_ASZ;
        __half* Bb = Bs + s * D_BSZ;
#pragma unroll
        for (int i = 0; i < 4; i++) {                 // A: 512 16B-chunks
            int ci = tid + (i << 7);
            int r = ci >> 3, c = (ci & 7) << 3;
            cpa16p(&Ab[r * 72 + c], Ag + (long)r * lda + k0 + c);
        }
#pragma unroll
        for (int i = 0; i < 8; i++) {                 // B: 1024 chunks
            int ci = tid + (i << 7);
            int r = ci >> 3, c = (ci & 7) << 3;
            cpa16p(&Bb[r * 72 + c], Bg + (long)r * ldb + k0 + c);
        }
        asm volatile("cp.async.commit_group;" ::: "memory");
    };

    auto compute = [&](int s) {
        uint32_t aBase = s2u(As + s * D_ASZ);
        uint32_t bBase = s2u(Bs + s * D_BSZ);
#pragma unroll
        for (int kk = 0; kk < 64; kk += 16) {
            uint32_t ar[2][4], br[4][4];
#pragma unroll
            for (int mt = 0; mt < 2; mt++) {
                uint32_t addr = aBase +
                    2u * ((wm * 32 + mt * 16 + (lane & 15)) * 72 + kk + ((lane >> 4) << 3));
                ldm_x4(ar[mt], addr);
            }
#pragma unroll
            for (int nt = 0; nt < 4; nt++) {
                uint32_t addr = bBase +
                    2u * ((wn * 64 + nt * 16 + (lane & 15)) * 72 + kk + ((lane >> 4) << 3));
                ldm_x4(br[nt], addr);
            }
#pragma unroll
            for (int mt = 0; mt < 2; mt++)
#pragma unroll
                for (int n8 = 0; n8 < 8; n8++) {
                    int nt = n8 >> 1, h = n8 & 1;
                    mma16816(acc[mt][n8], ar[mt], br[nt][h], br[nt][2 + h]);
                }
        }
    };

    const int nk = K >> 6;
    stage(0, 0);
    stage(1, 64);
    for (int kt = 0; kt < nk; kt++) {
        if (kt + 1 < nk) asm volatile("cp.async.wait_group 1;" ::: "memory");
        else             asm volatile("cp.async.wait_group 0;" ::: "memory");
        __syncthreads();
        compute(kt & 1);
        __syncthreads();
        if (kt + 2 < nk) stage(kt & 1, (kt + 2) << 6);
    }

    // epilogue
    const int r0 = bm + wm * 32 + (lane >> 2);
    const int c0 = bn + wn * 64 + ((lane & 3) << 1);
#pragma unroll
    for (int n8 = 0; n8 < 8; n8++) {
        int c = c0 + n8 * 8;
        float bb0 = 0.f, bb1 = 0.f;
        if (bias) { bb0 = __ldg(&bias[c]); bb1 = __ldg(&bias[c + 1]); }
#pragma unroll
        for (int mt = 0; mt < 2; mt++) {
#pragma unroll
            for (int hh = 0; hh < 2; hh++) {
                int r = r0 + mt * 16 + hh * 8;
                float v0 = acc[mt][n8][hh * 2 + 0] + bb0;
                float v1 = acc[mt][n8][hh * 2 + 1] + bb1;
                if (relu) { v0 = fmaxf(v0, 0.f); v1 = fmaxf(v1, 0.f); }
                if (outhalf) {
                    *reinterpret_cast<__half2*>(Ch + (long)r * ldc + c) =
                        __floats2half2_rn(v0, v1);
                } else {
                    *reinterpret_cast<float2*>(Cf + (long)r * ldc + c) = make_float2(v0, v1);
                }
            }
        }
    }
}

// ============ scores: pb = exp2(a2*(Q K^T) + off2), column partial sums ======
// gemm_d shape: CTA 64x128, 128 threads, K=64 single stage, 4+ CTAs/SM.
// grid (4 k-tiles, 8 q-tiles, 96 bh). psum[qtile][bh][col].
__global__ void __launch_bounds__(128, 4)
gemm_s(const __half* __restrict__ Qkv, __half* __restrict__ pbo,
       float* __restrict__ psum, float alpha2, float off2)
{
    extern __shared__ __half sm[];
    __half* As = sm;                 // [64][72]
    __half* Bs = sm + D_ASZ;         // [128][72]

    const int bh = blockIdx.z;
    const int b = bh / Hq, h = bh - b * Hq;
    const __half* Ag = Qkv + (long)b * Tq * C3 + h * Dq
                     + (long)(blockIdx.y * 64) * C3;            // Q rows
    const __half* Bg = Qkv + (long)b * Tq * C3 + 768 + h * Dq
                     + (long)(blockIdx.x * 128) * C3;           // K rows
    __half* Ch = pbo + (long)bh * TT;

    const int tid  = threadIdx.x;
    const int lane = tid & 31;
    const int warp = tid >> 5;
    const int wm   = warp >> 1;
    const int wn   = warp & 1;
    const int bm = blockIdx.y * 64;
    const int bn = blockIdx.x * 128;

    float acc[2][8][4];
#pragma unroll
    for (int i = 0; i < 2; i++)
#pragma unroll
        for (int j = 0; j < 8; j++)
#pragma unroll
            for (int q = 0; q < 4; q++) acc[i][j][q] = 0.f;

    // single k-tile stage
#pragma unroll
    for (int i = 0; i < 4; i++) {
        int ci = tid + (i << 7);
        int r = ci >> 3, c = (ci & 7) << 3;
        cpa16p(&As[r * 72 + c], Ag + (long)r * C3 + c);
    }
#pragma unroll
    for (int i = 0; i < 8; i++) {
        int ci = tid + (i << 7);
        int r = ci >> 3, c = (ci & 7) << 3;
        cpa16p(&Bs[r * 72 + c], Bg + (long)r * C3 + c);
    }
    asm volatile("cp.async.commit_group;" ::: "memory");
    asm volatile("cp.async.wait_group 0;" ::: "memory");
    __syncthreads();

    {
        uint32_t aBase = s2u(As);
        uint32_t bBase = s2u(Bs);
#pragma unroll
        for (int kk = 0; kk < 64; kk += 16) {
            uint32_t ar[2][4], br[4][4];
#pragma unroll
            for (int mt = 0; mt < 2; mt++) {
                uint32_t addr = aBase +
                    2u * ((wm * 32 + mt * 16 + (lane & 15)) * 72 + kk + ((lane >> 4) << 3));
                ldm_x4(ar[mt], addr);
            }
#pragma unroll
            for (int nt = 0; nt < 4; nt++) {
                uint32_t addr = bBase +
                    2u * ((wn * 64 + nt * 16 + (lane & 15)) * 72 + kk + ((lane >> 4) << 3));
                ldm_x4(br[nt], addr);
            }
#pragma unroll
            for (int mt = 0; mt < 2; mt++)
#pragma unroll
                for (int n8 = 0; n8 < 8; n8++) {
                    int nt = n8 >> 1, hh = n8 & 1;
                    mma16816(acc[mt][n8], ar[mt], br[nt][hh], br[nt][2 + hh]);
                }
        }
    }

    // epilogue: exp2 + write fp16 + per-CTA column sums (64 rows)
    const int r0 = bm + wm * 32 + (lane >> 2);
    const int c0 = bn + wn * 64 + ((lane & 3) << 1);
    float cs[8][2];
#pragma unroll
    for (int n8 = 0; n8 < 8; n8++) { cs[n8][0] = 0.f; cs[n8][1] = 0.f; }
#pragma unroll
    for (int n8 = 0; n8 < 8; n8++) {
        int c = c0 + n8 * 8;
#pragma unroll
        for (int mt = 0; mt < 2; mt++) {
#pragma unroll
            for (int hh = 0; hh < 2; hh++) {
                int r = r0 + mt * 16 + hh * 8;
                float v0 = exp2f(fmaf(acc[mt][n8][hh * 2 + 0], alpha2, off2));
                float v1 = exp2f(fmaf(acc[mt][n8][hh * 2 + 1], alpha2, off2));
                *reinterpret_cast<__half2*>(Ch + (long)r * Tq + c) =
                    __floats2half2_rn(v0, v1);
                cs[n8][0] += v0; cs[n8][1] += v1;
            }
        }
    }
    // reduce over the 8 row-lanes of each warp
#pragma unroll
    for (int n8 = 0; n8 < 8; n8++)
#pragma unroll
        for (int p = 0; p < 2; p++) {
            float v = cs[n8][p];
            v += __shfl_xor_sync(0xffffffffu, v, 4);
            v += __shfl_xor_sync(0xffffffffu, v, 8);
            v += __shfl_xor_sync(0xffffffffu, v, 16);
            cs[n8][p] = v;
        }
    __syncthreads();
    float* sred = (float*)sm;            // [4 warps][64 cols]
    if (lane < 4) {
#pragma unroll
        for (int n8 = 0; n8 < 8; n8++) {
            sred[warp * 64 + n8 * 8 + lane * 2 + 0] = cs[n8][0];
            sred[warp * 64 + n8 * 8 + lane * 2 + 1] = cs[n8][1];
        }
    }
    __syncthreads();
    // col c (0..127): warps (wn) and (2+wn) contribute
    if (tid < 128) {
        int wn2 = tid >> 6, cin = tid & 63;
        float t = sred[wn2 * 64 + cin] + sred[(2 + wn2) * 64 + cin];
        psum[((long)blockIdx.y * BHq + bh) * Tq + bn + tid] = t;
    }
}

// ========== mma.sync GEMM kept for AV ========================================
template<int BN, bool BT>
__global__ void __launch_bounds__(256, 2)
gemm_tc(const __half* __restrict__ A, const __half* __restrict__ B,
        void* __restrict__ Cout,
        int K, int lda, int ldb, int ldc,
        long sAo, long sAi, long sBo, long sBi, long sCo, long sCi, int zdiv)
{
    extern __shared__ __half smem_dyn[];
    constexpr int ASIZE = 128 * 40;
    constexpr int BROWS = BT ? BN : 32;
    constexpr int BCOLS = BT ? 40 : (BN + 8);
    constexpr int BSIZE = BROWS * BCOLS;
    __half* Asm = smem_dyn;
    __half* Bsm = smem_dyn + 3 * ASIZE;

    const int zo = blockIdx.z / zdiv, zi = blockIdx.z - zo * zdiv;
    A += zo * sAo + zi * sAi;
    B += zo * sBo + zi * sBi;
    __half* Ch = (__half*)Cout + zo * sCo + zi * sCi;

    const int bm = blockIdx.y * 128;
    const int bn = blockIdx.x * BN;
    const int tid  = threadIdx.x;
    const int lane = tid & 31;
    const int warp = tid >> 5;
    const int wm   = warp & 3;
    const int wn   = warp >> 2;
    const int m_w  = wm * 32;
    const int n_w  = wn * (BN / 2);
    constexpr int NT8  = (BN / 2) / 8;
    constexpr int NT16 = (BN / 2) / 16;

    const __half* Ag = A + (long)bm * lda;
    const __half* Bg = BT ? (B + (long)bn * ldb) : (B + bn);

    float acc[2][NT8][4];
#pragma unroll
    for (int i = 0; i < 2; i++)
#pragma unroll
        for (int j = 0; j < NT8; j++)
#pragma unroll
            for (int q = 0; q < 4; q++) acc[i][j][q] = 0.f;

    auto stage = [&](int s, int k0) {
        __half* As = Asm + s * ASIZE;
        __half* Bs = Bsm + s * BSIZE;
#pragma unroll
        for (int i = 0; i < 2; i++) {
            int ci = tid + i * 256;
            int r = ci >> 2, kc = (ci & 3) << 3;
            cpa16p(&As[r * 40 + kc], Ag + (long)r * lda + k0 + kc);
        }
        if (BT) {
            constexpr int IT = (BN * 4) / 256;
#pragma unroll
            for (int i = 0; i < IT; i++) {
                int ci = tid + i * 256;
                int r = ci >> 2, kc = (ci & 3) << 3;
                cpa16p(&Bs[r * 40 + kc], Bg + (long)r * ldb + k0 + kc);
            }
        } else {
            constexpr int CH = BN / 8;
            constexpr int IT = (32 * CH) / 256;
#pragma unroll
            for (int i = 0; i < IT; i++) {
                int ci = tid + i * 256;
                int r = ci / CH, nc = (ci % CH) << 3;
                cpa16p(&Bs[r * BCOLS + nc], Bg + (long)(k0 + r) * ldb + nc);
            }
        }
    };

    auto compute = [&](int s) {
        uint32_t aBase = s2u(Asm + s * ASIZE);
        uint32_t bBase = s2u(Bsm + s * BSIZE);
#pragma unroll
        for (int kk = 0; kk < 32; kk += 16) {
            uint32_t ar[2][4];
#pragma unroll
            for (int mt = 0; mt < 2; mt++) {
                uint32_t addr = aBase +
                    2u * ((m_w + mt * 16 + (lane & 15)) * 40 + kk + ((lane >> 4) << 3));
                ldm_x4(ar[mt], addr);
            }
            uint32_t br[NT16][4];
#pragma unroll
            for (int nt = 0; nt < NT16; nt++) {
                if (BT) {
                    uint32_t addr = bBase +
                        2u * ((n_w + nt * 16 + (lane & 15)) * 40 + kk + ((lane >> 4) << 3));
                    ldm_x4(br[nt], addr);
                } else {
                    uint32_t addr = bBase +
                        2u * ((kk + (lane & 15)) * BCOLS + n_w + nt * 16 + ((lane >> 4) << 3));
                    ldm_x4_t(br[nt], addr);
                }
            }
#pragma unroll
            for (int mt = 0; mt < 2; mt++)
#pragma unroll
                for (int n8 = 0; n8 < NT8; n8++) {
                    int nt = n8 >> 1, h = n8 & 1;
                    uint32_t b0, b1;
                    if (BT) { b0 = br[nt][h];     b1 = br[nt][2 + h];     }
                    else    { b0 = br[nt][h * 2]; b1 = br[nt][h * 2 + 1]; }
                    mma16816(acc[mt][n8], ar[mt], b0, b1);
                }
        }
    };

    const int ntile = K >> 5;
    stage(0, 0);
    asm volatile("cp.async.commit_group;");
    stage(1, 32);
    asm volatile("cp.async.commit_group;");
    for (int kt = 0; kt < ntile; kt++) {
        asm volatile("cp.async.wait_group 1;");
        __syncthreads();
        if (kt + 2 < ntile) stage((kt + 2) % 3, (kt + 2) << 5);
        asm volatile("cp.async.commit_group;");
        compute(kt % 3);
    }

    const int r0 = bm + m_w + (lane >> 2);
    const int c0 = bn + n_w + ((lane & 3) << 1);
#pragma unroll
    for (int n8 = 0; n8 < NT8; n8++) {
        int c = c0 + n8 * 8;
#pragma unroll
        for (int mt = 0; mt < 2; mt++) {
#pragma unroll
            for (int hh = 0; hh < 2; hh++) {
                int r = r0 + mt * 16 + hh * 8;
                float v0 = acc[mt][n8][hh * 2 + 0];
                float v1 = acc[mt][n8][hh * 2 + 1];
                *reinterpret_cast<__half2*>(Ch + (long)r * ldc + c) =
                    __floats2half2_rn(v0, v1);
            }
        }
    }
}

#define SMEM_64F  (3*(128*40 + 32*72)*2)    // 44544

// ---------------- weight transpose+convert kernels ---------------------------
__global__ void tr_f2h(const float* __restrict__ src, __half* __restrict__ dst,
                       int K, int N, long sSrc, long sDst)
{
    src += (long)blockIdx.z * sSrc;
    dst += (long)blockIdx.z * sDst;
    __shared__ float t[64][65];
    const int n0 = blockIdx.x * 64, k0 = blockIdx.y * 64;
    const int tid = threadIdx.x;
#pragma unroll
    for (int i = 0; i < 16; i++) {
        int idx = tid + i * 256;
        int r = idx >> 6, c = idx & 63;
        t[r][c] = src[(long)(k0 + r) * N + n0 + c];
    }
    __syncthreads();
#pragma unroll
    for (int i = 0; i < 16; i++) {
        int idx = tid + i * 256;
        int r = idx >> 6, c = idx & 63;
        dst[(long)(n0 + r) * K + k0 + c] = __float2half(t[c][r]);
    }
}

__global__ void tr_qkv_all(const float* __restrict__ Wq, const float* __restrict__ Wk,
                           const float* __restrict__ Wv, __half* __restrict__ dst)
{
    const int z = blockIdx.z;
    const int w = z / (Lq * Hq);
    const int lh = z - w * (Lq * Hq);
    const int l = lh / Hq, h = lh - l * Hq;
    const float* W = (w == 0) ? Wq : ((w == 1) ? Wk : Wv);
    const float* src = W + (long)lh * Cq * Dq;
    __half* d = dst + (long)l * C3 * Cq + (long)(w * 768 + h * Dq) * Cq;
    __shared__ float t[64][65];
    const int k0 = blockIdx.y * 64;
    const int tid = threadIdx.x;
#pragma unroll
    for (int i = 0; i < 16; i++) {
        int idx = tid + i * 256;
        int r = idx >> 6, c = idx & 63;
        t[r][c] = src[(long)(k0 + r) * Dq + c];
    }
    __syncthreads();
#pragma unroll
    for (int i = 0; i < 16; i++) {
        int idx = tid + i * 256;
        int r = idx >> 6, c = idx & 63;
        d[(long)r * Cq + k0 + c] = __float2half(t[c][r]);
    }
}

// ---------------- embed -------------------------------------------------------
__global__ void embed_kernel(const int* __restrict__ ids, const float* __restrict__ emb,
                             const float* __restrict__ pos,
                             float* __restrict__ x, __half* __restrict__ xb)
{
    int idx = blockIdx.x * blockDim.x + threadIdx.x;
    if (idx >= Mq * Cq) return;
    int m = idx / Cq, c = idx - m * Cq;
    int t = m & (Tq - 1);
    int tok = ids[m];
    float v = emb[(size_t)tok * Cq + c] + pos[(size_t)t * Cq + c];
    x[idx]  = v;
    xb[idx] = __float2half(v);
}

// vs[m][c] = V[m][c] / colsum (8 partials)
__global__ void vscale_kernel(const __half* __restrict__ qkv,
                              const float* __restrict__ ps, __half* __restrict__ vs)
{
    int idx = blockIdx.x * blockDim.x + threadIdx.x;
    if (idx >= Mq * Cq / 2) return;
    int c2 = idx % (Cq / 2);
    int m  = idx / (Cq / 2);
    int c  = c2 * 2;
    int b  = m >> 9, t = m & 511, h = c >> 6;
    long si = (((long)b * Hq + h) << 9) + t;
    float s = 0.f;
#pragma unroll
    for (int p = 0; p < NPS; p++) s += ps[(long)p * BHq * Tq + si];
    float r = 1.f / s;
    __half2 v = *reinterpret_cast<const __half2*>(&qkv[(long)m * C3 + 1536 + c]);
    float2 f = __half22float2(v);
    *reinterpret_cast<__half2*>(&vs[(long)m * Cq + c]) = __floats2half2_rn(f.x * r, f.y * r);
}

// ---------------- residual add (fp16 split-K partials) + bias + layernorm -----
__global__ void __launch_bounds__(192)
add_ln_kernel(float* __restrict__ x, const __half* __restrict__ y0,
              const __half* __restrict__ y1, const float* __restrict__ bias,
              const float* __restrict__ g, const float* __restrict__ bta,
              __half* __restrict__ xb)
{
    __shared__ float sh[6];
    long row = blockIdx.x;
    int tid = threadIdx.x;
    int c = tid << 2;
    float4 xv = *reinterpret_cast<const float4*>(&x [row * Cq + c]);
    uint2 u0 = *reinterpret_cast<const uint2*>(&y0[row * Cq + c]);
    uint2 u1 = *reinterpret_cast<const uint2*>(&y1[row * Cq + c]);
    float2 a0lo = __half22float2(*reinterpret_cast<__half2*>(&u0.x));
    float2 a0hi = __half22float2(*reinterpret_cast<__half2*>(&u0.y));
    float2 a1lo = __half22float2(*reinterpret_cast<__half2*>(&u1.x));
    float2 a1hi = __half22float2(*reinterpret_cast<__half2*>(&u1.y));
    float4 bv = *reinterpret_cast<const float4*>(&bias[c]);
    float v0 = xv.x + a0lo.x + a1lo.x + bv.x;
    float v1 = xv.y + a0lo.y + a1lo.y + bv.y;
    float v2 = xv.z + a0hi.x + a1hi.x + bv.z;
    float v3 = xv.w + a0hi.y + a1hi.y + bv.w;

    float s = v0 + v1 + v2 + v3;
#pragma unroll
    for (int o = 16; o > 0; o >>= 1) s += __shfl_xor_sync(0xffffffffu, s, o);
    if ((tid & 31) == 0) sh[tid >> 5] = s;
    __syncthreads();
    float mu = (sh[0] + sh[1] + sh[2] + sh[3] + sh[4] + sh[5]) * (1.f / Cq);
    __syncthreads();

    float d0 = v0 - mu, d1 = v1 - mu, d2 = v2 - mu, d3 = v3 - mu;
    float s2 = d0 * d0 + d1 * d1 + d2 * d2 + d3 * d3;
#pragma unroll
    for (int o = 16; o > 0; o >>= 1) s2 += __shfl_xor_sync(0xffffffffu, s2, o);
    if ((tid & 31) == 0) sh[tid >> 5] = s2;
    __syncthreads();
    float var = (sh[0] + sh[1] + sh[2] + sh[3] + sh[4] + sh[5]) * (1.f / Cq);
    float rstd = rsqrtf(var + 1e-5f);

    float4 gv = *reinterpret_cast<const float4*>(&g[c]);
    float4 tv = *reinterpret_cast<const float4*>(&bta[c]);
    float o0 = d0 * rstd * gv.x + tv.x;
    float o1 = d1 * rstd * gv.y + tv.y;
    float o2 = d2 * rstd * gv.z + tv.z;
    float o3 = d3 * rstd * gv.w + tv.w;
    *reinterpret_cast<float4*>(&x[row * Cq + c]) = make_float4(o0, o1, o2, o3);
    __half2 h0 = __floats2half2_rn(o0, o1);
    __half2 h1 = __floats2half2_rn(o2, o3);
    *reinterpret_cast<__half2*>(&xb[row * Cq + c])     = h0;
    *reinterpret_cast<__half2*>(&xb[row * Cq + c + 2]) = h1;
}

// ---------------- launch -------------------------------------------------------
static cudaStream_t g_side = nullptr;
static cudaEvent_t  g_evFork = nullptr, g_evJoin = nullptr;

extern "C" void kernel_launch(void* const* d_in, const int* in_sizes, int n_in,
                              void* d_out, int out_size)
{
    const int*   ids  = (const int*)  d_in[0];
    const float* emb  = (const float*)d_in[1];
    const float* pos  = (const float*)d_in[2];
    const float* Wq   = (const float*)d_in[3];
    const float* Wk   = (const float*)d_in[4];
    const float* Wv   = (const float*)d_in[5];
    const float* Wo   = (const float*)d_in[6];
    const float* bo   = (const float*)d_in[7];
    const float* ln1g = (const float*)d_in[8];
    const float* ln1b = (const float*)d_in[9];
    const float* W1   = (const float*)d_in[10];
    const float* b1   = (const float*)d_in[11];
    const float* W2   = (const float*)d_in[12];
    const float* b2   = (const float*)d_in[13];
    const float* ln2g = (const float*)d_in[14];
    const float* ln2b = (const float*)d_in[15];
    const float* decW = (const float*)d_in[16];
    const float* decb = (const float*)d_in[17];
    float* out = (float*)d_out;

    if (!g_side) {
        cudaStreamCreateWithFlags(&g_side, cudaStreamNonBlocking);
        cudaEventCreateWithFlags(&g_evFork, cudaEventDisableTiming);
        cudaEventCreateWithFlags(&g_evJoin, cudaEventDisableTiming);
    }

    cudaFuncSetAttribute(gemm_d,
        cudaFuncAttributeMaxDynamicSharedMemorySize, D_SMEM);
    cudaFuncSetAttribute(gemm_s,
        cudaFuncAttributeMaxDynamicSharedMemorySize, S_SMEM);
    cudaFuncSetAttribute(gemm_tc<64, false>,
        cudaFuncAttributeMaxDynamicSharedMemorySize, SMEM_64F);

    float *x, *ps;
    __half *t2h, *xb, *qkvb, *pb, *vs, *t1b, *ffnb;
    __half *wqkv, *wob, *w1b, *w2b, *wdb;
    cudaGetSymbolAddress((void**)&x,    g_x);
    cudaGetSymbolAddress((void**)&t2h,  g_t2h);
    cudaGetSymbolAddress((void**)&ps,   g_ps);
    cudaGetSymbolAddress((void**)&xb,   g_xb);
    cudaGetSymbolAddress((void**)&qkvb, g_qkvb);
    cudaGetSymbolAddress((void**)&pb,   g_pb);
    cudaGetSymbolAddress((void**)&vs,   g_vs);
    cudaGetSymbolAddress((void**)&t1b,  g_t1b);
    cudaGetSymbolAddress((void**)&ffnb, g_ffnb);
    cudaGetSymbolAddress((void**)&wqkv, g_wqkv);
    cudaGetSymbolAddress((void**)&wob,  g_wob);
    cudaGetSymbolAddress((void**)&w1b,  g_w1b);
    cudaGetSymbolAddress((void**)&w2b,  g_w2b);
    cudaGetSymbolAddress((void**)&wdb,  g_wdb);

    // fork: heavy FFN/decoder weight transposes on side stream
    cudaEventRecord(g_evFork, 0);
    cudaStreamWaitEvent(g_side, g_evFork, 0);
    tr_f2h<<<dim3(48, 12, Lq), 256, 0, g_side>>>(W1, w1b, Cq, FFq,
        (long)Cq * FFq, (long)Cq * FFq);
    tr_f2h<<<dim3(12, 48, Lq), 256, 0, g_side>>>(W2, w2b, FFq, Cq,
        (long)FFq * Cq, (long)FFq * Cq);
    tr_f2h<<<dim3(500, 12, 1), 256, 0, g_side>>>(decW, wdb, Cq, Vq, 0, 0);
    cudaEventRecord(g_evJoin, g_side);

    // main stream
    embed_kernel<<<(Mq * Cq + 255) / 256, 256>>>(ids, emb, pos, x, xb);
    tr_qkv_all<<<dim3(1, 12, 3 * Lq * Hq), 256>>>(Wq, Wk, Wv, wqkv);
    tr_f2h<<<dim3(12, 12, Lq), 256>>>(Wo, wob, Cq, Cq, (long)Cq * Cq, (long)Cq * Cq);
    gemm_d<<<dim3(C3 / 128, Mq / 64, 1), 128, D_SMEM>>>(
        xb, wqkv, nullptr, qkvb, Cq, Cq, Cq, C3, 0, 0, 0, 1);

    bool joined = false;
    for (int l = 0; l < Lq; l++) {
        const __half* wol = wob + (size_t)l * Cq * Cq;
        const __half* w1l = w1b + (size_t)l * Cq * FFq;
        const __half* w2l = w2b + (size_t)l * FFq * Cq;
        const float* bol = bo + (size_t)l * Cq;
        const float* b1l = b1 + (size_t)l * FFq;
        const float* b2l = b2 + (size_t)l * Cq;

        // scores: pb = exp2(0.125*log2e*S - 4*log2e) + column partial sums
        gemm_s<<<dim3(Tq / 128, Tq / 64, BHq), 128, S_SMEM>>>(
            qkvb, pb, ps, 0.125f * LOG2E, -4.f * LOG2E);

        vscale_kernel<<<(Mq * Cq / 2 + 255) / 256, 256>>>(qkvb, ps, vs);

        // AV (out fp16, concat-head layout)
        gemm_tc<64, false><<<dim3(1, Tq / 128, BHq), 256, SMEM_64F>>>(
            pb, vs, t1b,
            Tq, Tq, Cq, Cq,
            (long)Hq * TT, TT, (long)Tq * Cq, Dq, (long)Tq * Cq, Dq, Hq);

        // output projection: split-K x2 -> fp16 partials
        gemm_d<<<dim3(Cq / 128, Mq / 64, 2), 128, D_SMEM>>>(
            t1b, wol, nullptr, t2h, Cq / 2, Cq, Cq, Cq,
            (long)(Cq / 2), (long)Mq * Cq, 0, 1);
        add_ln_kernel<<<Mq, 192>>>(x, t2h, t2h + (long)Mq * Cq, bol,
            ln1g + (size_t)l * Cq, ln1b + (size_t)l * Cq, xb);

        if (!joined) {
            cudaStreamWaitEvent(0, g_evJoin, 0);
            joined = true;
        }

        // FFN1
        gemm_d<<<dim3(FFq / 128, Mq / 64, 1), 128, D_SMEM>>>(
            xb, w1l, b1l, ffnb, Cq, Cq, Cq, FFq, 0, 0, 1, 1);
        // FFN2: split-K x2 -> fp16 partials
        gemm_d<<<dim3(Cq / 128, Mq / 64, 2), 128, D_SMEM>>>(
            ffnb, w2l, nullptr, t2h, FFq / 2, FFq, FFq, Cq,
            (long)(FFq / 2), (long)Mq * Cq, 0, 1);
        add_ln_kernel<<<Mq, 192>>>(x, t2h, t2h + (long)Mq * Cq, b2l,
            ln2g + (size_t)l * Cq, ln2b + (size_t)l * Cq, xb);

        // QKV for next layer
        if (l + 1 < Lq) {
            const __half* wq1 = wqkv + (size_t)(l + 1) * C3 * Cq;
            gemm_d<<<dim3(C3 / 128, Mq / 64, 1), 128, D_SMEM>>>(
                xb, wq1, nullptr, qkvb, Cq, Cq, Cq, C3, 0, 0, 0, 1);
        }
    }

    // decoder: [4096,768] @ [768,32000] + bias (out fp32)
    gemm_d<<<dim3(Vq / 128, Mq / 64, 1), 128, D_SMEM>>>(
        xb, wdb, decb, out, Cq, Cq, Cq, Vq, 0, 0, 0, 0);
}

// round 16
// speedup vs baseline: 1.0936x; 1.0137x over previous
#include <cuda_runtime.h>
#include <cuda_fp16.h>
#include <cstdint>

#define Bq 8
#define Tq 512
#define Cq 768
#define Hq 12
#define Dq 64
#define Lq 12
#define Vq 32000
#define FFq 3072
#define Mq (Bq*Tq)          // 4096
#define BHq (Bq*Hq)         // 96
#define TT  (Tq*Tq)         // 262144
#define C3  (3*Cq)          // 2304
#define LOG2E 1.4426950408889634f
#define NPS 8               // score q-tile partials

// ---------------- scratch (device globals) ----------------------------------
__device__ float g_x  [Mq*Cq];
__device__ float g_ps [NPS*BHq*Tq];

__device__ __half g_t2h  [2*(size_t)Mq*Cq];   // split-K partial outputs (fp16)
__device__ __half g_xb   [Mq*Cq];
__device__ __half g_qkvb [(size_t)Mq*C3];
__device__ __half g_pb   [(size_t)BHq*TT];
__device__ __half g_vst  [(size_t)BHq*Dq*Tq]; // V^T scaled: [bh][d][t]
__device__ __half g_t1b  [Mq*Cq];
__device__ __half g_ffnb [(size_t)Mq*FFq];
__device__ __half g_wqkv [(size_t)Lq*C3*Cq];
__device__ __half g_wob  [(size_t)Lq*Cq*Cq];
__device__ __half g_w1b  [(size_t)Lq*FFq*Cq];
__device__ __half g_w2b  [(size_t)Lq*Cq*FFq];
__device__ __half g_wdb  [(size_t)Vq*Cq];

// ---------------- small helpers ---------------------------------------------
__device__ __forceinline__ uint32_t s2u(const void* p) {
    return (uint32_t)__cvta_generic_to_shared(p);
}
__device__ __forceinline__ void cpa16p(void* smem, const void* gmem) {
    asm volatile("cp.async.cg.shared.global [%0], [%1], 16;\n"
        :: "r"(s2u(smem)), "l"(gmem));
}
__device__ __forceinline__ void ldm_x4(uint32_t* r, uint32_t addr) {
    asm volatile("ldmatrix.sync.aligned.m8n8.x4.shared.b16 {%0,%1,%2,%3}, [%4];"
        : "=r"(r[0]), "=r"(r[1]), "=r"(r[2]), "=r"(r[3]) : "r"(addr));
}
__device__ __forceinline__ void mma16816(float* c, const uint32_t* a, uint32_t b0, uint32_t b1) {
    asm volatile(
        "mma.sync.aligned.m16n8k16.row.col.f32.f16.f16.f32 "
        "{%0,%1,%2,%3}, {%4,%5,%6,%7}, {%8,%9}, {%0,%1,%2,%3};"
        : "+f"(c[0]), "+f"(c[1]), "+f"(c[2]), "+f"(c[3])
        : "r"(a[0]), "r"(a[1]), "r"(a[2]), "r"(a[3]), "r"(b0), "r"(b1));
}

// ============ dense GEMM: C[M,N] = A[M,K-slice] @ Bt[N,K-slice]^T ============
// CTA 64x128, 128 threads (4 warps, 2m x 2n), warp tile 32x64, BK=64,
// 2-stage cp.async, 4 CTAs/SM. Split-K via blockIdx.z (offset z*sK, out +z*sC).
#define D_ASZ  (64*72)
#define D_BSZ  (128*72)
#define D_SMEM (2*(D_ASZ + D_BSZ)*2)     // 55296 bytes
#define S_SMEM ((D_ASZ + D_BSZ)*2)       // 27648 bytes (single stage)
#define A_SMEM (2*(D_ASZ + D_ASZ)*2)     // 36864 bytes (AV, 64x64 tiles)

__global__ void __launch_bounds__(128, 4)
gemm_d(const __half* __restrict__ A, const __half* __restrict__ Bt,
       const float* __restrict__ bias, void* __restrict__ Cout,
       int K, int lda, int ldb, int ldc,
       long sK, long sC, int relu, int outhalf)
{
    extern __shared__ __half sm[];
    __half* As = sm;                 // [2][64][72]
    __half* Bs = sm + 2 * D_ASZ;     // [2][128][72]

    A  += (long)blockIdx.z * sK;
    Bt += (long)blockIdx.z * sK;
    float*  Cf = (float*)Cout  + (long)blockIdx.z * sC;
    __half* Ch = (__half*)Cout + (long)blockIdx.z * sC;

    const int tid  = threadIdx.x;
    const int lane = tid & 31;
    const int warp = tid >> 5;
    const int wm   = warp >> 1;          // 0..1
    const int wn   = warp & 1;           // 0..1
    const int bm = blockIdx.y * 64;
    const int bn = blockIdx.x * 128;

    const __half* Ag = A  + (long)bm * lda;
    const __half* Bg = Bt + (long)bn * ldb;

    float acc[2][8][4];
#pragma unroll
    for (int i = 0; i < 2; i++)
#pragma unroll
        for (int j = 0; j < 8; j++)
#pragma unroll
            for (int q = 0; q < 4; q++) acc[i][j][q] = 0.f;

    auto stage = [&](int s, int k0) {
        __half* Ab = As + s * D_ASZ;
        __half* Bb = Bs + s * D_BSZ;
#pragma unroll
        for (int i = 0; i < 4; i++) {                 // A: 512 16B-chunks
            int ci = tid + (i << 7);
            int r = ci >> 3, c = (ci & 7) << 3;
            cpa16p(&Ab[r * 72 + c], Ag + (long)r * lda + k0 + c);
        }
#pragma unroll
        for (int i = 0; i < 8; i++) {                 // B: 1024 chunks
            int ci = tid + (i << 7);
            int r = ci >> 3, c = (ci & 7) << 3;
            cpa16p(&Bb[r * 72 + c], Bg + (long)r * ldb + k0 + c);
        }
        asm volatile("cp.async.commit_group;" ::: "memory");
    };

    auto compute = [&](int s) {
        uint32_t aBase = s2u(As + s * D_ASZ);
        uint32_t bBase = s2u(Bs + s * D_BSZ);
#pragma unroll
        for (int kk = 0; kk < 64; kk += 16) {
            uint32_t ar[2][4], br[4][4];
#pragma unroll
            for (int mt = 0; mt < 2; mt++) {
                uint32_t addr = aBase +
                    2u * ((wm * 32 + mt * 16 + (lane & 15)) * 72 + kk + ((lane >> 4) << 3));
                ldm_x4(ar[mt], addr);
            }
#pragma unroll
            for (int nt = 0; nt < 4; nt++) {
                uint32_t addr = bBase +
                    2u * ((wn * 64 + nt * 16 + (lane & 15)) * 72 + kk + ((lane >> 4) << 3));
                ldm_x4(br[nt], addr);
            }
#pragma unroll
            for (int mt = 0; mt < 2; mt++)
#pragma unroll
                for (int n8 = 0; n8 < 8; n8++) {
                    int nt = n8 >> 1, h = n8 & 1;
                    mma16816(acc[mt][n8], ar[mt], br[nt][h], br[nt][2 + h]);
                }
        }
    };

    const int nk = K >> 6;
    stage(0, 0);
    stage(1, 64);
    for (int kt = 0; kt < nk; kt++) {
        if (kt + 1 < nk) asm volatile("cp.async.wait_group 1;" ::: "memory");
        else             asm volatile("cp.async.wait_group 0;" ::: "memory");
        __syncthreads();
        compute(kt & 1);
        __syncthreads();
        if (kt + 2 < nk) stage(kt & 1, (kt + 2) << 6);
    }

    // epilogue
    const int r0 = bm + wm * 32 + (lane >> 2);
    const int c0 = bn + wn * 64 + ((lane & 3) << 1);
#pragma unroll
    for (int n8 = 0; n8 < 8; n8++) {
        int c = c0 + n8 * 8;
        float bb0 = 0.f, bb1 = 0.f;
        if (bias) { bb0 = __ldg(&bias[c]); bb1 = __ldg(&bias[c + 1]); }
#pragma unroll
        for (int mt = 0; mt < 2; mt++) {
#pragma unroll
            for (int hh = 0; hh < 2; hh++) {
                int r = r0 + mt * 16 + hh * 8;
                float v0 = acc[mt][n8][hh * 2 + 0] + bb0;
                float v1 = acc[mt][n8][hh * 2 + 1] + bb1;
                if (relu) { v0 = fmaxf(v0, 0.f); v1 = fmaxf(v1, 0.f); }
                if (outhalf) {
                    *reinterpret_cast<__half2*>(Ch + (long)r * ldc + c) =
                        __floats2half2_rn(v0, v1);
                } else {
                    *reinterpret_cast<float2*>(Cf + (long)r * ldc + c) = make_float2(v0, v1);
                }
            }
        }
    }
}

// ============ scores: pb = exp2(a2*(Q K^T) + off2), column partial sums ======
__global__ void __launch_bounds__(128, 4)
gemm_s(const __half* __restrict__ Qkv, __half* __restrict__ pbo,
       float* __restrict__ psum, float alpha2, float off2)
{
    extern __shared__ __half sm[];
    __half* As = sm;                 // [64][72]
    __half* Bs = sm + D_ASZ;         // [128][72]

    const int bh = blockIdx.z;
    const int b = bh / Hq, h = bh - b * Hq;
    const __half* Ag = Qkv + (long)b * Tq * C3 + h * Dq
                     + (long)(blockIdx.y * 64) * C3;            // Q rows
    const __half* Bg = Qkv + (long)b * Tq * C3 + 768 + h * Dq
                     + (long)(blockIdx.x * 128) * C3;           // K rows
    __half* Ch = pbo + (long)bh * TT;

    const int tid  = threadIdx.x;
    const int lane = tid & 31;
    const int warp = tid >> 5;
    const int wm   = warp >> 1;
    const int wn   = warp & 1;
    const int bm = blockIdx.y * 64;
    const int bn = blockIdx.x * 128;

    float acc[2][8][4];
#pragma unroll
    for (int i = 0; i < 2; i++)
#pragma unroll
        for (int j = 0; j < 8; j++)
#pragma unroll
            for (int q = 0; q < 4; q++) acc[i][j][q] = 0.f;

#pragma unroll
    for (int i = 0; i < 4; i++) {
        int ci = tid + (i << 7);
        int r = ci >> 3, c = (ci & 7) << 3;
        cpa16p(&As[r * 72 + c], Ag + (long)r * C3 + c);
    }
#pragma unroll
    for (int i = 0; i < 8; i++) {
        int ci = tid + (i << 7);
        int r = ci >> 3, c = (ci & 7) << 3;
        cpa16p(&Bs[r * 72 + c], Bg + (long)r * C3 + c);
    }
    asm volatile("cp.async.commit_group;" ::: "memory");
    asm volatile("cp.async.wait_group 0;" ::: "memory");
    __syncthreads();

    {
        uint32_t aBase = s2u(As);
        uint32_t bBase = s2u(Bs);
#pragma unroll
        for (int kk = 0; kk < 64; kk += 16) {
            uint32_t ar[2][4], br[4][4];
#pragma unroll
            for (int mt = 0; mt < 2; mt++) {
                uint32_t addr = aBase +
                    2u * ((wm * 32 + mt * 16 + (lane & 15)) * 72 + kk + ((lane >> 4) << 3));
                ldm_x4(ar[mt], addr);
            }
#pragma unroll
            for (int nt = 0; nt < 4; nt++) {
                uint32_t addr = bBase +
                    2u * ((wn * 64 + nt * 16 + (lane & 15)) * 72 + kk + ((lane >> 4) << 3));
                ldm_x4(br[nt], addr);
            }
#pragma unroll
            for (int mt = 0; mt < 2; mt++)
#pragma unroll
                for (int n8 = 0; n8 < 8; n8++) {
                    int nt = n8 >> 1, hh = n8 & 1;
                    mma16816(acc[mt][n8], ar[mt], br[nt][hh], br[nt][2 + hh]);
                }
        }
    }

    const int r0 = bm + wm * 32 + (lane >> 2);
    const int c0 = bn + wn * 64 + ((lane & 3) << 1);
    float cs[8][2];
#pragma unroll
    for (int n8 = 0; n8 < 8; n8++) { cs[n8][0] = 0.f; cs[n8][1] = 0.f; }
#pragma unroll
    for (int n8 = 0; n8 < 8; n8++) {
        int c = c0 + n8 * 8;
#pragma unroll
        for (int mt = 0; mt < 2; mt++) {
#pragma unroll
            for (int hh = 0; hh < 2; hh++) {
                int r = r0 + mt * 16 + hh * 8;
                float v0 = exp2f(fmaf(acc[mt][n8][hh * 2 + 0], alpha2, off2));
                float v1 = exp2f(fmaf(acc[mt][n8][hh * 2 + 1], alpha2, off2));
                *reinterpret_cast<__half2*>(Ch + (long)r * Tq + c) =
                    __floats2half2_rn(v0, v1);
                cs[n8][0] += v0; cs[n8][1] += v1;
            }
        }
    }
#pragma unroll
    for (int n8 = 0; n8 < 8; n8++)
#pragma unroll
        for (int p = 0; p < 2; p++) {
            float v = cs[n8][p];
            v += __shfl_xor_sync(0xffffffffu, v, 4);
            v += __shfl_xor_sync(0xffffffffu, v, 8);
            v += __shfl_xor_sync(0xffffffffu, v, 16);
            cs[n8][p] = v;
        }
    __syncthreads();
    float* sred = (float*)sm;            // [4 warps][64 cols]
    if (lane < 4) {
#pragma unroll
        for (int n8 = 0; n8 < 8; n8++) {
            sred[warp * 64 + n8 * 8 + lane * 2 + 0] = cs[n8][0];
            sred[warp * 64 + n8 * 8 + lane * 2 + 1] = cs[n8][1];
        }
    }
    __syncthreads();
    if (tid < 128) {
        int wn2 = tid >> 6, cin = tid & 63;
        float t = sred[wn2 * 64 + cin] + sred[(2 + wn2) * 64 + cin];
        psum[((long)blockIdx.y * BHq + bh) * Tq + bn + tid] = t;
    }
}

// ============ AV: t1b[b,q,h*64+d] = pb[bh] @ vst[bh]^T =======================
// CTA 64(q)x64(d), 128 threads (4 warps, 2m x 2n), warp tile 32x32, BK=64,
// 2-stage cp.async, 4 CTAs/SM. grid (8 q-tiles, 96 bh).
__global__ void __launch_bounds__(128, 4)
gemm_a(const __half* __restrict__ pb, const __half* __restrict__ vst,
       __half* __restrict__ t1b)
{
    extern __shared__ __half sm[];
    __half* As = sm;                 // [2][64][72]
    __half* Bs = sm + 2 * D_ASZ;     // [2][64][72]

    const int bh = blockIdx.y;
    const int b = bh / Hq, h = bh - b * Hq;
    const int bm = blockIdx.x * 64;
    const __half* Ag = pb  + (long)bh * TT + (long)bm * Tq;   // [64 q][K=512]
    const __half* Bg = vst + (long)bh * Dq * Tq;              // [64 d][K=512]
    __half* Ch = t1b + ((long)b * Tq) * Cq + h * Dq;

    const int tid  = threadIdx.x;
    const int lane = tid & 31;
    const int warp = tid >> 5;
    const int wm   = warp >> 1;
    const int wn   = warp & 1;

    float acc[2][4][4];
#pragma unroll
    for (int i = 0; i < 2; i++)
#pragma unroll
        for (int j = 0; j < 4; j++)
#pragma unroll
            for (int q = 0; q < 4; q++) acc[i][j][q] = 0.f;

    auto stage = [&](int s, int k0) {
        __half* Ab = As + s * D_ASZ;
        __half* Bb = Bs + s * D_ASZ;
#pragma unroll
        for (int i = 0; i < 4; i++) {
            int ci = tid + (i << 7);
            int r = ci >> 3, c = (ci & 7) << 3;
            cpa16p(&Ab[r * 72 + c], Ag + (long)r * Tq + k0 + c);
        }
#pragma unroll
        for (int i = 0; i < 4; i++) {
            int ci = tid + (i << 7);
            int r = ci >> 3, c = (ci & 7) << 3;
            cpa16p(&Bb[r * 72 + c], Bg + (long)r * Tq + k0 + c);
        }
        asm volatile("cp.async.commit_group;" ::: "memory");
    };

    auto compute = [&](int s) {
        uint32_t aBase = s2u(As + s * D_ASZ);
        uint32_t bBase = s2u(Bs + s * D_ASZ);
#pragma unroll
        for (int kk = 0; kk < 64; kk += 16) {
            uint32_t ar[2][4], br[2][4];
#pragma unroll
            for (int mt = 0; mt < 2; mt++) {
                uint32_t addr = aBase +
                    2u * ((wm * 32 + mt * 16 + (lane & 15)) * 72 + kk + ((lane >> 4) << 3));
                ldm_x4(ar[mt], addr);
            }
#pragma unroll
            for (int nt = 0; nt < 2; nt++) {
                uint32_t addr = bBase +
                    2u * ((wn * 32 + nt * 16 + (lane & 15)) * 72 + kk + ((lane >> 4) << 3));
                ldm_x4(br[nt], addr);
            }
#pragma unroll
            for (int mt = 0; mt < 2; mt++)
#pragma unroll
                for (int n8 = 0; n8 < 4; n8++) {
                    int nt = n8 >> 1, hh = n8 & 1;
                    mma16816(acc[mt][n8], ar[mt], br[nt][hh], br[nt][2 + hh]);
                }
        }
    };

    stage(0, 0);
    stage(1, 64);
    const int nk = Tq >> 6;    // 8
    for (int kt = 0; kt < nk; kt++) {
        if (kt + 1 < nk) asm volatile("cp.async.wait_group 1;" ::: "memory");
        else             asm volatile("cp.async.wait_group 0;" ::: "memory");
        __syncthreads();
        compute(kt & 1);
        __syncthreads();
        if (kt + 2 < nk) stage(kt & 1, (kt + 2) << 6);
    }

    const int r0 = bm + wm * 32 + (lane >> 2);
    const int c0 = wn * 32 + ((lane & 3) << 1);
#pragma unroll
    for (int n8 = 0; n8 < 4; n8++) {
        int c = c0 + n8 * 8;
#pragma unroll
        for (int mt = 0; mt < 2; mt++) {
#pragma unroll
            for (int hh = 0; hh < 2; hh++) {
                int r = r0 + mt * 16 + hh * 8;
                *reinterpret_cast<__half2*>(Ch + (long)r * Cq + c) =
                    __floats2half2_rn(acc[mt][n8][hh * 2 + 0], acc[mt][n8][hh * 2 + 1]);
            }
        }
    }
}

// ---------------- weight transpose+convert kernels ---------------------------
__global__ void tr_f2h(const float* __restrict__ src, __half* __restrict__ dst,
                       int K, int N, long sSrc, long sDst)
{
    src += (long)blockIdx.z * sSrc;
    dst += (long)blockIdx.z * sDst;
    __shared__ float t[64][65];
    const int n0 = blockIdx.x * 64, k0 = blockIdx.y * 64;
    const int tid = threadIdx.x;
#pragma unroll
    for (int i = 0; i < 16; i++) {
        int idx = tid + i * 256;
        int r = idx >> 6, c = idx & 63;
        t[r][c] = src[(long)(k0 + r) * N + n0 + c];
    }
    __syncthreads();
#pragma unroll
    for (int i = 0; i < 16; i++) {
        int idx = tid + i * 256;
        int r = idx >> 6, c = idx & 63;
        dst[(long)(n0 + r) * K + k0 + c] = __float2half(t[c][r]);
    }
}

__global__ void tr_qkv_all(const float* __restrict__ Wq, const float* __restrict__ Wk,
                           const float* __restrict__ Wv, __half* __restrict__ dst)
{
    const int z = blockIdx.z;
    const int w = z / (Lq * Hq);
    const int lh = z - w * (Lq * Hq);
    const int l = lh / Hq, h = lh - l * Hq;
    const float* W = (w == 0) ? Wq : ((w == 1) ? Wk : Wv);
    const float* src = W + (long)lh * Cq * Dq;
    __half* d = dst + (long)l * C3 * Cq + (long)(w * 768 + h * Dq) * Cq;
    __shared__ float t[64][65];
    const int k0 = blockIdx.y * 64;
    const int tid = threadIdx.x;
#pragma unroll
    for (int i = 0; i < 16; i++) {
        int idx = tid + i * 256;
        int r = idx >> 6, c = idx & 63;
        t[r][c] = src[(long)(k0 + r) * Dq + c];
    }
    __syncthreads();
#pragma unroll
    for (int i = 0; i < 16; i++) {
        int idx = tid + i * 256;
        int r = idx >> 6, c = idx & 63;
        d[(long)r * Cq + k0 + c] = __float2half(t[c][r]);
    }
}

// ---------------- embed -------------------------------------------------------
__global__ void embed_kernel(const int* __restrict__ ids, const float* __restrict__ emb,
                             const float* __restrict__ pos,
                             float* __restrict__ x, __half* __restrict__ xb)
{
    int idx = blockIdx.x * blockDim.x + threadIdx.x;
    if (idx >= Mq * Cq) return;
    int m = idx / Cq, c = idx - m * Cq;
    int t = m & (Tq - 1);
    int tok = ids[m];
    float v = emb[(size_t)tok * Cq + c] + pos[(size_t)t * Cq + c];
    x[idx]  = v;
    xb[idx] = __float2half(v);
}

// vst[bh][d][t] = V[b, t, h*64+d] / colsum(bh,t)   (8 partials)
__global__ void __launch_bounds__(256)
vscale_t(const __half* __restrict__ qkv, const float* __restrict__ ps,
         __half* __restrict__ vst)
{
    __shared__ float st[64][65];
    __shared__ float shs[64];
    const int bh = blockIdx.y;
    const int t0 = blockIdx.x * 64;
    const int b = bh / Hq, h = bh - b * Hq;
    const int tid = threadIdx.x;
    if (tid < 64) {
        long si = (long)bh * Tq + t0 + tid;
        float s = 0.f;
#pragma unroll
        for (int p = 0; p < NPS; p++) s += ps[(long)p * BHq * Tq + si];
        shs[tid] = 1.f / s;
    }
    __syncthreads();
#pragma unroll
    for (int i = 0; i < 16; i++) {
        int idx = tid + i * 256;
        int r = idx >> 6, c = idx & 63;
        float v = __half2float(qkv[(long)(b * Tq + t0 + r) * C3 + 1536 + h * Dq + c]);
        st[r][c] = v * shs[r];
    }
    __syncthreads();
#pragma unroll
    for (int i = 0; i < 16; i++) {
        int idx = tid + i * 256;
        int d = idx >> 6, tt = idx & 63;
        vst[((long)bh * Dq + d) * Tq + t0 + tt] = __float2half(st[tt][d]);
    }
}

// ---------------- residual add (fp16 split-K partials) + bias + layernorm -----
__global__ void __launch_bounds__(192)
add_ln_kernel(float* __restrict__ x, const __half* __restrict__ y0,
              const __half* __restrict__ y1, const float* __restrict__ bias,
              const float* __restrict__ g, const float* __restrict__ bta,
              __half* __restrict__ xb)
{
    __shared__ float sh[6];
    long row = blockIdx.x;
    int tid = threadIdx.x;
    int c = tid << 2;
    float4 xv = *reinterpret_cast<const float4*>(&x [row * Cq + c]);
    uint2 u0 = *reinterpret_cast<const uint2*>(&y0[row * Cq + c]);
    uint2 u1 = *reinterpret_cast<const uint2*>(&y1[row * Cq + c]);
    float2 a0lo = __half22float2(*reinterpret_cast<__half2*>(&u0.x));
    float2 a0hi = __half22float2(*reinterpret_cast<__half2*>(&u0.y));
    float2 a1lo = __half22float2(*reinterpret_cast<__half2*>(&u1.x));
    float2 a1hi = __half22float2(*reinterpret_cast<__half2*>(&u1.y));
    float4 bv = *reinterpret_cast<const float4*>(&bias[c]);
    float v0 = xv.x + a0lo.x + a1lo.x + bv.x;
    float v1 = xv.y + a0lo.y + a1lo.y + bv.y;
    float v2 = xv.z + a0hi.x + a1hi.x + bv.z;
    float v3 = xv.w + a0hi.y + a1hi.y + bv.w;

    float s = v0 + v1 + v2 + v3;
#pragma unroll
    for (int o = 16; o > 0; o >>= 1) s += __shfl_xor_sync(0xffffffffu, s, o);
    if ((tid & 31) == 0) sh[tid >> 5] = s;
    __syncthreads();
    float mu = (sh[0] + sh[1] + sh[2] + sh[3] + sh[4] + sh[5]) * (1.f / Cq);
    __syncthreads();

    float d0 = v0 - mu, d1 = v1 - mu, d2 = v2 - mu, d3 = v3 - mu;
    float s2 = d0 * d0 + d1 * d1 + d2 * d2 + d3 * d3;
#pragma unroll
    for (int o = 16; o > 0; o >>= 1) s2 += __shfl_xor_sync(0xffffffffu, s2, o);
    if ((tid & 31) == 0) sh[tid >> 5] = s2;
    __syncthreads();
    float var = (sh[0] + sh[1] + sh[2] + sh[3] + sh[4] + sh[5]) * (1.f / Cq);
    float rstd = rsqrtf(var + 1e-5f);

    float4 gv = *reinterpret_cast<const float4*>(&g[c]);
    float4 tv = *reinterpret_cast<const float4*>(&bta[c]);
    float o0 = d0 * rstd * gv.x + tv.x;
    float o1 = d1 * rstd * gv.y + tv.y;
    float o2 = d2 * rstd * gv.z + tv.z;
    float o3 = d3 * rstd * gv.w + tv.w;
    *reinterpret_cast<float4*>(&x[row * Cq + c]) = make_float4(o0, o1, o2, o3);
    __half2 h0 = __floats2half2_rn(o0, o1);
    __half2 h1 = __floats2half2_rn(o2, o3);
    *reinterpret_cast<__half2*>(&xb[row * Cq + c])     = h0;
    *reinterpret_cast<__half2*>(&xb[row * Cq + c + 2]) = h1;
}

// ---------------- launch -------------------------------------------------------
static cudaStream_t g_side = nullptr;
static cudaEvent_t  g_evFork = nullptr, g_evJoin = nullptr;

extern "C" void kernel_launch(void* const* d_in, const int* in_sizes, int n_in,
                              void* d_out, int out_size)
{
    const int*   ids  = (const int*)  d_in[0];
    const float* emb  = (const float*)d_in[1];
    const float* pos  = (const float*)d_in[2];
    const float* Wq   = (const float*)d_in[3];
    const float* Wk   = (const float*)d_in[4];
    const float* Wv   = (const float*)d_in[5];
    const float* Wo   = (const float*)d_in[6];
    const float* bo   = (const float*)d_in[7];
    const float* ln1g = (const float*)d_in[8];
    const float* ln1b = (const float*)d_in[9];
    const float* W1   = (const float*)d_in[10];
    const float* b1   = (const float*)d_in[11];
    const float* W2   = (const float*)d_in[12];
    const float* b2   = (const float*)d_in[13];
    const float* ln2g = (const float*)d_in[14];
    const float* ln2b = (const float*)d_in[15];
    const float* decW = (const float*)d_in[16];
    const float* decb = (const float*)d_in[17];
    float* out = (float*)d_out;

    if (!g_side) {
        cudaStreamCreateWithFlags(&g_side, cudaStreamNonBlocking);
        cudaEventCreateWithFlags(&g_evFork, cudaEventDisableTiming);
        cudaEventCreateWithFlags(&g_evJoin, cudaEventDisableTiming);
    }

    cudaFuncSetAttribute(gemm_d,
        cudaFuncAttributeMaxDynamicSharedMemorySize, D_SMEM);
    cudaFuncSetAttribute(gemm_s,
        cudaFuncAttributeMaxDynamicSharedMemorySize, S_SMEM);
    cudaFuncSetAttribute(gemm_a,
        cudaFuncAttributeMaxDynamicSharedMemorySize, A_SMEM);

    float *x, *ps;
    __half *t2h, *xb, *qkvb, *pb, *vst, *t1b, *ffnb;
    __half *wqkv, *wob, *w1b, *w2b, *wdb;
    cudaGetSymbolAddress((void**)&x,    g_x);
    cudaGetSymbolAddress((void**)&t2h,  g_t2h);
    cudaGetSymbolAddress((void**)&ps,   g_ps);
    cudaGetSymbolAddress((void**)&xb,   g_xb);
    cudaGetSymbolAddress((void**)&qkvb, g_qkvb);
    cudaGetSymbolAddress((void**)&pb,   g_pb);
    cudaGetSymbolAddress((void**)&vst,  g_vst);
    cudaGetSymbolAddress((void**)&t1b,  g_t1b);
    cudaGetSymbolAddress((void**)&ffnb, g_ffnb);
    cudaGetSymbolAddress((void**)&wqkv, g_wqkv);
    cudaGetSymbolAddress((void**)&wob,  g_wob);
    cudaGetSymbolAddress((void**)&w1b,  g_w1b);
    cudaGetSymbolAddress((void**)&w2b,  g_w2b);
    cudaGetSymbolAddress((void**)&wdb,  g_wdb);

    // fork: heavy FFN/decoder weight transposes on side stream
    cudaEventRecord(g_evFork, 0);
    cudaStreamWaitEvent(g_side, g_evFork, 0);
    tr_f2h<<<dim3(48, 12, Lq), 256, 0, g_side>>>(W1, w1b, Cq, FFq,
        (long)Cq * FFq, (long)Cq * FFq);
    tr_f2h<<<dim3(12, 48, Lq), 256, 0, g_side>>>(W2, w2b, FFq, Cq,
        (long)FFq * Cq, (long)FFq * Cq);
    tr_f2h<<<dim3(500, 12, 1), 256, 0, g_side>>>(decW, wdb, Cq, Vq, 0, 0);
    cudaEventRecord(g_evJoin, g_side);

    // main stream
    embed_kernel<<<(Mq * Cq + 255) / 256, 256>>>(ids, emb, pos, x, xb);
    tr_qkv_all<<<dim3(1, 12, 3 * Lq * Hq), 256>>>(Wq, Wk, Wv, wqkv);
    tr_f2h<<<dim3(12, 12, Lq), 256>>>(Wo, wob, Cq, Cq, (long)Cq * Cq, (long)Cq * Cq);
    gemm_d<<<dim3(C3 / 128, Mq / 64, 1), 128, D_SMEM>>>(
        xb, wqkv, nullptr, qkvb, Cq, Cq, Cq, C3, 0, 0, 0, 1);

    bool joined = false;
    for (int l = 0; l < Lq; l++) {
        const __half* wol = wob + (size_t)l * Cq * Cq;
        const __half* w1l = w1b + (size_t)l * Cq * FFq;
        const __half* w2l = w2b + (size_t)l * FFq * Cq;
        const float* bol = bo + (size_t)l * Cq;
        const float* b1l = b1 + (size_t)l * FFq;
        const float* b2l = b2 + (size_t)l * Cq;

        // scores: pb = exp2(0.125*log2e*S - 4*log2e) + column partial sums
        gemm_s<<<dim3(Tq / 128, Tq / 64, BHq), 128, S_SMEM>>>(
            qkvb, pb, ps, 0.125f * LOG2E, -4.f * LOG2E);

        // vst = V^T / colsum
        vscale_t<<<dim3(Tq / 64, BHq), 256>>>(qkvb, ps, vst);

        // AV: t1b = pb @ vst^T (gemm_d-shaped)
        gemm_a<<<dim3(Tq / 64, BHq), 128, A_SMEM>>>(pb, vst, t1b);

        // output projection: split-K x2 -> fp16 partials
        gemm_d<<<dim3(Cq / 128, Mq / 64, 2), 128, D_SMEM>>>(
            t1b, wol, nullptr, t2h, Cq / 2, Cq, Cq, Cq,
            (long)(Cq / 2), (long)Mq * Cq, 0, 1);
        add_ln_kernel<<<Mq, 192>>>(x, t2h, t2h + (long)Mq * Cq, bol,
            ln1g + (size_t)l * Cq, ln1b + (size_t)l * Cq, xb);

        if (!joined) {
            cudaStreamWaitEvent(0, g_evJoin, 0);
            joined = true;
        }

        // FFN1
        gemm_d<<<dim3(FFq / 128, Mq / 64, 1), 128, D_SMEM>>>(
            xb, w1l, b1l, ffnb, Cq, Cq, Cq, FFq, 0, 0, 1, 1);
        // FFN2: split-K x2 -> fp16 partials
        gemm_d<<<dim3(Cq / 128, Mq / 64, 2), 128, D_SMEM>>>(
            ffnb, w2l, nullptr, t2h, FFq / 2, FFq, FFq, Cq,
            (long)(FFq / 2), (long)Mq * Cq, 0, 1);
        add_ln_kernel<<<Mq, 192>>>(x, t2h, t2h + (long)Mq * Cq, b2l,
            ln2g + (size_t)l * Cq, ln2b + (size_t)l * Cq, xb);

        // QKV for next layer
        if (l + 1 < Lq) {
            const __half* wq1 = wqkv + (size_t)(l + 1) * C3 * Cq;
            gemm_d<<<dim3(C3 / 128, Mq / 64, 1), 128, D_SMEM>>>(
                xb, wq1, nullptr, qkvb, Cq, Cq, Cq, C3, 0, 0, 0, 1);
        }
    }

    // decoder: [4096,768] @ [768,32000] + bias (out fp32)
    gemm_d<<<dim3(Vq / 128, Mq / 64, 1), 128, D_SMEM>>>(
        xb, wdb, decb, out, Cq, Cq, Cq, Vq, 0, 0, 0, 0);
}

// round 17
// speedup vs baseline: 1.1131x; 1.0178x over previous
#include <cuda_runtime.h>
#include <cuda_fp16.h>
#include <cstdint>

#define Bq 8
#define Tq 512
#define Cq 768
#define Hq 12
#define Dq 64
#define Lq 12
#define Vq 32000
#define FFq 3072
#define Mq (Bq*Tq)          // 4096
#define BHq (Bq*Hq)         // 96
#define TT  (Tq*Tq)         // 262144
#define C3  (3*Cq)          // 2304
#define LOG2E 1.4426950408889634f
#define NPS 8               // score q-tile partials

// ---------------- scratch (device globals) ----------------------------------
__device__ float g_x  [Mq*Cq];
__device__ float g_ps [NPS*BHq*Tq];

__device__ __half g_t2h  [3*(size_t)Mq*Cq];   // split-K partial outputs (fp16)
__device__ __half g_xb   [Mq*Cq];
__device__ __half g_qkvb [(size_t)Mq*C3];
__device__ __half g_pb   [(size_t)BHq*TT];
__device__ __half g_vst  [(size_t)BHq*Dq*Tq]; // V^T scaled: [bh][d][t]
__device__ __half g_t1b  [Mq*Cq];
__device__ __half g_ffnb [(size_t)Mq*FFq];
__device__ __half g_wqkv [(size_t)Lq*C3*Cq];
__device__ __half g_wob  [(size_t)Lq*Cq*Cq];
__device__ __half g_w1b  [(size_t)Lq*FFq*Cq];
__device__ __half g_w2b  [(size_t)Lq*Cq*FFq];
__device__ __half g_wdb  [(size_t)Vq*Cq];

// ---------------- small helpers ---------------------------------------------
__device__ __forceinline__ uint32_t s2u(const void* p) {
    return (uint32_t)__cvta_generic_to_shared(p);
}
__device__ __forceinline__ void cpa16p(void* smem, const void* gmem) {
    asm volatile("cp.async.cg.shared.global [%0], [%1], 16;\n"
        :: "r"(s2u(smem)), "l"(gmem));
}
__device__ __forceinline__ void ldm_x4(uint32_t* r, uint32_t addr) {
    asm volatile("ldmatrix.sync.aligned.m8n8.x4.shared.b16 {%0,%1,%2,%3}, [%4];"
        : "=r"(r[0]), "=r"(r[1]), "=r"(r[2]), "=r"(r[3]) : "r"(addr));
}
__device__ __forceinline__ void mma16816(float* c, const uint32_t* a, uint32_t b0, uint32_t b1) {
    asm volatile(
        "mma.sync.aligned.m16n8k16.row.col.f32.f16.f16.f32 "
        "{%0,%1,%2,%3}, {%4,%5,%6,%7}, {%8,%9}, {%0,%1,%2,%3};"
        : "+f"(c[0]), "+f"(c[1]), "+f"(c[2]), "+f"(c[3])
        : "r"(a[0]), "r"(a[1]), "r"(a[2]), "r"(a[3]), "r"(b0), "r"(b1));
}

// ============ dense GEMM: C[M,N] = A[M,K-slice] @ Bt[N,K-slice]^T ============
// CTA 64x128, 128 threads (4 warps, 2m x 2n), warp tile 32x64, BK=64,
// 2-stage cp.async, 4 CTAs/SM. Split-K via blockIdx.z (offset z*sK, out +z*sC).
#define D_ASZ  (64*72)
#define D_BSZ  (128*72)
#define D_SMEM (2*(D_ASZ + D_BSZ)*2)     // 55296 bytes
#define S_SMEM ((D_ASZ + D_BSZ)*2)       // 27648 bytes (single stage)
#define A_SMEM (2*(D_ASZ + D_ASZ)*2)     // 36864 bytes (AV, 64x64 tiles)

__global__ void __launch_bounds__(128, 4)
gemm_d(const __half* __restrict__ A, const __half* __restrict__ Bt,
       const float* __restrict__ bias, void* __restrict__ Cout,
       int K, int lda, int ldb, int ldc,
       long sK, long sC, int relu, int outhalf)
{
    extern __shared__ __half sm[];
    __half* As = sm;                 // [2][64][72]
    __half* Bs = sm + 2 * D_ASZ;     // [2][128][72]

    A  += (long)blockIdx.z * sK;
    Bt += (long)blockIdx.z * sK;
    float*  Cf = (float*)Cout  + (long)blockIdx.z * sC;
    __half* Ch = (__half*)Cout + (long)blockIdx.z * sC;

    const int tid  = threadIdx.x;
    const int lane = tid & 31;
    const int warp = tid >> 5;
    const int wm   = warp >> 1;          // 0..1
    const int wn   = warp & 1;           // 0..1
    const int bm = blockIdx.y * 64;
    const int bn = blockIdx.x * 128;

    const __half* Ag = A  + (long)bm * lda;
    const __half* Bg = Bt + (long)bn * ldb;

    float acc[2][8][4];
#pragma unroll
    for (int i = 0; i < 2; i++)
#pragma unroll
        for (int j = 0; j < 8; j++)
#pragma unroll
            for (int q = 0; q < 4; q++) acc[i][j][q] = 0.f;

    auto stage = [&](int s, int k0) {
        __half* Ab = As + s * D_ASZ;
        __half* Bb = Bs + s * D_BSZ;
#pragma unroll
        for (int i = 0; i < 4; i++) {                 // A: 512 16B-chunks
            int ci = tid + (i << 7);
            int r = ci >> 3, c = (ci & 7) << 3;
            cpa16p(&Ab[r * 72 + c], Ag + (long)r * lda + k0 + c);
        }
#pragma unroll
        for (int i = 0; i < 8; i++) {                 // B: 1024 chunks
            int ci = tid + (i << 7);
            int r = ci >> 3, c = (ci & 7) << 3;
            cpa16p(&Bb[r * 72 + c], Bg + (long)r * ldb + k0 + c);
        }
        asm volatile("cp.async.commit_group;" ::: "memory");
    };

    auto compute = [&](int s) {
        uint32_t aBase = s2u(As + s * D_ASZ);
        uint32_t bBase = s2u(Bs + s * D_BSZ);
#pragma unroll
        for (int kk = 0; kk < 64; kk += 16) {
            uint32_t ar[2][4], br[4][4];
#pragma unroll
            for (int mt = 0; mt < 2; mt++) {
                uint32_t addr = aBase +
                    2u * ((wm * 32 + mt * 16 + (lane & 15)) * 72 + kk + ((lane >> 4) << 3));
                ldm_x4(ar[mt], addr);
            }
#pragma unroll
            for (int nt = 0; nt < 4; nt++) {
                uint32_t addr = bBase +
                    2u * ((wn * 64 + nt * 16 + (lane & 15)) * 72 + kk + ((lane >> 4) << 3));
                ldm_x4(br[nt], addr);
            }
#pragma unroll
            for (int mt = 0; mt < 2; mt++)
#pragma unroll
                for (int n8 = 0; n8 < 8; n8++) {
                    int nt = n8 >> 1, h = n8 & 1;
                    mma16816(acc[mt][n8], ar[mt], br[nt][h], br[nt][2 + h]);
                }
        }
    };

    const int nk = K >> 6;
    stage(0, 0);
    stage(1, 64);
    for (int kt = 0; kt < nk; kt++) {
        if (kt + 1 < nk) asm volatile("cp.async.wait_group 1;" ::: "memory");
        else             asm volatile("cp.async.wait_group 0;" ::: "memory");
        __syncthreads();
        compute(kt & 1);
        __syncthreads();
        if (kt + 2 < nk) stage(kt & 1, (kt + 2) << 6);
    }

    // epilogue
    const int r0 = bm + wm * 32 + (lane >> 2);
    const int c0 = bn + wn * 64 + ((lane & 3) << 1);
#pragma unroll
    for (int n8 = 0; n8 < 8; n8++) {
        int c = c0 + n8 * 8;
        float bb0 = 0.f, bb1 = 0.f;
        if (bias) { bb0 = __ldg(&bias[c]); bb1 = __ldg(&bias[c + 1]); }
#pragma unroll
        for (int mt = 0; mt < 2; mt++) {
#pragma unroll
            for (int hh = 0; hh < 2; hh++) {
                int r = r0 + mt * 16 + hh * 8;
                float v0 = acc[mt][n8][hh * 2 + 0] + bb0;
                float v1 = acc[mt][n8][hh * 2 + 1] + bb1;
                if (relu) { v0 = fmaxf(v0, 0.f); v1 = fmaxf(v1, 0.f); }
                if (outhalf) {
                    *reinterpret_cast<__half2*>(Ch + (long)r * ldc + c) =
                        __floats2half2_rn(v0, v1);
                } else {
                    *reinterpret_cast<float2*>(Cf + (long)r * ldc + c) = make_float2(v0, v1);
                }
            }
        }
    }
}

// ============ scores: pb = exp2(a2*(Q K^T) + off2), column partial sums ======
__global__ void __launch_bounds__(128, 4)
gemm_s(const __half* __restrict__ Qkv, __half* __restrict__ pbo,
       float* __restrict__ psum, float alpha2, float off2)
{
    extern __shared__ __half sm[];
    __half* As = sm;                 // [64][72]
    __half* Bs = sm + D_ASZ;         // [128][72]

    const int bh = blockIdx.z;
    const int b = bh / Hq, h = bh - b * Hq;
    const __half* Ag = Qkv + (long)b * Tq * C3 + h * Dq
                     + (long)(blockIdx.y * 64) * C3;            // Q rows
    const __half* Bg = Qkv + (long)b * Tq * C3 + 768 + h * Dq
                     + (long)(blockIdx.x * 128) * C3;           // K rows
    __half* Ch = pbo + (long)bh * TT;

    const int tid  = threadIdx.x;
    const int lane = tid & 31;
    const int warp = tid >> 5;
    const int wm   = warp >> 1;
    const int wn   = warp & 1;
    const int bm = blockIdx.y * 64;
    const int bn = blockIdx.x * 128;

    float acc[2][8][4];
#pragma unroll
    for (int i = 0; i < 2; i++)
#pragma unroll
        for (int j = 0; j < 8; j++)
#pragma unroll
            for (int q = 0; q < 4; q++) acc[i][j][q] = 0.f;

#pragma unroll
    for (int i = 0; i < 4; i++) {
        int ci = tid + (i << 7);
        int r = ci >> 3, c = (ci & 7) << 3;
        cpa16p(&As[r * 72 + c], Ag + (long)r * C3 + c);
    }
#pragma unroll
    for (int i = 0; i < 8; i++) {
        int ci = tid + (i << 7);
        int r = ci >> 3, c = (ci & 7) << 3;
        cpa16p(&Bs[r * 72 + c], Bg + (long)r * C3 + c);
    }
    asm volatile("cp.async.commit_group;" ::: "memory");
    asm volatile("cp.async.wait_group 0;" ::: "memory");
    __syncthreads();

    {
        uint32_t aBase = s2u(As);
        uint32_t bBase = s2u(Bs);
#pragma unroll
        for (int kk = 0; kk < 64; kk += 16) {
            uint32_t ar[2][4], br[4][4];
#pragma unroll
            for (int mt = 0; mt < 2; mt++) {
                uint32_t addr = aBase +
                    2u * ((wm * 32 + mt * 16 + (lane & 15)) * 72 + kk + ((lane >> 4) << 3));
                ldm_x4(ar[mt], addr);
            }
#pragma unroll
            for (int nt = 0; nt < 4; nt++) {
                uint32_t addr = bBase +
                    2u * ((wn * 64 + nt * 16 + (lane & 15)) * 72 + kk + ((lane >> 4) << 3));
                ldm_x4(br[nt], addr);
            }
#pragma unroll
            for (int mt = 0; mt < 2; mt++)
#pragma unroll
                for (int n8 = 0; n8 < 8; n8++) {
                    int nt = n8 >> 1, hh = n8 & 1;
                    mma16816(acc[mt][n8], ar[mt], br[nt][hh], br[nt][2 + hh]);
                }
        }
    }

    const int r0 = bm + wm * 32 + (lane >> 2);
    const int c0 = bn + wn * 64 + ((lane & 3) << 1);
    float cs[8][2];
#pragma unroll
    for (int n8 = 0; n8 < 8; n8++) { cs[n8][0] = 0.f; cs[n8][1] = 0.f; }
#pragma unroll
    for (int n8 = 0; n8 < 8; n8++) {
        int c = c0 + n8 * 8;
#pragma unroll
        for (int mt = 0; mt < 2; mt++) {
#pragma unroll
            for (int hh = 0; hh < 2; hh++) {
                int r = r0 + mt * 16 + hh * 8;
                float v0 = exp2f(fmaf(acc[mt][n8][hh * 2 + 0], alpha2, off2));
                float v1 = exp2f(fmaf(acc[mt][n8][hh * 2 + 1], alpha2, off2));
                *reinterpret_cast<__half2*>(Ch + (long)r * Tq + c) =
                    __floats2half2_rn(v0, v1);
                cs[n8][0] += v0; cs[n8][1] += v1;
            }
        }
    }
#pragma unroll
    for (int n8 = 0; n8 < 8; n8++)
#pragma unroll
        for (int p = 0; p < 2; p++) {
            float v = cs[n8][p];
            v += __shfl_xor_sync(0xffffffffu, v, 4);
            v += __shfl_xor_sync(0xffffffffu, v, 8);
            v += __shfl_xor_sync(0xffffffffu, v, 16);
            cs[n8][p] = v;
        }
    __syncthreads();
    float* sred = (float*)sm;            // [4 warps][64 cols]
    if (lane < 4) {
#pragma unroll
        for (int n8 = 0; n8 < 8; n8++) {
            sred[warp * 64 + n8 * 8 + lane * 2 + 0] = cs[n8][0];
            sred[warp * 64 + n8 * 8 + lane * 2 + 1] = cs[n8][1];
        }
    }
    __syncthreads();
    if (tid < 128) {
        int wn2 = tid >> 6, cin = tid & 63;
        float t = sred[wn2 * 64 + cin] + sred[(2 + wn2) * 64 + cin];
        psum[((long)blockIdx.y * BHq + bh) * Tq + bn + tid] = t;
    }
}

// ============ AV: t1b[b,q,h*64+d] = pb[bh] @ vst[bh]^T =======================
__global__ void __launch_bounds__(128, 4)
gemm_a(const __half* __restrict__ pb, const __half* __restrict__ vst,
       __half* __restrict__ t1b)
{
    extern __shared__ __half sm[];
    __half* As = sm;                 // [2][64][72]
    __half* Bs = sm + 2 * D_ASZ;     // [2][64][72]

    const int bh = blockIdx.y;
    const int b = bh / Hq, h = bh - b * Hq;
    const int bm = blockIdx.x * 64;
    const __half* Ag = pb  + (long)bh * TT + (long)bm * Tq;   // [64 q][K=512]
    const __half* Bg = vst + (long)bh * Dq * Tq;              // [64 d][K=512]
    __half* Ch = t1b + ((long)b * Tq) * Cq + h * Dq;

    const int tid  = threadIdx.x;
    const int lane = tid & 31;
    const int warp = tid >> 5;
    const int wm   = warp >> 1;
    const int wn   = warp & 1;

    float acc[2][4][4];
#pragma unroll
    for (int i = 0; i < 2; i++)
#pragma unroll
        for (int j = 0; j < 4; j++)
#pragma unroll
            for (int q = 0; q < 4; q++) acc[i][j][q] = 0.f;

    auto stage = [&](int s, int k0) {
        __half* Ab = As + s * D_ASZ;
        __half* Bb = Bs + s * D_ASZ;
#pragma unroll
        for (int i = 0; i < 4; i++) {
            int ci = tid + (i << 7);
            int r = ci >> 3, c = (ci & 7) << 3;
            cpa16p(&Ab[r * 72 + c], Ag + (long)r * Tq + k0 + c);
        }
#pragma unroll
        for (int i = 0; i < 4; i++) {
            int ci = tid + (i << 7);
            int r = ci >> 3, c = (ci & 7) << 3;
            cpa16p(&Bb[r * 72 + c], Bg + (long)r * Tq + k0 + c);
        }
        asm volatile("cp.async.commit_group;" ::: "memory");
    };

    auto compute = [&](int s) {
        uint32_t aBase = s2u(As + s * D_ASZ);
        uint32_t bBase = s2u(Bs + s * D_ASZ);
#pragma unroll
        for (int kk = 0; kk < 64; kk += 16) {
            uint32_t ar[2][4], br[2][4];
#pragma unroll
            for (int mt = 0; mt < 2; mt++) {
                uint32_t addr = aBase +
                    2u * ((wm * 32 + mt * 16 + (lane & 15)) * 72 + kk + ((lane >> 4) << 3));
                ldm_x4(ar[mt], addr);
            }
#pragma unroll
            for (int nt = 0; nt < 2; nt++) {
                uint32_t addr = bBase +
                    2u * ((wn * 32 + nt * 16 + (lane & 15)) * 72 + kk + ((lane >> 4) << 3));
                ldm_x4(br[nt], addr);
            }
#pragma unroll
            for (int mt = 0; mt < 2; mt++)
#pragma unroll
                for (int n8 = 0; n8 < 4; n8++) {
                    int nt = n8 >> 1, hh = n8 & 1;
                    mma16816(acc[mt][n8], ar[mt], br[nt][hh], br[nt][2 + hh]);
                }
        }
    };

    stage(0, 0);
    stage(1, 64);
    const int nk = Tq >> 6;    // 8
    for (int kt = 0; kt < nk; kt++) {
        if (kt + 1 < nk) asm volatile("cp.async.wait_group 1;" ::: "memory");
        else             asm volatile("cp.async.wait_group 0;" ::: "memory");
        __syncthreads();
        compute(kt & 1);
        __syncthreads();
        if (kt + 2 < nk) stage(kt & 1, (kt + 2) << 6);
    }

    const int r0 = bm + wm * 32 + (lane >> 2);
    const int c0 = wn * 32 + ((lane & 3) << 1);
#pragma unroll
    for (int n8 = 0; n8 < 4; n8++) {
        int c = c0 + n8 * 8;
#pragma unroll
        for (int mt = 0; mt < 2; mt++) {
#pragma unroll
            for (int hh = 0; hh < 2; hh++) {
                int r = r0 + mt * 16 + hh * 8;
                *reinterpret_cast<__half2*>(Ch + (long)r * Cq + c) =
                    __floats2half2_rn(acc[mt][n8][hh * 2 + 0], acc[mt][n8][hh * 2 + 1]);
            }
        }
    }
}

// ---------------- weight transpose+convert kernels ---------------------------
__global__ void tr_f2h(const float* __restrict__ src, __half* __restrict__ dst,
                       int K, int N, long sSrc, long sDst)
{
    src += (long)blockIdx.z * sSrc;
    dst += (long)blockIdx.z * sDst;
    __shared__ float t[64][65];
    const int n0 = blockIdx.x * 64, k0 = blockIdx.y * 64;
    const int tid = threadIdx.x;
#pragma unroll
    for (int i = 0; i < 16; i++) {
        int idx = tid + i * 256;
        int r = idx >> 6, c = idx & 63;
        t[r][c] = src[(long)(k0 + r) * N + n0 + c];
    }
    __syncthreads();
#pragma unroll
    for (int i = 0; i < 16; i++) {
        int idx = tid + i * 256;
        int r = idx >> 6, c = idx & 63;
        dst[(long)(n0 + r) * K + k0 + c] = __float2half(t[c][r]);
    }
}

__global__ void tr_qkv_all(const float* __restrict__ Wq, const float* __restrict__ Wk,
                           const float* __restrict__ Wv, __half* __restrict__ dst)
{
    const int z = blockIdx.z;
    const int w = z / (Lq * Hq);
    const int lh = z - w * (Lq * Hq);
    const int l = lh / Hq, h = lh - l * Hq;
    const float* W = (w == 0) ? Wq : ((w == 1) ? Wk : Wv);
    const float* src = W + (long)lh * Cq * Dq;
    __half* d = dst + (long)l * C3 * Cq + (long)(w * 768 + h * Dq) * Cq;
    __shared__ float t[64][65];
    const int k0 = blockIdx.y * 64;
    const int tid = threadIdx.x;
#pragma unroll
    for (int i = 0; i < 16; i++) {
        int idx = tid + i * 256;
        int r = idx >> 6, c = idx & 63;
        t[r][c] = src[(long)(k0 + r) * Dq + c];
    }
    __syncthreads();
#pragma unroll
    for (int i = 0; i < 16; i++) {
        int idx = tid + i * 256;
        int r = idx >> 6, c = idx & 63;
        d[(long)r * Cq + k0 + c] = __float2half(t[c][r]);
    }
}

// ---------------- embed -------------------------------------------------------
__global__ void embed_kernel(const int* __restrict__ ids, const float* __restrict__ emb,
                             const float* __restrict__ pos,
                             float* __restrict__ x, __half* __restrict__ xb)
{
    int idx = blockIdx.x * blockDim.x + threadIdx.x;
    if (idx >= Mq * Cq) return;
    int m = idx / Cq, c = idx - m * Cq;
    int t = m & (Tq - 1);
    int tok = ids[m];
    float v = emb[(size_t)tok * Cq + c] + pos[(size_t)t * Cq + c];
    x[idx]  = v;
    xb[idx] = __float2half(v);
}

// vst[bh][d][t] = V[b, t, h*64+d] / colsum(bh,t)   (8 partials)
__global__ void __launch_bounds__(256)
vscale_t(const __half* __restrict__ qkv, const float* __restrict__ ps,
         __half* __restrict__ vst)
{
    __shared__ float st[64][65];
    __shared__ float shs[64];
    const int bh = blockIdx.y;
    const int t0 = blockIdx.x * 64;
    const int b = bh / Hq, h = bh - b * Hq;
    const int tid = threadIdx.x;
    if (tid < 64) {
        long si = (long)bh * Tq + t0 + tid;
        float s = 0.f;
#pragma unroll
        for (int p = 0; p < NPS; p++) s += ps[(long)p * BHq * Tq + si];
        shs[tid] = 1.f / s;
    }
    __syncthreads();
#pragma unroll
    for (int i = 0; i < 16; i++) {
        int idx = tid + i * 256;
        int r = idx >> 6, c = idx & 63;
        float v = __half2float(qkv[(long)(b * Tq + t0 + r) * C3 + 1536 + h * Dq + c]);
        st[r][c] = v * shs[r];
    }
    __syncthreads();
#pragma unroll
    for (int i = 0; i < 16; i++) {
        int idx = tid + i * 256;
        int d = idx >> 6, tt = idx & 63;
        vst[((long)bh * Dq + d) * Tq + t0 + tt] = __float2half(st[tt][d]);
    }
}

// ---------------- residual add (3 fp16 split-K partials) + bias + layernorm ---
__global__ void __launch_bounds__(192)
add_ln_kernel(float* __restrict__ x, const __half* __restrict__ y0,
              const __half* __restrict__ y1, const __half* __restrict__ y2,
              const float* __restrict__ bias,
              const float* __restrict__ g, const float* __restrict__ bta,
              __half* __restrict__ xb)
{
    __shared__ float sh[6];
    long row = blockIdx.x;
    int tid = threadIdx.x;
    int c = tid << 2;
    float4 xv = *reinterpret_cast<const float4*>(&x [row * Cq + c]);
    uint2 u0 = *reinterpret_cast<const uint2*>(&y0[row * Cq + c]);
    uint2 u1 = *reinterpret_cast<const uint2*>(&y1[row * Cq + c]);
    uint2 u2 = *reinterpret_cast<const uint2*>(&y2[row * Cq + c]);
    float2 a0lo = __half22float2(*reinterpret_cast<__half2*>(&u0.x));
    float2 a0hi = __half22float2(*reinterpret_cast<__half2*>(&u0.y));
    float2 a1lo = __half22float2(*reinterpret_cast<__half2*>(&u1.x));
    float2 a1hi = __half22float2(*reinterpret_cast<__half2*>(&u1.y));
    float2 a2lo = __half22float2(*reinterpret_cast<__half2*>(&u2.x));
    float2 a2hi = __half22float2(*reinterpret_cast<__half2*>(&u2.y));
    float4 bv = *reinterpret_cast<const float4*>(&bias[c]);
    float v0 = xv.x + a0lo.x + a1lo.x + a2lo.x + bv.x;
    float v1 = xv.y + a0lo.y + a1lo.y + a2lo.y + bv.y;
    float v2 = xv.z + a0hi.x + a1hi.x + a2hi.x + bv.z;
    float v3 = xv.w + a0hi.y + a1hi.y + a2hi.y + bv.w;

    float s = v0 + v1 + v2 + v3;
#pragma unroll
    for (int o = 16; o > 0; o >>= 1) s += __shfl_xor_sync(0xffffffffu, s, o);
    if ((tid & 31) == 0) sh[tid >> 5] = s;
    __syncthreads();
    float mu = (sh[0] + sh[1] + sh[2] + sh[3] + sh[4] + sh[5]) * (1.f / Cq);
    __syncthreads();

    float d0 = v0 - mu, d1 = v1 - mu, d2 = v2 - mu, d3 = v3 - mu;
    float s2 = d0 * d0 + d1 * d1 + d2 * d2 + d3 * d3;
#pragma unroll
    for (int o = 16; o > 0; o >>= 1) s2 += __shfl_xor_sync(0xffffffffu, s2, o);
    if ((tid & 31) == 0) sh[tid >> 5] = s2;
    __syncthreads();
    float var = (sh[0] + sh[1] + sh[2] + sh[3] + sh[4] + sh[5]) * (1.f / Cq);
    float rstd = rsqrtf(var + 1e-5f);

    float4 gv = *reinterpret_cast<const float4*>(&g[c]);
    float4 tv = *reinterpret_cast<const float4*>(&bta[c]);
    float o0 = d0 * rstd * gv.x + tv.x;
    float o1 = d1 * rstd * gv.y + tv.y;
    float o2 = d2 * rstd * gv.z + tv.z;
    float o3 = d3 * rstd * gv.w + tv.w;
    *reinterpret_cast<float4*>(&x[row * Cq + c]) = make_float4(o0, o1, o2, o3);
    __half2 h0 = __floats2half2_rn(o0, o1);
    __half2 h1 = __floats2half2_rn(o2, o3);
    *reinterpret_cast<__half2*>(&xb[row * Cq + c])     = h0;
    *reinterpret_cast<__half2*>(&xb[row * Cq + c + 2]) = h1;
}

// ---------------- launch -------------------------------------------------------
static cudaStream_t g_side = nullptr;
static cudaEvent_t  g_evFork = nullptr, g_evJoin = nullptr;

extern "C" void kernel_launch(void* const* d_in, const int* in_sizes, int n_in,
                              void* d_out, int out_size)
{
    const int*   ids  = (const int*)  d_in[0];
    const float* emb  = (const float*)d_in[1];
    const float* pos  = (const float*)d_in[2];
    const float* Wq   = (const float*)d_in[3];
    const float* Wk   = (const float*)d_in[4];
    const float* Wv   = (const float*)d_in[5];
    const float* Wo   = (const float*)d_in[6];
    const float* bo   = (const float*)d_in[7];
    const float* ln1g = (const float*)d_in[8];
    const float* ln1b = (const float*)d_in[9];
    const float* W1   = (const float*)d_in[10];
    const float* b1   = (const float*)d_in[11];
    const float* W2   = (const float*)d_in[12];
    const float* b2   = (const float*)d_in[13];
    const float* ln2g = (const float*)d_in[14];
    const float* ln2b = (const float*)d_in[15];
    const float* decW = (const float*)d_in[16];
    const float* decb = (const float*)d_in[17];
    float* out = (float*)d_out;

    if (!g_side) {
        cudaStreamCreateWithFlags(&g_side, cudaStreamNonBlocking);
        cudaEventCreateWithFlags(&g_evFork, cudaEventDisableTiming);
        cudaEventCreateWithFlags(&g_evJoin, cudaEventDisableTiming);
    }

    cudaFuncSetAttribute(gemm_d,
        cudaFuncAttributeMaxDynamicSharedMemorySize, D_SMEM);
    cudaFuncSetAttribute(gemm_s,
        cudaFuncAttributeMaxDynamicSharedMemorySize, S_SMEM);
    cudaFuncSetAttribute(gemm_a,
        cudaFuncAttributeMaxDynamicSharedMemorySize, A_SMEM);

    float *x, *ps;
    __half *t2h, *xb, *qkvb, *pb, *vst, *t1b, *ffnb;
    __half *wqkv, *wob, *w1b, *w2b, *wdb;
    cudaGetSymbolAddress((void**)&x,    g_x);
    cudaGetSymbolAddress((void**)&t2h,  g_t2h);
    cudaGetSymbolAddress((void**)&ps,   g_ps);
    cudaGetSymbolAddress((void**)&xb,   g_xb);
    cudaGetSymbolAddress((void**)&qkvb, g_qkvb);
    cudaGetSymbolAddress((void**)&pb,   g_pb);
    cudaGetSymbolAddress((void**)&vst,  g_vst);
    cudaGetSymbolAddress((void**)&t1b,  g_t1b);
    cudaGetSymbolAddress((void**)&ffnb, g_ffnb);
    cudaGetSymbolAddress((void**)&wqkv, g_wqkv);
    cudaGetSymbolAddress((void**)&wob,  g_wob);
    cudaGetSymbolAddress((void**)&w1b,  g_w1b);
    cudaGetSymbolAddress((void**)&w2b,  g_w2b);
    cudaGetSymbolAddress((void**)&wdb,  g_wdb);

    const long PCH = (long)Mq * Cq;     // partial-buffer stride

    // fork: heavy FFN/decoder weight transposes on side stream
    cudaEventRecord(g_evFork, 0);
    cudaStreamWaitEvent(g_side, g_evFork, 0);
    tr_f2h<<<dim3(48, 12, Lq), 256, 0, g_side>>>(W1, w1b, Cq, FFq,
        (long)Cq * FFq, (long)Cq * FFq);
    tr_f2h<<<dim3(12, 48, Lq), 256, 0, g_side>>>(W2, w2b, FFq, Cq,
        (long)FFq * Cq, (long)FFq * Cq);
    tr_f2h<<<dim3(500, 12, 1), 256, 0, g_side>>>(decW, wdb, Cq, Vq, 0, 0);
    cudaEventRecord(g_evJoin, g_side);

    // main stream
    embed_kernel<<<(Mq * Cq + 255) / 256, 256>>>(ids, emb, pos, x, xb);
    tr_qkv_all<<<dim3(1, 12, 3 * Lq * Hq), 256>>>(Wq, Wk, Wv, wqkv);
    tr_f2h<<<dim3(12, 12, Lq), 256>>>(Wo, wob, Cq, Cq, (long)Cq * Cq, (long)Cq * Cq);
    gemm_d<<<dim3(C3 / 128, Mq / 64, 1), 128, D_SMEM>>>(
        xb, wqkv, nullptr, qkvb, Cq, Cq, Cq, C3, 0, 0, 0, 1);

    bool joined = false;
    for (int l = 0; l < Lq; l++) {
        const __half* wol = wob + (size_t)l * Cq * Cq;
        const __half* w1l = w1b + (size_t)l * Cq * FFq;
        const __half* w2l = w2b + (size_t)l * FFq * Cq;
        const float* bol = bo + (size_t)l * Cq;
        const float* b1l = b1 + (size_t)l * FFq;
        const float* b2l = b2 + (size_t)l * Cq;

        // scores: pb = exp2(0.125*log2e*S - 4*log2e) + column partial sums
        gemm_s<<<dim3(Tq / 128, Tq / 64, BHq), 128, S_SMEM>>>(
            qkvb, pb, ps, 0.125f * LOG2E, -4.f * LOG2E);

        // vst = V^T / colsum
        vscale_t<<<dim3(Tq / 64, BHq), 256>>>(qkvb, ps, vst);

        // AV: t1b = pb @ vst^T
        gemm_a<<<dim3(Tq / 64, BHq), 128, A_SMEM>>>(pb, vst, t1b);

        // output projection: split-K x3 -> fp16 partials
        gemm_d<<<dim3(Cq / 128, Mq / 64, 3), 128, D_SMEM>>>(
            t1b, wol, nullptr, t2h, Cq / 3, Cq, Cq, Cq,
            (long)(Cq / 3), PCH, 0, 1);
        add_ln_kernel<<<Mq, 192>>>(x, t2h, t2h + PCH, t2h + 2 * PCH, bol,
            ln1g + (size_t)l * Cq, ln1b + (size_t)l * Cq, xb);

        if (!joined) {
            cudaStreamWaitEvent(0, g_evJoin, 0);
            joined = true;
        }

        // FFN1
        gemm_d<<<dim3(FFq / 128, Mq / 64, 1), 128, D_SMEM>>>(
            xb, w1l, b1l, ffnb, Cq, Cq, Cq, FFq, 0, 0, 1, 1);
        // FFN2: split-K x3 -> fp16 partials
        gemm_d<<<dim3(Cq / 128, Mq / 64, 3), 128, D_SMEM>>>(
            ffnb, w2l, nullptr, t2h, FFq / 3, FFq, FFq, Cq,
            (long)(FFq / 3), PCH, 0, 1);
        add_ln_kernel<<<Mq, 192>>>(x, t2h, t2h + PCH, t2h + 2 * PCH, b2l,
            ln2g + (size_t)l * Cq, ln2b + (size_t)l * Cq, xb);

        // QKV for next layer
        if (l + 1 < Lq) {
            const __half* wq1 = wqkv + (size_t)(l + 1) * C3 * Cq;
            gemm_d<<<dim3(C3 / 128, Mq / 64, 1), 128, D_SMEM>>>(
                xb, wq1, nullptr, qkvb, Cq, Cq, Cq, C3, 0, 0, 0, 1);
        }
    }

    // decoder: [4096,768] @ [768,32000] + bias (out fp32)
    gemm_d<<<dim3(Vq / 128, Mq / 64, 1), 128, D_SMEM>>>(
        xb, wdb, decb, out, Cq, Cq, Cq, Vq, 0, 0, 0, 0);
}